// round 10
// baseline (speedup 1.0000x reference)
#include <cuda_runtime.h>
#include <cuda_bf16.h>
#include <cstdint>
#include <math.h>

#define NB 2
#define NS 2048
#define NHID 2048
#define NHEADS 16
#define NKVH 4
#define DHEAD 128
#define NQKV 3072

// ------------------------- scratch (static device globals; no allocs) ------
static __device__ float g_cos[(size_t)NB * NS * 64];
static __device__ float g_sin[(size_t)NB * NS * 64];

static __device__ __nv_bfloat16 g_qh[(size_t)NB * NHEADS * NS * DHEAD];
static __device__ __nv_bfloat16 g_ql[(size_t)NB * NHEADS * NS * DHEAD];
static __device__ __nv_bfloat16 g_kh[(size_t)NB * NKVH * NS * DHEAD];
static __device__ __nv_bfloat16 g_kl[(size_t)NB * NKVH * NS * DHEAD];
static __device__ __nv_bfloat16 g_vh[(size_t)NB * NKVH * NS * DHEAD];
static __device__ __nv_bfloat16 g_vl[(size_t)NB * NKVH * NS * DHEAD];

static __device__ __nv_bfloat16 g_hid_hi[(size_t)NB * NS * NHID];
static __device__ __nv_bfloat16 g_hid_lo[(size_t)NB * NS * NHID];
static __device__ __nv_bfloat16 g_w1_hi[(size_t)NQKV * NHID];
static __device__ __nv_bfloat16 g_w1_lo[(size_t)NQKV * NHID];
static __device__ __nv_bfloat16 g_w2_hi[(size_t)NHID * NHID];
static __device__ __nv_bfloat16 g_w2_lo[(size_t)NHID * NHID];
static __device__ __nv_bfloat16 g_at_hi[(size_t)NB * NS * NHID];
static __device__ __nv_bfloat16 g_at_lo[(size_t)NB * NS * NHID];

// ------------------------- PTX helpers (baseline ISA only) -----------------
__device__ __forceinline__ uint32_t smem_u32(const void* p) {
    uint32_t a;
    asm("{ .reg .u64 t; cvta.to.shared.u64 t, %1; cvt.u32.u64 %0, t; }"
        : "=r"(a) : "l"(p));
    return a;
}

__device__ __forceinline__ void cp16(uint32_t dst, const void* src) {
    asm volatile("cp.async.cg.shared.global [%0], [%1], 16;"
                 :: "r"(dst), "l"(src));
}
#define CP_COMMIT() asm volatile("cp.async.commit_group;" ::: "memory")
#define CP_WAIT0() asm volatile("cp.async.wait_group 0;" ::: "memory")
#define CP_WAIT1() asm volatile("cp.async.wait_group 1;" ::: "memory")
#define CP_WAIT2() asm volatile("cp.async.wait_group 2;" ::: "memory")

__device__ __forceinline__ void ldsm4(uint32_t* r, uint32_t addr) {
    asm volatile("ldmatrix.sync.aligned.m8n8.x4.shared.b16 {%0,%1,%2,%3}, [%4];"
                 : "=r"(r[0]), "=r"(r[1]), "=r"(r[2]), "=r"(r[3]) : "r"(addr));
}

__device__ __forceinline__ void ldsm4t(uint32_t* r, uint32_t addr) {
    asm volatile("ldmatrix.sync.aligned.m8n8.x4.trans.shared.b16 {%0,%1,%2,%3}, [%4];"
                 : "=r"(r[0]), "=r"(r[1]), "=r"(r[2]), "=r"(r[3]) : "r"(addr));
}

__device__ __forceinline__ void mma16816(float* c, const uint32_t* a, const uint32_t* b) {
    asm volatile(
        "mma.sync.aligned.m16n8k16.row.col.f32.bf16.bf16.f32 "
        "{%0,%1,%2,%3}, {%4,%5,%6,%7}, {%8,%9}, {%0,%1,%2,%3};"
        : "+f"(c[0]), "+f"(c[1]), "+f"(c[2]), "+f"(c[3])
        : "r"(a[0]), "r"(a[1]), "r"(a[2]), "r"(a[3]), "r"(b[0]), "r"(b[1]));
}

__device__ __forceinline__ void bsplit(float x, __nv_bfloat16& h, __nv_bfloat16& l) {
    h = __float2bfloat16(x);
    l = __float2bfloat16(x - __bfloat162float(h));
}

__device__ __forceinline__ void split_pack2(float a, float b, uint32_t& hi, uint32_t& lo) {
    __nv_bfloat16 ah, al, bh, bl;
    bsplit(a, ah, al);
    bsplit(b, bh, bl);
    hi = (uint32_t)__bfloat16_as_ushort(ah) | ((uint32_t)__bfloat16_as_ushort(bh) << 16);
    lo = (uint32_t)__bfloat16_as_ushort(al) | ((uint32_t)__bfloat16_as_ushort(bl) << 16);
}

#define SWZ128(x) ((x) ^ (((x) >> 3) & 0x70))

// ------------------------- split fp32 -> bf16 hi/lo ------------------------
__global__ void __launch_bounds__(256) split_bf16(const float* __restrict__ x,
                                                  __nv_bfloat16* __restrict__ hi,
                                                  __nv_bfloat16* __restrict__ lo,
                                                  int n4) {
    int i = blockIdx.x * 256 + threadIdx.x;
    if (i >= n4) return;
    float4 v = ((const float4*)x)[i];
    __nv_bfloat16 h0, l0, h1, l1, h2, l2, h3, l3;
    bsplit(v.x, h0, l0); bsplit(v.y, h1, l1);
    bsplit(v.z, h2, l2); bsplit(v.w, h3, l3);
    __nv_bfloat162 hh0 = {h0, h1}, hh1 = {h2, h3};
    __nv_bfloat162 ll0 = {l0, l1}, ll1 = {l2, l3};
    ((__nv_bfloat162*)hi)[2 * i] = hh0;
    ((__nv_bfloat162*)hi)[2 * i + 1] = hh1;
    ((__nv_bfloat162*)lo)[2 * i] = ll0;
    ((__nv_bfloat162*)lo)[2 * i + 1] = ll1;
}

// ------------------------- RoPE cos/sin table (fp64 trig) ------------------
__global__ void __launch_bounds__(64) rope_table(const void* __restrict__ pos_ids) {
    const int bs = blockIdx.x;
    const int d = threadIdx.x;  // 0..63
    const int* p32 = (const int*)pos_ids;
    const bool is64 = (p32[1] == 0) && (p32[3] == 0) && (p32[2 * NS + 1] == 0);
    const long long pv = is64 ? ((const long long*)pos_ids)[bs] : (long long)p32[bs];
    const double C_LN = 0.20503692777194264;  // ln(500000)/64
    const double invf = exp(-(double)d * C_LN);
    double sd, cd;
    sincos((double)pv * invf, &sd, &cd);
    g_cos[(size_t)bs * 64 + d] = (float)cd;
    g_sin[(size_t)bs * 64 + d] = (float)sd;
}

// ------------------------- QKV GEMM + fused clamp/RoPE/split ---------------
// 128x128 CTA tile (one full head per tile), 8 warps, 32x64 warp tile,
// BK=32, merged hi/lo SW128 rows. Epilogue: acc -> smem -> clamp -> rope
// -> bf16 hi/lo scatter. No fp32 C output.
#define QST 32768
#define EPI_S 132                              // fp32 row stride in epilogue
#define QSMEM (128 * EPI_S * 4)                // 67584 > 2*QST
__global__ void __launch_bounds__(256, 2) gemm_qkv_rope(
    const __nv_bfloat16* __restrict__ Ahi, const __nv_bfloat16* __restrict__ Alo,
    const __nv_bfloat16* __restrict__ Bhi, const __nv_bfloat16* __restrict__ Blo) {
    extern __shared__ char smem[];
    const uint32_t sb = smem_u32(smem);
    const int tid = threadIdx.x;
    const int lane = tid & 31;
    const int wid = tid >> 5;
    const int wm = (wid & 3) * 32;
    const int wn = (wid >> 2) * 64;
    const int bx = blockIdx.x;
    const int by = blockIdx.y;
    const int K = NHID;

    auto load_stage = [&](int st, int kt) {
        const uint32_t s = sb + st * QST;
        const int kc = kt * 32;
#pragma unroll
        for (int i = 0; i < 4; i++) {
            const int q = tid + i * 256;
            const int r = q >> 3, c = q & 7;
            const __nv_bfloat16* srcA =
                (c < 4 ? Ahi : Alo) + (size_t)(by * 128 + r) * K + kc + (c & 3) * 8;
            cp16(s + SWZ128(r * 128 + c * 16), srcA);
        }
#pragma unroll
        for (int i = 0; i < 4; i++) {
            const int q = tid + i * 256;
            const int r = q >> 3, c = q & 7;
            const __nv_bfloat16* srcB =
                (c < 4 ? Bhi : Blo) + (size_t)(bx * 128 + r) * K + kc + (c & 3) * 8;
            cp16(s + 16384 + SWZ128(r * 128 + c * 16), srcB);
        }
    };

    float acc[2][8][4];
#pragma unroll
    for (int i = 0; i < 2; i++)
#pragma unroll
        for (int j = 0; j < 8; j++)
#pragma unroll
            for (int e = 0; e < 4; e++) acc[i][j][e] = 0.0f;

    const int KT = K >> 5;
    load_stage(0, 0);
    CP_COMMIT();

    const int lr = (lane & 7) + ((lane >> 3) & 1) * 8;
    const int lc = lane >> 4;

    for (int kt = 0; kt < KT; kt++) {
        CP_WAIT0();
        __syncthreads();
        if (kt + 1 < KT) {
            load_stage((kt + 1) & 1, kt + 1);
            CP_COMMIT();
        }
        const uint32_t s = sb + (kt & 1) * QST;
#pragma unroll
        for (int ks = 0; ks < 2; ks++) {
            const int ch = 2 * ks + lc;
            uint32_t bh[8][2], bl[8][2];
#pragma unroll
            for (int nf2 = 0; nf2 < 4; nf2++) {
                const uint32_t rb = (wn + nf2 * 16 + lr) * 128;
                uint32_t th[4], tl[4];
                ldsm4(th, s + 16384 + SWZ128(rb + ch * 16));
                ldsm4(tl, s + 16384 + SWZ128(rb + (ch + 4) * 16));
                bh[nf2 * 2][0] = th[0]; bh[nf2 * 2 + 1][0] = th[1];
                bh[nf2 * 2][1] = th[2]; bh[nf2 * 2 + 1][1] = th[3];
                bl[nf2 * 2][0] = tl[0]; bl[nf2 * 2 + 1][0] = tl[1];
                bl[nf2 * 2][1] = tl[2]; bl[nf2 * 2 + 1][1] = tl[3];
            }
#pragma unroll
            for (int mf = 0; mf < 2; mf++) {
                uint32_t ah[4], al[4];
                const uint32_t ra = (wm + mf * 16 + lr) * 128;
                ldsm4(ah, s + SWZ128(ra + ch * 16));
                ldsm4(al, s + SWZ128(ra + (ch + 4) * 16));
#pragma unroll
                for (int nf = 0; nf < 8; nf++) mma16816(acc[mf][nf], ah, bh[nf]);
#pragma unroll
                for (int nf = 0; nf < 8; nf++) mma16816(acc[mf][nf], ah, bl[nf]);
#pragma unroll
                for (int nf = 0; nf < 8; nf++) mma16816(acc[mf][nf], al, bh[nf]);
            }
        }
    }

    // ---- fused epilogue: acc -> smem (fp32) -> clamp/rope/split -> global
    __syncthreads();
    float* sepi = (float*)smem;
    const int erow = lane >> 2;
    const int ecol = (lane & 3) * 2;
#pragma unroll
    for (int mf = 0; mf < 2; mf++)
#pragma unroll
        for (int nf = 0; nf < 8; nf++) {
            const int r = wm + mf * 16 + erow;
            const int c = wn + nf * 8 + ecol;
            sepi[r * EPI_S + c] = acc[mf][nf][0];
            sepi[r * EPI_S + c + 1] = acc[mf][nf][1];
            sepi[(r + 8) * EPI_S + c] = acc[mf][nf][2];
            sepi[(r + 8) * EPI_S + c + 1] = acc[mf][nf][3];
        }
    __syncthreads();

    const int d = tid & 63;        // 0..63 (pairs with d+64)
    const int rg = tid >> 6;       // 0..3 row groups of 32
    const int b = by >> 4;         // 128 rows stay within one batch
    const int s0 = (by * 128) & (NS - 1);
    const float qscale = 0.08838834764831845f;

    __nv_bfloat16 *dsth, *dstl;
    bool dorope;
    float oscale = 1.0f;
    if (bx < 16) {                 // Q head bx
        size_t base = ((size_t)(b * NHEADS + bx) * NS + s0) * DHEAD;
        dsth = g_qh + base; dstl = g_ql + base;
        dorope = true; oscale = qscale;
    } else if (bx < 20) {          // K head bx-16
        size_t base = ((size_t)(b * NKVH + (bx - 16)) * NS + s0) * DHEAD;
        dsth = g_kh + base; dstl = g_kl + base;
        dorope = true;
    } else {                       // V head bx-20
        size_t base = ((size_t)(b * NKVH + (bx - 20)) * NS + s0) * DHEAD;
        dsth = g_vh + base; dstl = g_vl + base;
        dorope = false;
    }

#pragma unroll 4
    for (int i = 0; i < 32; i++) {
        const int r = rg * 32 + i;
        float x = sepi[r * EPI_S + d];
        float y = sepi[r * EPI_S + d + 64];
        x = fminf(8.0f, fmaxf(-8.0f, x));
        y = fminf(8.0f, fmaxf(-8.0f, y));
        float ox, oy;
        if (dorope) {
            const size_t ti = (size_t)(by * 128 + r) * 64 + d;
            const float c = g_cos[ti];
            const float sn = g_sin[ti];
            ox = (x * c - y * sn) * oscale;
            oy = (y * c + x * sn) * oscale;
        } else {
            ox = x; oy = y;
        }
        __nv_bfloat16 hh, ll;
        const size_t o = (size_t)r * DHEAD + d;
        bsplit(ox, hh, ll);
        dsth[o] = hh; dstl[o] = ll;
        bsplit(oy, hh, ll);
        dsth[o + 64] = hh; dstl[o + 64] = ll;
    }
}

// ------------------------- HMMA GEMM (out-proj): C = A * B^T ---------------
// R8 config: 128x64 CTA, 32x32 warp tile, 48KB smem, 3 CTAs/SM.
#define GST 24576
#define GSMEM (2 * GST)

__global__ void __launch_bounds__(256, 3) gemm_hmma(const __nv_bfloat16* __restrict__ Ahi,
                                                    const __nv_bfloat16* __restrict__ Alo,
                                                    const __nv_bfloat16* __restrict__ Bhi,
                                                    const __nv_bfloat16* __restrict__ Blo,
                                                    float* __restrict__ C,
                                                    int M, int N, int K) {
    extern __shared__ char smem[];
    const uint32_t sb = smem_u32(smem);
    const int tid = threadIdx.x;
    const int lane = tid & 31;
    const int wid = tid >> 5;
    const int wm = (wid & 3) * 32;
    const int wn = (wid >> 2) * 32;
    const int bx = blockIdx.x;
    const int by = blockIdx.y;

    auto load_stage = [&](int st, int kt) {
        const uint32_t s = sb + st * GST;
        const int kc = kt * 32;
#pragma unroll
        for (int i = 0; i < 4; i++) {
            const int q = tid + i * 256;
            const int r = q >> 3, c = q & 7;
            const __nv_bfloat16* srcA =
                (c < 4 ? Ahi : Alo) + (size_t)(by * 128 + r) * K + kc + (c & 3) * 8;
            cp16(s + SWZ128(r * 128 + c * 16), srcA);
        }
#pragma unroll
        for (int i = 0; i < 2; i++) {
            const int q = tid + i * 256;
            const int r = q >> 3, c = q & 7;
            const __nv_bfloat16* srcB =
                (c < 4 ? Bhi : Blo) + (size_t)(bx * 64 + r) * K + kc + (c & 3) * 8;
            cp16(s + 16384 + SWZ128(r * 128 + c * 16), srcB);
        }
    };

    float acc[2][4][4];
#pragma unroll
    for (int i = 0; i < 2; i++)
#pragma unroll
        for (int j = 0; j < 4; j++)
#pragma unroll
            for (int e = 0; e < 4; e++) acc[i][j][e] = 0.0f;

    const int KT = K >> 5;
    load_stage(0, 0);
    CP_COMMIT();

    const int lr = (lane & 7) + ((lane >> 3) & 1) * 8;
    const int lc = lane >> 4;

    for (int kt = 0; kt < KT; kt++) {
        CP_WAIT0();
        __syncthreads();
        if (kt + 1 < KT) {
            load_stage((kt + 1) & 1, kt + 1);
            CP_COMMIT();
        }
        const uint32_t s = sb + (kt & 1) * GST;
#pragma unroll
        for (int ks = 0; ks < 2; ks++) {
            const int ch = 2 * ks + lc;
            uint32_t bh[4][2], bl[4][2];
#pragma unroll
            for (int nf2 = 0; nf2 < 2; nf2++) {
                const uint32_t rb = (wn + nf2 * 16 + lr) * 128;
                uint32_t th[4], tl[4];
                ldsm4(th, s + 16384 + SWZ128(rb + ch * 16));
                ldsm4(tl, s + 16384 + SWZ128(rb + (ch + 4) * 16));
                bh[nf2 * 2][0] = th[0]; bh[nf2 * 2 + 1][0] = th[1];
                bh[nf2 * 2][1] = th[2]; bh[nf2 * 2 + 1][1] = th[3];
                bl[nf2 * 2][0] = tl[0]; bl[nf2 * 2 + 1][0] = tl[1];
                bl[nf2 * 2][1] = tl[2]; bl[nf2 * 2 + 1][1] = tl[3];
            }
#pragma unroll
            for (int mf = 0; mf < 2; mf++) {
                uint32_t ah[4], al[4];
                const uint32_t ra = (wm + mf * 16 + lr) * 128;
                ldsm4(ah, s + SWZ128(ra + ch * 16));
                ldsm4(al, s + SWZ128(ra + (ch + 4) * 16));
#pragma unroll
                for (int nf = 0; nf < 4; nf++) mma16816(acc[mf][nf], ah, bh[nf]);
#pragma unroll
                for (int nf = 0; nf < 4; nf++) mma16816(acc[mf][nf], ah, bl[nf]);
#pragma unroll
                for (int nf = 0; nf < 4; nf++) mma16816(acc[mf][nf], al, bh[nf]);
            }
        }
    }

    const int erow = lane >> 2;
    const int ecol = (lane & 3) * 2;
#pragma unroll
    for (int mf = 0; mf < 2; mf++) {
#pragma unroll
        for (int nf = 0; nf < 4; nf++) {
            float* c = acc[mf][nf];
            const int row = by * 128 + wm + mf * 16 + erow;
            const int col = bx * 64 + wn + nf * 8 + ecol;
            float2 v0 = {c[0], c[1]};
            float2 v1 = {c[2], c[3]};
            *(float2*)(C + (size_t)row * N + col) = v0;
            *(float2*)(C + (size_t)(row + 8) * N + col) = v1;
        }
    }
}

// ------------------------- tensor-core flash attention ---------------------
#define AQ_HI 0
#define AQ_LO 17408
#define AK_HI 34816
#define AK_LO 52224
#define AV_HI 69632
#define AV_LO 87040
#define ATTN_SMEM 104448

__global__ void __launch_bounds__(128) flash_attn_tc() {
    extern __shared__ char smem[];
    const uint32_t sb = smem_u32(smem);
    const int tid = threadIdx.x;
    const int lane = tid & 31;
    const int w = tid >> 5;
    const int qb = gridDim.x - 1 - blockIdx.x;
    const int h = blockIdx.y;
    const int b = blockIdx.z;
    const int hk = h >> 2;
    const int q0 = qb * 64;
    const int wrow = w * 16;

    const __nv_bfloat16* Qh = g_qh + ((size_t)(b * NHEADS + h) * NS + q0) * DHEAD;
    const __nv_bfloat16* Ql = g_ql + ((size_t)(b * NHEADS + h) * NS + q0) * DHEAD;
    const __nv_bfloat16* Kh = g_kh + ((size_t)(b * NKVH + hk) * NS) * DHEAD;
    const __nv_bfloat16* Kl = g_kl + ((size_t)(b * NKVH + hk) * NS) * DHEAD;
    const __nv_bfloat16* Vh = g_vh + ((size_t)(b * NKVH + hk) * NS) * DHEAD;
    const __nv_bfloat16* Vl = g_vl + ((size_t)(b * NKVH + hk) * NS) * DHEAD;

    auto load_K = [&](int t) {
#pragma unroll
        for (int i = 0; i < 8; i++) {
            int q = tid + i * 128;
            int r = q >> 4, cc = q & 15;
            cp16(sb + AK_HI + r * 272 + cc * 16, Kh + (size_t)(t * 64 + r) * DHEAD + cc * 8);
            cp16(sb + AK_LO + r * 272 + cc * 16, Kl + (size_t)(t * 64 + r) * DHEAD + cc * 8);
        }
    };
    auto load_V = [&](int t) {
#pragma unroll
        for (int i = 0; i < 8; i++) {
            int q = tid + i * 128;
            int r = q >> 4, cc = q & 15;
            cp16(sb + AV_HI + r * 272 + cc * 16, Vh + (size_t)(t * 64 + r) * DHEAD + cc * 8);
            cp16(sb + AV_LO + r * 272 + cc * 16, Vl + (size_t)(t * 64 + r) * DHEAD + cc * 8);
        }
    };

#pragma unroll
    for (int i = 0; i < 8; i++) {
        int q = tid + i * 128;
        int r = q >> 4, cc = q & 15;
        cp16(sb + AQ_HI + r * 272 + cc * 16, Qh + (size_t)r * DHEAD + cc * 8);
        cp16(sb + AQ_LO + r * 272 + cc * 16, Ql + (size_t)r * DHEAD + cc * 8);
    }
    CP_COMMIT();
    load_K(0);
    CP_COMMIT();
    load_V(0);
    CP_COMMIT();

    const int lr = (lane & 7) + ((lane >> 3) & 1) * 8;
    const int lc16 = (lane >> 4) * 16;

    CP_WAIT2();
    __syncthreads();
    uint32_t qfh[8][4], qfl[8][4];
#pragma unroll
    for (int kc = 0; kc < 8; kc++) {
        const uint32_t qaddr = sb + AQ_HI + (wrow + lr) * 272 + kc * 32 + lc16;
        ldsm4(qfh[kc], qaddr);
        ldsm4(qfl[kc], qaddr + (AQ_LO - AQ_HI));
    }

    float of[16][4];
#pragma unroll
    for (int f = 0; f < 16; f++)
#pragma unroll
        for (int e = 0; e < 4; e++) of[f][e] = 0.0f;
    float m0 = -1e30f, m1 = -1e30f, l0 = 0.0f, l1 = 0.0f;

    for (int t = 0; t <= qb; t++) {
        CP_WAIT1();
        __syncthreads();

        float sc[8][4];
#pragma unroll
        for (int nf = 0; nf < 8; nf++)
#pragma unroll
            for (int e = 0; e < 4; e++) sc[nf][e] = 0.0f;

#pragma unroll
        for (int kc = 0; kc < 8; kc++) {
            uint32_t bh0[4][2], bh1[4][2], bl0[4][2], bl1[4][2];
#pragma unroll
            for (int np = 0; np < 4; np++) {
                uint32_t kh4[4], kl4[4];
                const uint32_t kaddr = sb + AK_HI + (np * 16 + lr) * 272 + kc * 32 + lc16;
                ldsm4(kh4, kaddr);
                ldsm4(kl4, kaddr + (AK_LO - AK_HI));
                bh0[np][0] = kh4[0]; bh0[np][1] = kh4[2];
                bh1[np][0] = kh4[1]; bh1[np][1] = kh4[3];
                bl0[np][0] = kl4[0]; bl0[np][1] = kl4[2];
                bl1[np][0] = kl4[1]; bl1[np][1] = kl4[3];
            }
#pragma unroll
            for (int np = 0; np < 4; np++) {
                mma16816(sc[2 * np], qfh[kc], bh0[np]);
                mma16816(sc[2 * np + 1], qfh[kc], bh1[np]);
            }
#pragma unroll
            for (int np = 0; np < 4; np++) {
                mma16816(sc[2 * np], qfh[kc], bl0[np]);
                mma16816(sc[2 * np + 1], qfh[kc], bl1[np]);
            }
#pragma unroll
            for (int np = 0; np < 4; np++) {
                mma16816(sc[2 * np], qfl[kc], bh0[np]);
                mma16816(sc[2 * np + 1], qfl[kc], bh1[np]);
            }
        }

        __syncthreads();
        if (t < qb) {
            load_K(t + 1);
            CP_COMMIT();
        }

        if (t == qb) {
            const int row0 = q0 + wrow + (lane >> 2);
            const int colb = t * 64 + 2 * (lane & 3);
#pragma unroll
            for (int nf = 0; nf < 8; nf++) {
                const int cb = colb + 8 * nf;
                if (cb > row0) sc[nf][0] = -1e30f;
                if (cb + 1 > row0) sc[nf][1] = -1e30f;
                if (cb > row0 + 8) sc[nf][2] = -1e30f;
                if (cb + 1 > row0 + 8) sc[nf][3] = -1e30f;
            }
        }

        float rmax0 = -1e30f, rmax1 = -1e30f;
#pragma unroll
        for (int nf = 0; nf < 8; nf++) {
            rmax0 = fmaxf(rmax0, fmaxf(sc[nf][0], sc[nf][1]));
            rmax1 = fmaxf(rmax1, fmaxf(sc[nf][2], sc[nf][3]));
        }
        rmax0 = fmaxf(rmax0, __shfl_xor_sync(0xffffffffu, rmax0, 1));
        rmax0 = fmaxf(rmax0, __shfl_xor_sync(0xffffffffu, rmax0, 2));
        rmax1 = fmaxf(rmax1, __shfl_xor_sync(0xffffffffu, rmax1, 1));
        rmax1 = fmaxf(rmax1, __shfl_xor_sync(0xffffffffu, rmax1, 2));
        const float mn0 = fmaxf(m0, rmax0);
        const float mn1 = fmaxf(m1, rmax1);
        const float scl0 = __expf(m0 - mn0);
        const float scl1 = __expf(m1 - mn1);
        float rs0 = 0.0f, rs1 = 0.0f;
#pragma unroll
        for (int nf = 0; nf < 8; nf++) {
            sc[nf][0] = __expf(sc[nf][0] - mn0); rs0 += sc[nf][0];
            sc[nf][1] = __expf(sc[nf][1] - mn0); rs0 += sc[nf][1];
            sc[nf][2] = __expf(sc[nf][2] - mn1); rs1 += sc[nf][2];
            sc[nf][3] = __expf(sc[nf][3] - mn1); rs1 += sc[nf][3];
        }
        rs0 += __shfl_xor_sync(0xffffffffu, rs0, 1);
        rs0 += __shfl_xor_sync(0xffffffffu, rs0, 2);
        rs1 += __shfl_xor_sync(0xffffffffu, rs1, 1);
        rs1 += __shfl_xor_sync(0xffffffffu, rs1, 2);
        l0 = l0 * scl0 + rs0;
        l1 = l1 * scl1 + rs1;
        m0 = mn0;
        m1 = mn1;
#pragma unroll
        for (int f = 0; f < 16; f++) {
            of[f][0] *= scl0; of[f][1] *= scl0;
            of[f][2] *= scl1; of[f][3] *= scl1;
        }

        if (t < qb) CP_WAIT1(); else CP_WAIT0();
        __syncthreads();

#pragma unroll
        for (int kb = 0; kb < 4; kb++) {
            uint32_t ph[4], pl[4];
            split_pack2(sc[2 * kb][0], sc[2 * kb][1], ph[0], pl[0]);
            split_pack2(sc[2 * kb][2], sc[2 * kb][3], ph[1], pl[1]);
            split_pack2(sc[2 * kb + 1][0], sc[2 * kb + 1][1], ph[2], pl[2]);
            split_pack2(sc[2 * kb + 1][2], sc[2 * kb + 1][3], ph[3], pl[3]);
            const uint32_t vbase = sb + AV_HI + (kb * 16 + lr) * 272 + lc16;
#pragma unroll
            for (int npp = 0; npp < 4; npp++) {
                const int np0 = 2 * npp, np1 = 2 * npp + 1;
                uint32_t vhA[4], vlA[4], vhB[4], vlB[4];
                ldsm4t(vhA, vbase + np0 * 32);
                ldsm4t(vlA, vbase + np0 * 32 + (AV_LO - AV_HI));
                ldsm4t(vhB, vbase + np1 * 32);
                ldsm4t(vlB, vbase + np1 * 32 + (AV_LO - AV_HI));
                uint32_t h0A[2] = {vhA[0], vhA[1]}, h1A[2] = {vhA[2], vhA[3]};
                uint32_t l0A[2] = {vlA[0], vlA[1]}, l1A[2] = {vlA[2], vlA[3]};
                uint32_t h0B[2] = {vhB[0], vhB[1]}, h1B[2] = {vhB[2], vhB[3]};
                uint32_t l0B[2] = {vlB[0], vlB[1]}, l1B[2] = {vlB[2], vlB[3]};
                mma16816(of[2 * np0], ph, h0A);
                mma16816(of[2 * np0 + 1], ph, h1A);
                mma16816(of[2 * np1], ph, h0B);
                mma16816(of[2 * np1 + 1], ph, h1B);
                mma16816(of[2 * np0], ph, l0A);
                mma16816(of[2 * np0 + 1], ph, l1A);
                mma16816(of[2 * np1], ph, l0B);
                mma16816(of[2 * np1 + 1], ph, l1B);
                mma16816(of[2 * np0], pl, h0A);
                mma16816(of[2 * np0 + 1], pl, h1A);
                mma16816(of[2 * np1], pl, h0B);
                mma16816(of[2 * np1 + 1], pl, h1B);
            }
        }

        __syncthreads();
        if (t < qb) {
            load_V(t + 1);
            CP_COMMIT();
        }
    }

    const float inv0 = 1.0f / l0;
    const float inv1 = 1.0f / l1;
    const int r0g = q0 + wrow + (lane >> 2);
    const int colb = 2 * (lane & 3);
#pragma unroll
    for (int nf = 0; nf < 16; nf++) {
        const int col = h * DHEAD + 8 * nf + colb;
        float x0 = of[nf][0] * inv0, y0 = of[nf][1] * inv0;
        float x1 = of[nf][2] * inv1, y1 = of[nf][3] * inv1;
        __nv_bfloat16 xh, xl, yh, yl;
        bsplit(x0, xh, xl); bsplit(y0, yh, yl);
        size_t i0 = (size_t)(b * NS + r0g) * NHID + col;
        *(__nv_bfloat162*)(g_at_hi + i0) = {xh, yh};
        *(__nv_bfloat162*)(g_at_lo + i0) = {xl, yl};
        bsplit(x1, xh, xl); bsplit(y1, yh, yl);
        size_t i1 = (size_t)(b * NS + r0g + 8) * NHID + col;
        *(__nv_bfloat162*)(g_at_hi + i1) = {xh, yh};
        *(__nv_bfloat162*)(g_at_lo + i1) = {xl, yl};
    }
}

// ------------------------- launch ------------------------------------------
extern "C" void kernel_launch(void* const* d_in, const int* in_sizes, int n_in,
                              void* d_out, int out_size) {
    const float* hidden = (const float*)d_in[0];
    const void* pos = d_in[1];
    const float* Wqkv = (const float*)d_in[2];
    const float* Wout = (const float*)d_in[3];
    float* out = (float*)d_out;

    void *p_hh, *p_hl, *p_w1h, *p_w1l, *p_w2h, *p_w2l, *p_ah, *p_al;
    cudaGetSymbolAddress(&p_hh, g_hid_hi);
    cudaGetSymbolAddress(&p_hl, g_hid_lo);
    cudaGetSymbolAddress(&p_w1h, g_w1_hi);
    cudaGetSymbolAddress(&p_w1l, g_w1_lo);
    cudaGetSymbolAddress(&p_w2h, g_w2_hi);
    cudaGetSymbolAddress(&p_w2l, g_w2_lo);
    cudaGetSymbolAddress(&p_ah, g_at_hi);
    cudaGetSymbolAddress(&p_al, g_at_lo);

    const int nHid = NB * NS * NHID;
    const int nW1 = NQKV * NHID;
    const int nW2 = NHID * NHID;

    split_bf16<<<(nHid / 4 + 255) / 256, 256>>>(hidden, (__nv_bfloat16*)p_hh,
                                                (__nv_bfloat16*)p_hl, nHid / 4);
    split_bf16<<<(nW1 / 4 + 255) / 256, 256>>>(Wqkv, (__nv_bfloat16*)p_w1h,
                                               (__nv_bfloat16*)p_w1l, nW1 / 4);
    split_bf16<<<(nW2 / 4 + 255) / 256, 256>>>(Wout, (__nv_bfloat16*)p_w2h,
                                               (__nv_bfloat16*)p_w2l, nW2 / 4);
    rope_table<<<NB * NS, 64>>>(pos);

    // 1) QKV projection + clamp + RoPE + split (fused)
    {
        cudaFuncSetAttribute(gemm_qkv_rope, cudaFuncAttributeMaxDynamicSharedMemorySize, QSMEM);
        dim3 grid(NQKV / 128, (NB * NS) / 128);
        gemm_qkv_rope<<<grid, 256, QSMEM>>>(
            (const __nv_bfloat16*)p_hh, (const __nv_bfloat16*)p_hl,
            (const __nv_bfloat16*)p_w1h, (const __nv_bfloat16*)p_w1l);
    }
    // 2) tensor-core causal flash attention
    {
        cudaFuncSetAttribute(flash_attn_tc, cudaFuncAttributeMaxDynamicSharedMemorySize, ATTN_SMEM);
        dim3 grid(NS / 64, NHEADS, NB);
        flash_attn_tc<<<grid, 128, ATTN_SMEM>>>();
    }
    // 3) output projection
    {
        cudaFuncSetAttribute(gemm_hmma, cudaFuncAttributeMaxDynamicSharedMemorySize, GSMEM);
        dim3 grid(NHID / 64, (NB * NS) / 128);
        gemm_hmma<<<grid, 256, GSMEM>>>(
            (const __nv_bfloat16*)p_ah, (const __nv_bfloat16*)p_al,
            (const __nv_bfloat16*)p_w2h, (const __nv_bfloat16*)p_w2l,
            out, NB * NS, NHID, NHID);
    }
}

// round 11
// speedup vs baseline: 1.3516x; 1.3516x over previous
#include <cuda_runtime.h>
#include <cuda_fp16.h>
#include <cstdint>
#include <math.h>

#define NB 2
#define NS 2048
#define NHID 2048
#define NHEADS 16
#define NKVH 4
#define DHEAD 128
#define NQKV 3072

// ------------------------- scratch (static device globals; no allocs) ------
static __device__ float g_qkv[(size_t)NB * NS * NQKV];

static __device__ __half g_qh[(size_t)NB * NHEADS * NS * DHEAD];
static __device__ __half g_ql[(size_t)NB * NHEADS * NS * DHEAD];
static __device__ __half g_kh[(size_t)NB * NKVH * NS * DHEAD];
static __device__ __half g_kl[(size_t)NB * NKVH * NS * DHEAD];
static __device__ __half g_vh[(size_t)NB * NKVH * NS * DHEAD];
static __device__ __half g_vl[(size_t)NB * NKVH * NS * DHEAD];

static __device__ __half g_hid[(size_t)NB * NS * NHID];        // single fp16
static __device__ __half g_w1_hi[(size_t)NQKV * NHID];
static __device__ __half g_w1_lo[(size_t)NQKV * NHID];
static __device__ __half g_w2_hi[(size_t)NHID * NHID];
static __device__ __half g_w2_lo[(size_t)NHID * NHID];
static __device__ __half g_at[(size_t)NB * NS * NHID];         // single fp16

// ------------------------- PTX helpers (baseline ISA only) -----------------
__device__ __forceinline__ uint32_t smem_u32(const void* p) {
    uint32_t a;
    asm("{ .reg .u64 t; cvta.to.shared.u64 t, %1; cvt.u32.u64 %0, t; }"
        : "=r"(a) : "l"(p));
    return a;
}

__device__ __forceinline__ void cp16(uint32_t dst, const void* src) {
    asm volatile("cp.async.cg.shared.global [%0], [%1], 16;"
                 :: "r"(dst), "l"(src));
}
#define CP_COMMIT() asm volatile("cp.async.commit_group;" ::: "memory")
#define CP_WAIT0() asm volatile("cp.async.wait_group 0;" ::: "memory")
#define CP_WAIT1() asm volatile("cp.async.wait_group 1;" ::: "memory")
#define CP_WAIT2() asm volatile("cp.async.wait_group 2;" ::: "memory")

__device__ __forceinline__ void ldsm4(uint32_t* r, uint32_t addr) {
    asm volatile("ldmatrix.sync.aligned.m8n8.x4.shared.b16 {%0,%1,%2,%3}, [%4];"
                 : "=r"(r[0]), "=r"(r[1]), "=r"(r[2]), "=r"(r[3]) : "r"(addr));
}

__device__ __forceinline__ void ldsm4t(uint32_t* r, uint32_t addr) {
    asm volatile("ldmatrix.sync.aligned.m8n8.x4.trans.shared.b16 {%0,%1,%2,%3}, [%4];"
                 : "=r"(r[0]), "=r"(r[1]), "=r"(r[2]), "=r"(r[3]) : "r"(addr));
}

__device__ __forceinline__ void mma16816(float* c, const uint32_t* a, const uint32_t* b) {
    asm volatile(
        "mma.sync.aligned.m16n8k16.row.col.f32.f16.f16.f32 "
        "{%0,%1,%2,%3}, {%4,%5,%6,%7}, {%8,%9}, {%0,%1,%2,%3};"
        : "+f"(c[0]), "+f"(c[1]), "+f"(c[2]), "+f"(c[3])
        : "r"(a[0]), "r"(a[1]), "r"(a[2]), "r"(a[3]), "r"(b[0]), "r"(b[1]));
}

__device__ __forceinline__ void hsplit(float x, __half& h, __half& l) {
    h = __float2half_rn(x);
    l = __float2half_rn(x - __half2float(h));
}

__device__ __forceinline__ void split_pack2(float a, float b, uint32_t& hi, uint32_t& lo) {
    __half ah, al, bh, bl;
    hsplit(a, ah, al);
    hsplit(b, bh, bl);
    hi = (uint32_t)__half_as_ushort(ah) | ((uint32_t)__half_as_ushort(bh) << 16);
    lo = (uint32_t)__half_as_ushort(al) | ((uint32_t)__half_as_ushort(bl) << 16);
}

#define SWZ128(x) ((x) ^ (((x) >> 3) & 0x70))
#define SWZ64(x) ((x) ^ (((x) >> 3) & 0x30))

// ------------------------- fp32 -> fp16 convert / split --------------------
__global__ void __launch_bounds__(256) conv_half(const float* __restrict__ x,
                                                 __half* __restrict__ o, int n4) {
    int i = blockIdx.x * 256 + threadIdx.x;
    if (i >= n4) return;
    float4 v = ((const float4*)x)[i];
    __half2 a = {__float2half_rn(v.x), __float2half_rn(v.y)};
    __half2 b = {__float2half_rn(v.z), __float2half_rn(v.w)};
    ((__half2*)o)[2 * i] = a;
    ((__half2*)o)[2 * i + 1] = b;
}

__global__ void __launch_bounds__(256) split_half(const float* __restrict__ x,
                                                  __half* __restrict__ hi,
                                                  __half* __restrict__ lo, int n4) {
    int i = blockIdx.x * 256 + threadIdx.x;
    if (i >= n4) return;
    float4 v = ((const float4*)x)[i];
    __half h0, l0, h1, l1, h2, l2, h3, l3;
    hsplit(v.x, h0, l0); hsplit(v.y, h1, l1);
    hsplit(v.z, h2, l2); hsplit(v.w, h3, l3);
    __half2 hh0 = {h0, h1}, hh1 = {h2, h3};
    __half2 ll0 = {l0, l1}, ll1 = {l2, l3};
    ((__half2*)hi)[2 * i] = hh0;
    ((__half2*)hi)[2 * i + 1] = hh1;
    ((__half2*)lo)[2 * i] = ll0;
    ((__half2*)lo)[2 * i + 1] = ll1;
}

// ------------------------- 2-pass HMMA GEMM: C = A * B^T -------------------
// A single fp16, B hi/lo fp16. CTA 128x64, 8 warps (32x32), BK=32.
// A tile: 128 x 64B rows (SWZ64); B tile: 64 x 128B rows (hi ch0-3, lo ch4-7).
// 32KB smem (2 stages), 3 CTAs/SM.
#define GST 16384
#define GSMEM (2 * GST)

template <int CLAMP>
__global__ void __launch_bounds__(256, 3) gemm_2p(const __half* __restrict__ A,
                                                  const __half* __restrict__ Bhi,
                                                  const __half* __restrict__ Blo,
                                                  float* __restrict__ C,
                                                  int M, int N, int K) {
    extern __shared__ char smem[];
    const uint32_t sb = smem_u32(smem);
    const int tid = threadIdx.x;
    const int lane = tid & 31;
    const int wid = tid >> 5;
    const int wm = (wid & 3) * 32;
    const int wn = (wid >> 2) * 32;
    const int bx = blockIdx.x;
    const int by = blockIdx.y;

    auto load_stage = [&](int st, int kt) {
        const uint32_t s = sb + st * GST;
        const int kc = kt * 32;
#pragma unroll
        for (int i = 0; i < 2; i++) {  // A: 128 rows x 4 chunks = 512 tasks
            const int q = tid + i * 256;
            const int r = q >> 2, c = q & 3;
            cp16(s + SWZ64(r * 64 + c * 16), A + (size_t)(by * 128 + r) * K + kc + c * 8);
        }
#pragma unroll
        for (int i = 0; i < 2; i++) {  // B: 64 rows x 8 chunks = 512 tasks
            const int q = tid + i * 256;
            const int r = q >> 3, c = q & 7;
            const __half* srcB =
                (c < 4 ? Bhi : Blo) + (size_t)(bx * 64 + r) * K + kc + (c & 3) * 8;
            cp16(s + 8192 + SWZ128(r * 128 + c * 16), srcB);
        }
    };

    float acc[2][4][4];
#pragma unroll
    for (int i = 0; i < 2; i++)
#pragma unroll
        for (int j = 0; j < 4; j++)
#pragma unroll
            for (int e = 0; e < 4; e++) acc[i][j][e] = 0.0f;

    const int KT = K >> 5;
    load_stage(0, 0);
    CP_COMMIT();

    const int lr = (lane & 7) + ((lane >> 3) & 1) * 8;
    const int lc = lane >> 4;

    for (int kt = 0; kt < KT; kt++) {
        CP_WAIT0();
        __syncthreads();
        if (kt + 1 < KT) {
            load_stage((kt + 1) & 1, kt + 1);
            CP_COMMIT();
        }
        const uint32_t s = sb + (kt & 1) * GST;
#pragma unroll
        for (int ks = 0; ks < 2; ks++) {
            const int ch = 2 * ks + lc;  // 0..3
            uint32_t bh[4][2], bl[4][2];
#pragma unroll
            for (int nf2 = 0; nf2 < 2; nf2++) {
                const uint32_t rb = (wn + nf2 * 16 + lr) * 128;
                uint32_t th[4], tl[4];
                ldsm4(th, s + 8192 + SWZ128(rb + ch * 16));
                ldsm4(tl, s + 8192 + SWZ128(rb + (ch + 4) * 16));
                bh[nf2 * 2][0] = th[0]; bh[nf2 * 2 + 1][0] = th[1];
                bh[nf2 * 2][1] = th[2]; bh[nf2 * 2 + 1][1] = th[3];
                bl[nf2 * 2][0] = tl[0]; bl[nf2 * 2 + 1][0] = tl[1];
                bl[nf2 * 2][1] = tl[2]; bl[nf2 * 2 + 1][1] = tl[3];
            }
#pragma unroll
            for (int mf = 0; mf < 2; mf++) {
                uint32_t ah[4];
                ldsm4(ah, s + SWZ64((wm + mf * 16 + lr) * 64 + ch * 16));
#pragma unroll
                for (int nf = 0; nf < 4; nf++) mma16816(acc[mf][nf], ah, bh[nf]);
#pragma unroll
                for (int nf = 0; nf < 4; nf++) mma16816(acc[mf][nf], ah, bl[nf]);
            }
        }
    }

    const int erow = lane >> 2;
    const int ecol = (lane & 3) * 2;
#pragma unroll
    for (int mf = 0; mf < 2; mf++) {
#pragma unroll
        for (int nf = 0; nf < 4; nf++) {
            float* c = acc[mf][nf];
            if (CLAMP) {
#pragma unroll
                for (int e = 0; e < 4; e++)
                    c[e] = fminf(8.0f, fmaxf(-8.0f, c[e]));
            }
            const int row = by * 128 + wm + mf * 16 + erow;
            const int col = bx * 64 + wn + nf * 8 + ecol;
            float2 v0 = {c[0], c[1]};
            float2 v1 = {c[2], c[3]};
            *(float2*)(C + (size_t)row * N + col) = v0;
            *(float2*)(C + (size_t)(row + 8) * N + col) = v1;
        }
    }
}

// ------------------------- RoPE + scatter to fp16 hi/lo --------------------
__global__ void __launch_bounds__(128) rope_scatter(const void* __restrict__ pos_ids) {
    const int bs = blockIdx.x;
    const int b = bs / NS;
    const int s = bs % NS;
    const int d = threadIdx.x;
    const int dm = d & 63;

    const int* p32 = (const int*)pos_ids;
    const bool is64 = (p32[1] == 0) && (p32[3] == 0) && (p32[2 * NS + 1] == 0);
    const long long pv = is64 ? ((const long long*)pos_ids)[bs] : (long long)p32[bs];

    const double p = (double)pv;
    const double C_LN = 0.20503692777194264;  // ln(500000)/64
    const double invf = exp(-(double)dm * C_LN);
    double sd, cd;
    sincos(p * invf, &sd, &cd);
    const float c = (float)cd;
    const float sn = (float)sd;
    const float sign = (d < 64) ? -1.0f : 1.0f;
    const float qscale = 0.08838834764831845f;

    const float* row = g_qkv + (size_t)bs * NQKV;

#pragma unroll
    for (int h = 0; h < NHEADS; h++) {
        float v = row[h * DHEAD + d];
        float pr = row[h * DHEAD + (d ^ 64)];
        float qv = (v * c + sign * pr * sn) * qscale;
        __half hh, ll;
        hsplit(qv, hh, ll);
        size_t idx = (((size_t)b * NHEADS + h) * NS + s) * DHEAD + d;
        g_qh[idx] = hh;
        g_ql[idx] = ll;
    }
#pragma unroll
    for (int h = 0; h < NKVH; h++) {
        float v = row[NHID + h * DHEAD + d];
        float pr = row[NHID + h * DHEAD + (d ^ 64)];
        float kv = v * c + sign * pr * sn;
        __half hh, ll;
        hsplit(kv, hh, ll);
        size_t idx = (((size_t)b * NKVH + h) * NS + s) * DHEAD + d;
        g_kh[idx] = hh;
        g_kl[idx] = ll;
        float vv = row[NHID + NKVH * DHEAD + h * DHEAD + d];
        hsplit(vv, hh, ll);
        g_vh[idx] = hh;
        g_vl[idx] = ll;
    }
}

// ------------------------- tensor-core flash attention ---------------------
// BM=64, BN=64, 4 warps. fp16 hi/lo 3-pass. V row-major; PV B-frags via
// ldmatrix.trans. Pipelined K/V prefetch. (R8 structure, fp16 dtype.)
#define AQ_HI 0
#define AQ_LO 17408
#define AK_HI 34816
#define AK_LO 52224
#define AV_HI 69632
#define AV_LO 87040
#define ATTN_SMEM 104448

__global__ void __launch_bounds__(128) flash_attn_tc() {
    extern __shared__ char smem[];
    const uint32_t sb = smem_u32(smem);
    const int tid = threadIdx.x;
    const int lane = tid & 31;
    const int w = tid >> 5;
    const int qb = gridDim.x - 1 - blockIdx.x;
    const int h = blockIdx.y;
    const int b = blockIdx.z;
    const int hk = h >> 2;
    const int q0 = qb * 64;
    const int wrow = w * 16;

    const __half* Qh = g_qh + ((size_t)(b * NHEADS + h) * NS + q0) * DHEAD;
    const __half* Ql = g_ql + ((size_t)(b * NHEADS + h) * NS + q0) * DHEAD;
    const __half* Kh = g_kh + ((size_t)(b * NKVH + hk) * NS) * DHEAD;
    const __half* Kl = g_kl + ((size_t)(b * NKVH + hk) * NS) * DHEAD;
    const __half* Vh = g_vh + ((size_t)(b * NKVH + hk) * NS) * DHEAD;
    const __half* Vl = g_vl + ((size_t)(b * NKVH + hk) * NS) * DHEAD;

    auto load_K = [&](int t) {
#pragma unroll
        for (int i = 0; i < 8; i++) {
            int q = tid + i * 128;
            int r = q >> 4, cc = q & 15;
            cp16(sb + AK_HI + r * 272 + cc * 16, Kh + (size_t)(t * 64 + r) * DHEAD + cc * 8);
            cp16(sb + AK_LO + r * 272 + cc * 16, Kl + (size_t)(t * 64 + r) * DHEAD + cc * 8);
        }
    };
    auto load_V = [&](int t) {
#pragma unroll
        for (int i = 0; i < 8; i++) {
            int q = tid + i * 128;
            int r = q >> 4, cc = q & 15;
            cp16(sb + AV_HI + r * 272 + cc * 16, Vh + (size_t)(t * 64 + r) * DHEAD + cc * 8);
            cp16(sb + AV_LO + r * 272 + cc * 16, Vl + (size_t)(t * 64 + r) * DHEAD + cc * 8);
        }
    };

#pragma unroll
    for (int i = 0; i < 8; i++) {
        int q = tid + i * 128;
        int r = q >> 4, cc = q & 15;
        cp16(sb + AQ_HI + r * 272 + cc * 16, Qh + (size_t)r * DHEAD + cc * 8);
        cp16(sb + AQ_LO + r * 272 + cc * 16, Ql + (size_t)r * DHEAD + cc * 8);
    }
    CP_COMMIT();
    load_K(0);
    CP_COMMIT();
    load_V(0);
    CP_COMMIT();

    const int lr = (lane & 7) + ((lane >> 3) & 1) * 8;
    const int lc16 = (lane >> 4) * 16;

    CP_WAIT2();
    __syncthreads();
    uint32_t qfh[8][4], qfl[8][4];
#pragma unroll
    for (int kc = 0; kc < 8; kc++) {
        const uint32_t qaddr = sb + AQ_HI + (wrow + lr) * 272 + kc * 32 + lc16;
        ldsm4(qfh[kc], qaddr);
        ldsm4(qfl[kc], qaddr + (AQ_LO - AQ_HI));
    }

    float of[16][4];
#pragma unroll
    for (int f = 0; f < 16; f++)
#pragma unroll
        for (int e = 0; e < 4; e++) of[f][e] = 0.0f;
    float m0 = -1e30f, m1 = -1e30f, l0 = 0.0f, l1 = 0.0f;

    for (int t = 0; t <= qb; t++) {
        CP_WAIT1();
        __syncthreads();

        float sc[8][4];
#pragma unroll
        for (int nf = 0; nf < 8; nf++)
#pragma unroll
            for (int e = 0; e < 4; e++) sc[nf][e] = 0.0f;

#pragma unroll
        for (int kc = 0; kc < 8; kc++) {
            uint32_t bh0[4][2], bh1[4][2], bl0[4][2], bl1[4][2];
#pragma unroll
            for (int np = 0; np < 4; np++) {
                uint32_t kh4[4], kl4[4];
                const uint32_t kaddr = sb + AK_HI + (np * 16 + lr) * 272 + kc * 32 + lc16;
                ldsm4(kh4, kaddr);
                ldsm4(kl4, kaddr + (AK_LO - AK_HI));
                bh0[np][0] = kh4[0]; bh0[np][1] = kh4[2];
                bh1[np][0] = kh4[1]; bh1[np][1] = kh4[3];
                bl0[np][0] = kl4[0]; bl0[np][1] = kl4[2];
                bl1[np][0] = kl4[1]; bl1[np][1] = kl4[3];
            }
#pragma unroll
            for (int np = 0; np < 4; np++) {
                mma16816(sc[2 * np], qfh[kc], bh0[np]);
                mma16816(sc[2 * np + 1], qfh[kc], bh1[np]);
            }
#pragma unroll
            for (int np = 0; np < 4; np++) {
                mma16816(sc[2 * np], qfh[kc], bl0[np]);
                mma16816(sc[2 * np + 1], qfh[kc], bl1[np]);
            }
#pragma unroll
            for (int np = 0; np < 4; np++) {
                mma16816(sc[2 * np], qfl[kc], bh0[np]);
                mma16816(sc[2 * np + 1], qfl[kc], bh1[np]);
            }
        }

        __syncthreads();
        if (t < qb) {
            load_K(t + 1);
            CP_COMMIT();
        }

        if (t == qb) {
            const int row0 = q0 + wrow + (lane >> 2);
            const int colb = t * 64 + 2 * (lane & 3);
#pragma unroll
            for (int nf = 0; nf < 8; nf++) {
                const int cb = colb + 8 * nf;
                if (cb > row0) sc[nf][0] = -1e30f;
                if (cb + 1 > row0) sc[nf][1] = -1e30f;
                if (cb > row0 + 8) sc[nf][2] = -1e30f;
                if (cb + 1 > row0 + 8) sc[nf][3] = -1e30f;
            }
        }

        float rmax0 = -1e30f, rmax1 = -1e30f;
#pragma unroll
        for (int nf = 0; nf < 8; nf++) {
            rmax0 = fmaxf(rmax0, fmaxf(sc[nf][0], sc[nf][1]));
            rmax1 = fmaxf(rmax1, fmaxf(sc[nf][2], sc[nf][3]));
        }
        rmax0 = fmaxf(rmax0, __shfl_xor_sync(0xffffffffu, rmax0, 1));
        rmax0 = fmaxf(rmax0, __shfl_xor_sync(0xffffffffu, rmax0, 2));
        rmax1 = fmaxf(rmax1, __shfl_xor_sync(0xffffffffu, rmax1, 1));
        rmax1 = fmaxf(rmax1, __shfl_xor_sync(0xffffffffu, rmax1, 2));
        const float mn0 = fmaxf(m0, rmax0);
        const float mn1 = fmaxf(m1, rmax1);
        const float scl0 = __expf(m0 - mn0);
        const float scl1 = __expf(m1 - mn1);
        float rs0 = 0.0f, rs1 = 0.0f;
#pragma unroll
        for (int nf = 0; nf < 8; nf++) {
            sc[nf][0] = __expf(sc[nf][0] - mn0); rs0 += sc[nf][0];
            sc[nf][1] = __expf(sc[nf][1] - mn0); rs0 += sc[nf][1];
            sc[nf][2] = __expf(sc[nf][2] - mn1); rs1 += sc[nf][2];
            sc[nf][3] = __expf(sc[nf][3] - mn1); rs1 += sc[nf][3];
        }
        rs0 += __shfl_xor_sync(0xffffffffu, rs0, 1);
        rs0 += __shfl_xor_sync(0xffffffffu, rs0, 2);
        rs1 += __shfl_xor_sync(0xffffffffu, rs1, 1);
        rs1 += __shfl_xor_sync(0xffffffffu, rs1, 2);
        l0 = l0 * scl0 + rs0;
        l1 = l1 * scl1 + rs1;
        m0 = mn0;
        m1 = mn1;
#pragma unroll
        for (int f = 0; f < 16; f++) {
            of[f][0] *= scl0; of[f][1] *= scl0;
            of[f][2] *= scl1; of[f][3] *= scl1;
        }

        if (t < qb) CP_WAIT1(); else CP_WAIT0();
        __syncthreads();

#pragma unroll
        for (int kb = 0; kb < 4; kb++) {
            uint32_t ph[4], pl[4];
            split_pack2(sc[2 * kb][0], sc[2 * kb][1], ph[0], pl[0]);
            split_pack2(sc[2 * kb][2], sc[2 * kb][3], ph[1], pl[1]);
            split_pack2(sc[2 * kb + 1][0], sc[2 * kb + 1][1], ph[2], pl[2]);
            split_pack2(sc[2 * kb + 1][2], sc[2 * kb + 1][3], ph[3], pl[3]);
            const uint32_t vbase = sb + AV_HI + (kb * 16 + lr) * 272 + lc16;
#pragma unroll
            for (int npp = 0; npp < 4; npp++) {
                const int np0 = 2 * npp, np1 = 2 * npp + 1;
                uint32_t vhA[4], vlA[4], vhB[4], vlB[4];
                ldsm4t(vhA, vbase + np0 * 32);
                ldsm4t(vlA, vbase + np0 * 32 + (AV_LO - AV_HI));
                ldsm4t(vhB, vbase + np1 * 32);
                ldsm4t(vlB, vbase + np1 * 32 + (AV_LO - AV_HI));
                uint32_t h0A[2] = {vhA[0], vhA[1]}, h1A[2] = {vhA[2], vhA[3]};
                uint32_t l0A[2] = {vlA[0], vlA[1]}, l1A[2] = {vlA[2], vlA[3]};
                uint32_t h0B[2] = {vhB[0], vhB[1]}, h1B[2] = {vhB[2], vhB[3]};
                uint32_t l0B[2] = {vlB[0], vlB[1]}, l1B[2] = {vlB[2], vlB[3]};
                mma16816(of[2 * np0], ph, h0A);
                mma16816(of[2 * np0 + 1], ph, h1A);
                mma16816(of[2 * np1], ph, h0B);
                mma16816(of[2 * np1 + 1], ph, h1B);
                mma16816(of[2 * np0], ph, l0A);
                mma16816(of[2 * np0 + 1], ph, l1A);
                mma16816(of[2 * np1], ph, l0B);
                mma16816(of[2 * np1 + 1], ph, l1B);
                mma16816(of[2 * np0], pl, h0A);
                mma16816(of[2 * np0 + 1], pl, h1A);
                mma16816(of[2 * np1], pl, h0B);
                mma16816(of[2 * np1 + 1], pl, h1B);
            }
        }

        __syncthreads();
        if (t < qb) {
            load_V(t + 1);
            CP_COMMIT();
        }
    }

    // epilogue: O /= l, write single fp16 head-major
    const float inv0 = 1.0f / l0;
    const float inv1 = 1.0f / l1;
    const int r0g = q0 + wrow + (lane >> 2);
    const int colb = 2 * (lane & 3);
#pragma unroll
    for (int nf = 0; nf < 16; nf++) {
        const int col = h * DHEAD + 8 * nf + colb;
        __half2 a = {__float2half_rn(of[nf][0] * inv0), __float2half_rn(of[nf][1] * inv0)};
        __half2 bvals = {__float2half_rn(of[nf][2] * inv1), __float2half_rn(of[nf][3] * inv1)};
        *(__half2*)(g_at + (size_t)(b * NS + r0g) * NHID + col) = a;
        *(__half2*)(g_at + (size_t)(b * NS + r0g + 8) * NHID + col) = bvals;
    }
}

// ------------------------- launch ------------------------------------------
extern "C" void kernel_launch(void* const* d_in, const int* in_sizes, int n_in,
                              void* d_out, int out_size) {
    const float* hidden = (const float*)d_in[0];
    const void* pos = d_in[1];
    const float* Wqkv = (const float*)d_in[2];
    const float* Wout = (const float*)d_in[3];
    float* out = (float*)d_out;

    void *p_qkv, *p_hid, *p_w1h, *p_w1l, *p_w2h, *p_w2l, *p_at;
    cudaGetSymbolAddress(&p_qkv, g_qkv);
    cudaGetSymbolAddress(&p_hid, g_hid);
    cudaGetSymbolAddress(&p_w1h, g_w1_hi);
    cudaGetSymbolAddress(&p_w1l, g_w1_lo);
    cudaGetSymbolAddress(&p_w2h, g_w2_hi);
    cudaGetSymbolAddress(&p_w2l, g_w2_lo);
    cudaGetSymbolAddress(&p_at, g_at);

    const int nHid = NB * NS * NHID;
    const int nW1 = NQKV * NHID;
    const int nW2 = NHID * NHID;

    conv_half<<<(nHid / 4 + 255) / 256, 256>>>(hidden, (__half*)p_hid, nHid / 4);
    split_half<<<(nW1 / 4 + 255) / 256, 256>>>(Wqkv, (__half*)p_w1h, (__half*)p_w1l, nW1 / 4);
    split_half<<<(nW2 / 4 + 255) / 256, 256>>>(Wout, (__half*)p_w2h, (__half*)p_w2l, nW2 / 4);

    // 1) QKV projection + clamp (2-pass fp16)
    {
        cudaFuncSetAttribute(gemm_2p<1>, cudaFuncAttributeMaxDynamicSharedMemorySize, GSMEM);
        dim3 grid(NQKV / 64, (NB * NS) / 128);
        gemm_2p<1><<<grid, 256, GSMEM>>>(
            (const __half*)p_hid, (const __half*)p_w1h, (const __half*)p_w1l,
            (float*)p_qkv, NB * NS, NQKV, NHID);
    }
    // 2) RoPE + scatter (emits fp16 hi/lo Q, K, V)
    rope_scatter<<<NB * NS, 128>>>(pos);

    // 3) tensor-core causal flash attention (fp16 3-pass)
    {
        cudaFuncSetAttribute(flash_attn_tc, cudaFuncAttributeMaxDynamicSharedMemorySize, ATTN_SMEM);
        dim3 grid(NS / 64, NHEADS, NB);
        flash_attn_tc<<<grid, 128, ATTN_SMEM>>>();
    }
    // 4) output projection (2-pass fp16)
    {
        cudaFuncSetAttribute(gemm_2p<0>, cudaFuncAttributeMaxDynamicSharedMemorySize, GSMEM);
        dim3 grid(NHID / 64, (NB * NS) / 128);
        gemm_2p<0><<<grid, 256, GSMEM>>>(
            (const __half*)p_at, (const __half*)p_w2h, (const __half*)p_w2l,
            out, NB * NS, NHID, NHID);
    }
}

// round 12
// speedup vs baseline: 1.4589x; 1.0794x over previous
#include <cuda_runtime.h>
#include <cuda_fp16.h>
#include <cstdint>
#include <math.h>

#define NB 2
#define NS 2048
#define NHID 2048
#define NHEADS 16
#define NKVH 4
#define DHEAD 128
#define NQKV 3072

// ------------------------- scratch (static device globals; no allocs) ------
static __device__ float g_qkv[(size_t)NB * NS * NQKV];

static __device__ __half g_q[(size_t)NB * NHEADS * NS * DHEAD];   // single fp16
static __device__ __half g_kh[(size_t)NB * NKVH * NS * DHEAD];
static __device__ __half g_kl[(size_t)NB * NKVH * NS * DHEAD];
static __device__ __half g_vh[(size_t)NB * NKVH * NS * DHEAD];
static __device__ __half g_vl[(size_t)NB * NKVH * NS * DHEAD];

static __device__ __half g_hid[(size_t)NB * NS * NHID];
static __device__ __half g_w1_hi[(size_t)NQKV * NHID];
static __device__ __half g_w1_lo[(size_t)NQKV * NHID];
static __device__ __half g_w2_hi[(size_t)NHID * NHID];
static __device__ __half g_w2_lo[(size_t)NHID * NHID];
static __device__ __half g_at[(size_t)NB * NS * NHID];

// ------------------------- PTX helpers (baseline ISA only) -----------------
__device__ __forceinline__ uint32_t smem_u32(const void* p) {
    uint32_t a;
    asm("{ .reg .u64 t; cvta.to.shared.u64 t, %1; cvt.u32.u64 %0, t; }"
        : "=r"(a) : "l"(p));
    return a;
}

__device__ __forceinline__ void cp16(uint32_t dst, const void* src) {
    asm volatile("cp.async.cg.shared.global [%0], [%1], 16;"
                 :: "r"(dst), "l"(src));
}
#define CP_COMMIT() asm volatile("cp.async.commit_group;" ::: "memory")
#define CP_WAIT0() asm volatile("cp.async.wait_group 0;" ::: "memory")
#define CP_WAIT1() asm volatile("cp.async.wait_group 1;" ::: "memory")
#define CP_WAIT2() asm volatile("cp.async.wait_group 2;" ::: "memory")

__device__ __forceinline__ void ldsm4(uint32_t* r, uint32_t addr) {
    asm volatile("ldmatrix.sync.aligned.m8n8.x4.shared.b16 {%0,%1,%2,%3}, [%4];"
                 : "=r"(r[0]), "=r"(r[1]), "=r"(r[2]), "=r"(r[3]) : "r"(addr));
}

__device__ __forceinline__ void ldsm4t(uint32_t* r, uint32_t addr) {
    asm volatile("ldmatrix.sync.aligned.m8n8.x4.trans.shared.b16 {%0,%1,%2,%3}, [%4];"
                 : "=r"(r[0]), "=r"(r[1]), "=r"(r[2]), "=r"(r[3]) : "r"(addr));
}

__device__ __forceinline__ void mma16816(float* c, const uint32_t* a, const uint32_t* b) {
    asm volatile(
        "mma.sync.aligned.m16n8k16.row.col.f32.f16.f16.f32 "
        "{%0,%1,%2,%3}, {%4,%5,%6,%7}, {%8,%9}, {%0,%1,%2,%3};"
        : "+f"(c[0]), "+f"(c[1]), "+f"(c[2]), "+f"(c[3])
        : "r"(a[0]), "r"(a[1]), "r"(a[2]), "r"(a[3]), "r"(b[0]), "r"(b[1]));
}

__device__ __forceinline__ void hsplit(float x, __half& h, __half& l) {
    h = __float2half_rn(x);
    l = __float2half_rn(x - __half2float(h));
}

__device__ __forceinline__ uint32_t pack2(float a, float b) {
    __half2 p = {__float2half_rn(a), __float2half_rn(b)};
    return *(uint32_t*)&p;
}

#define SWZ128(x) ((x) ^ (((x) >> 3) & 0x70))
#define SWZ64(x) ((x) ^ (((x) >> 3) & 0x30))

// ------------------------- fp32 -> fp16 convert / split --------------------
__global__ void __launch_bounds__(256) conv_half(const float* __restrict__ x,
                                                 __half* __restrict__ o, int n4) {
    int i = blockIdx.x * 256 + threadIdx.x;
    if (i >= n4) return;
    float4 v = ((const float4*)x)[i];
    __half2 a = {__float2half_rn(v.x), __float2half_rn(v.y)};
    __half2 b = {__float2half_rn(v.z), __float2half_rn(v.w)};
    ((__half2*)o)[2 * i] = a;
    ((__half2*)o)[2 * i + 1] = b;
}

__global__ void __launch_bounds__(256) split_half(const float* __restrict__ x,
                                                  __half* __restrict__ hi,
                                                  __half* __restrict__ lo, int n4) {
    int i = blockIdx.x * 256 + threadIdx.x;
    if (i >= n4) return;
    float4 v = ((const float4*)x)[i];
    __half h0, l0, h1, l1, h2, l2, h3, l3;
    hsplit(v.x, h0, l0); hsplit(v.y, h1, l1);
    hsplit(v.z, h2, l2); hsplit(v.w, h3, l3);
    __half2 hh0 = {h0, h1}, hh1 = {h2, h3};
    __half2 ll0 = {l0, l1}, ll1 = {l2, l3};
    ((__half2*)hi)[2 * i] = hh0;
    ((__half2*)hi)[2 * i + 1] = hh1;
    ((__half2*)lo)[2 * i] = ll0;
    ((__half2*)lo)[2 * i + 1] = ll1;
}

// ------------------------- 2-pass HMMA GEMM: C = A * B^T -------------------
#define GST 16384
#define GSMEM (2 * GST)

template <int CLAMP>
__global__ void __launch_bounds__(256, 3) gemm_2p(const __half* __restrict__ A,
                                                  const __half* __restrict__ Bhi,
                                                  const __half* __restrict__ Blo,
                                                  float* __restrict__ C,
                                                  int M, int N, int K) {
    extern __shared__ char smem[];
    const uint32_t sb = smem_u32(smem);
    const int tid = threadIdx.x;
    const int lane = tid & 31;
    const int wid = tid >> 5;
    const int wm = (wid & 3) * 32;
    const int wn = (wid >> 2) * 32;
    const int bx = blockIdx.x;
    const int by = blockIdx.y;

    auto load_stage = [&](int st, int kt) {
        const uint32_t s = sb + st * GST;
        const int kc = kt * 32;
#pragma unroll
        for (int i = 0; i < 2; i++) {
            const int q = tid + i * 256;
            const int r = q >> 2, c = q & 3;
            cp16(s + SWZ64(r * 64 + c * 16), A + (size_t)(by * 128 + r) * K + kc + c * 8);
        }
#pragma unroll
        for (int i = 0; i < 2; i++) {
            const int q = tid + i * 256;
            const int r = q >> 3, c = q & 7;
            const __half* srcB =
                (c < 4 ? Bhi : Blo) + (size_t)(bx * 64 + r) * K + kc + (c & 3) * 8;
            cp16(s + 8192 + SWZ128(r * 128 + c * 16), srcB);
        }
    };

    float acc[2][4][4];
#pragma unroll
    for (int i = 0; i < 2; i++)
#pragma unroll
        for (int j = 0; j < 4; j++)
#pragma unroll
            for (int e = 0; e < 4; e++) acc[i][j][e] = 0.0f;

    const int KT = K >> 5;
    load_stage(0, 0);
    CP_COMMIT();

    const int lr = (lane & 7) + ((lane >> 3) & 1) * 8;
    const int lc = lane >> 4;

    for (int kt = 0; kt < KT; kt++) {
        CP_WAIT0();
        __syncthreads();
        if (kt + 1 < KT) {
            load_stage((kt + 1) & 1, kt + 1);
            CP_COMMIT();
        }
        const uint32_t s = sb + (kt & 1) * GST;
#pragma unroll
        for (int ks = 0; ks < 2; ks++) {
            const int ch = 2 * ks + lc;
            uint32_t bh[4][2], bl[4][2];
#pragma unroll
            for (int nf2 = 0; nf2 < 2; nf2++) {
                const uint32_t rb = (wn + nf2 * 16 + lr) * 128;
                uint32_t th[4], tl[4];
                ldsm4(th, s + 8192 + SWZ128(rb + ch * 16));
                ldsm4(tl, s + 8192 + SWZ128(rb + (ch + 4) * 16));
                bh[nf2 * 2][0] = th[0]; bh[nf2 * 2 + 1][0] = th[1];
                bh[nf2 * 2][1] = th[2]; bh[nf2 * 2 + 1][1] = th[3];
                bl[nf2 * 2][0] = tl[0]; bl[nf2 * 2 + 1][0] = tl[1];
                bl[nf2 * 2][1] = tl[2]; bl[nf2 * 2 + 1][1] = tl[3];
            }
#pragma unroll
            for (int mf = 0; mf < 2; mf++) {
                uint32_t ah[4];
                ldsm4(ah, s + SWZ64((wm + mf * 16 + lr) * 64 + ch * 16));
#pragma unroll
                for (int nf = 0; nf < 4; nf++) mma16816(acc[mf][nf], ah, bh[nf]);
#pragma unroll
                for (int nf = 0; nf < 4; nf++) mma16816(acc[mf][nf], ah, bl[nf]);
            }
        }
    }

    const int erow = lane >> 2;
    const int ecol = (lane & 3) * 2;
#pragma unroll
    for (int mf = 0; mf < 2; mf++) {
#pragma unroll
        for (int nf = 0; nf < 4; nf++) {
            float* c = acc[mf][nf];
            if (CLAMP) {
#pragma unroll
                for (int e = 0; e < 4; e++)
                    c[e] = fminf(8.0f, fmaxf(-8.0f, c[e]));
            }
            const int row = by * 128 + wm + mf * 16 + erow;
            const int col = bx * 64 + wn + nf * 8 + ecol;
            float2 v0 = {c[0], c[1]};
            float2 v1 = {c[2], c[3]};
            *(float2*)(C + (size_t)row * N + col) = v0;
            *(float2*)(C + (size_t)(row + 8) * N + col) = v1;
        }
    }
}

// ------------------------- RoPE + scatter ----------------------------------
__global__ void __launch_bounds__(128) rope_scatter(const void* __restrict__ pos_ids) {
    const int bs = blockIdx.x;
    const int b = bs / NS;
    const int s = bs % NS;
    const int d = threadIdx.x;
    const int dm = d & 63;

    const int* p32 = (const int*)pos_ids;
    const bool is64 = (p32[1] == 0) && (p32[3] == 0) && (p32[2 * NS + 1] == 0);
    const long long pv = is64 ? ((const long long*)pos_ids)[bs] : (long long)p32[bs];

    const double p = (double)pv;
    const double C_LN = 0.20503692777194264;  // ln(500000)/64
    const double invf = exp(-(double)dm * C_LN);
    double sd, cd;
    sincos(p * invf, &sd, &cd);
    const float c = (float)cd;
    const float sn = (float)sd;
    const float sign = (d < 64) ? -1.0f : 1.0f;
    const float qscale = 0.08838834764831845f;

    const float* row = g_qkv + (size_t)bs * NQKV;

#pragma unroll
    for (int h = 0; h < NHEADS; h++) {
        float v = row[h * DHEAD + d];
        float pr = row[h * DHEAD + (d ^ 64)];
        float qv = (v * c + sign * pr * sn) * qscale;
        size_t idx = (((size_t)b * NHEADS + h) * NS + s) * DHEAD + d;
        g_q[idx] = __float2half_rn(qv);     // single fp16 Q
    }
#pragma unroll
    for (int h = 0; h < NKVH; h++) {
        float v = row[NHID + h * DHEAD + d];
        float pr = row[NHID + h * DHEAD + (d ^ 64)];
        float kv = v * c + sign * pr * sn;
        __half hh, ll;
        hsplit(kv, hh, ll);
        size_t idx = (((size_t)b * NKVH + h) * NS + s) * DHEAD + d;
        g_kh[idx] = hh;
        g_kl[idx] = ll;
        float vv = row[NHID + NKVH * DHEAD + h * DHEAD + d];
        hsplit(vv, hh, ll);
        g_vh[idx] = hh;
        g_vl[idx] = ll;
    }
}

// ------------------------- tensor-core flash attention ---------------------
// BM=64, BN=64, 4 warps. 2-pass: Q single fp16 x K hi/lo; P single x V hi/lo.
#define AQ 0
#define AK_HI 17408
#define AK_LO 34816
#define AV_HI 52224
#define AV_LO 69632
#define ATTN_SMEM 87040

__global__ void __launch_bounds__(128) flash_attn_tc() {
    extern __shared__ char smem[];
    const uint32_t sb = smem_u32(smem);
    const int tid = threadIdx.x;
    const int lane = tid & 31;
    const int w = tid >> 5;
    const int qb = gridDim.x - 1 - blockIdx.x;
    const int h = blockIdx.y;
    const int b = blockIdx.z;
    const int hk = h >> 2;
    const int q0 = qb * 64;
    const int wrow = w * 16;

    const __half* Qg = g_q + ((size_t)(b * NHEADS + h) * NS + q0) * DHEAD;
    const __half* Kh = g_kh + ((size_t)(b * NKVH + hk) * NS) * DHEAD;
    const __half* Kl = g_kl + ((size_t)(b * NKVH + hk) * NS) * DHEAD;
    const __half* Vh = g_vh + ((size_t)(b * NKVH + hk) * NS) * DHEAD;
    const __half* Vl = g_vl + ((size_t)(b * NKVH + hk) * NS) * DHEAD;

    auto load_K = [&](int t) {
#pragma unroll
        for (int i = 0; i < 8; i++) {
            int q = tid + i * 128;
            int r = q >> 4, cc = q & 15;
            cp16(sb + AK_HI + r * 272 + cc * 16, Kh + (size_t)(t * 64 + r) * DHEAD + cc * 8);
            cp16(sb + AK_LO + r * 272 + cc * 16, Kl + (size_t)(t * 64 + r) * DHEAD + cc * 8);
        }
    };
    auto load_V = [&](int t) {
#pragma unroll
        for (int i = 0; i < 8; i++) {
            int q = tid + i * 128;
            int r = q >> 4, cc = q & 15;
            cp16(sb + AV_HI + r * 272 + cc * 16, Vh + (size_t)(t * 64 + r) * DHEAD + cc * 8);
            cp16(sb + AV_LO + r * 272 + cc * 16, Vl + (size_t)(t * 64 + r) * DHEAD + cc * 8);
        }
    };

    // Q: 64 rows x 16 chunks = 1024 tasks over 128 threads = 8 iters
#pragma unroll
    for (int i = 0; i < 8; i++) {
        int q = tid + i * 128;
        int r = q >> 4, cc = q & 15;
        cp16(sb + AQ + r * 272 + cc * 16, Qg + (size_t)r * DHEAD + cc * 8);
    }
    CP_COMMIT();
    load_K(0);
    CP_COMMIT();
    load_V(0);
    CP_COMMIT();

    const int lr = (lane & 7) + ((lane >> 3) & 1) * 8;
    const int lc16 = (lane >> 4) * 16;

    CP_WAIT2();
    __syncthreads();
    uint32_t qf[8][4];
#pragma unroll
    for (int kc = 0; kc < 8; kc++)
        ldsm4(qf[kc], sb + AQ + (wrow + lr) * 272 + kc * 32 + lc16);

    float of[16][4];
#pragma unroll
    for (int f = 0; f < 16; f++)
#pragma unroll
        for (int e = 0; e < 4; e++) of[f][e] = 0.0f;
    float m0 = -1e30f, m1 = -1e30f, l0 = 0.0f, l1 = 0.0f;

    for (int t = 0; t <= qb; t++) {
        CP_WAIT1();
        __syncthreads();

        float sc[8][4];
#pragma unroll
        for (int nf = 0; nf < 8; nf++)
#pragma unroll
            for (int e = 0; e < 4; e++) sc[nf][e] = 0.0f;

#pragma unroll
        for (int kc = 0; kc < 8; kc++) {
            uint32_t bh0[4][2], bh1[4][2], bl0[4][2], bl1[4][2];
#pragma unroll
            for (int np = 0; np < 4; np++) {
                uint32_t kh4[4], kl4[4];
                const uint32_t kaddr = sb + AK_HI + (np * 16 + lr) * 272 + kc * 32 + lc16;
                ldsm4(kh4, kaddr);
                ldsm4(kl4, kaddr + (AK_LO - AK_HI));
                bh0[np][0] = kh4[0]; bh0[np][1] = kh4[2];
                bh1[np][0] = kh4[1]; bh1[np][1] = kh4[3];
                bl0[np][0] = kl4[0]; bl0[np][1] = kl4[2];
                bl1[np][0] = kl4[1]; bl1[np][1] = kl4[3];
            }
#pragma unroll
            for (int np = 0; np < 4; np++) {
                mma16816(sc[2 * np], qf[kc], bh0[np]);
                mma16816(sc[2 * np + 1], qf[kc], bh1[np]);
            }
#pragma unroll
            for (int np = 0; np < 4; np++) {
                mma16816(sc[2 * np], qf[kc], bl0[np]);
                mma16816(sc[2 * np + 1], qf[kc], bl1[np]);
            }
        }

        __syncthreads();
        if (t < qb) {
            load_K(t + 1);
            CP_COMMIT();
        }

        if (t == qb) {
            const int row0 = q0 + wrow + (lane >> 2);
            const int colb = t * 64 + 2 * (lane & 3);
#pragma unroll
            for (int nf = 0; nf < 8; nf++) {
                const int cb = colb + 8 * nf;
                if (cb > row0) sc[nf][0] = -1e30f;
                if (cb + 1 > row0) sc[nf][1] = -1e30f;
                if (cb > row0 + 8) sc[nf][2] = -1e30f;
                if (cb + 1 > row0 + 8) sc[nf][3] = -1e30f;
            }
        }

        float rmax0 = -1e30f, rmax1 = -1e30f;
#pragma unroll
        for (int nf = 0; nf < 8; nf++) {
            rmax0 = fmaxf(rmax0, fmaxf(sc[nf][0], sc[nf][1]));
            rmax1 = fmaxf(rmax1, fmaxf(sc[nf][2], sc[nf][3]));
        }
        rmax0 = fmaxf(rmax0, __shfl_xor_sync(0xffffffffu, rmax0, 1));
        rmax0 = fmaxf(rmax0, __shfl_xor_sync(0xffffffffu, rmax0, 2));
        rmax1 = fmaxf(rmax1, __shfl_xor_sync(0xffffffffu, rmax1, 1));
        rmax1 = fmaxf(rmax1, __shfl_xor_sync(0xffffffffu, rmax1, 2));
        const float mn0 = fmaxf(m0, rmax0);
        const float mn1 = fmaxf(m1, rmax1);
        const float scl0 = __expf(m0 - mn0);
        const float scl1 = __expf(m1 - mn1);
        float rs0 = 0.0f, rs1 = 0.0f;
#pragma unroll
        for (int nf = 0; nf < 8; nf++) {
            sc[nf][0] = __expf(sc[nf][0] - mn0); rs0 += sc[nf][0];
            sc[nf][1] = __expf(sc[nf][1] - mn0); rs0 += sc[nf][1];
            sc[nf][2] = __expf(sc[nf][2] - mn1); rs1 += sc[nf][2];
            sc[nf][3] = __expf(sc[nf][3] - mn1); rs1 += sc[nf][3];
        }
        rs0 += __shfl_xor_sync(0xffffffffu, rs0, 1);
        rs0 += __shfl_xor_sync(0xffffffffu, rs0, 2);
        rs1 += __shfl_xor_sync(0xffffffffu, rs1, 1);
        rs1 += __shfl_xor_sync(0xffffffffu, rs1, 2);
        l0 = l0 * scl0 + rs0;
        l1 = l1 * scl1 + rs1;
        m0 = mn0;
        m1 = mn1;
#pragma unroll
        for (int f = 0; f < 16; f++) {
            of[f][0] *= scl0; of[f][1] *= scl0;
            of[f][2] *= scl1; of[f][3] *= scl1;
        }

        if (t < qb) CP_WAIT1(); else CP_WAIT0();
        __syncthreads();

        // O += P V : P single fp16 (packed), V hi/lo via ldsm.trans
#pragma unroll
        for (int kb = 0; kb < 4; kb++) {
            uint32_t ph[4];
            ph[0] = pack2(sc[2 * kb][0], sc[2 * kb][1]);
            ph[1] = pack2(sc[2 * kb][2], sc[2 * kb][3]);
            ph[2] = pack2(sc[2 * kb + 1][0], sc[2 * kb + 1][1]);
            ph[3] = pack2(sc[2 * kb + 1][2], sc[2 * kb + 1][3]);
            const uint32_t vbase = sb + AV_HI + (kb * 16 + lr) * 272 + lc16;
#pragma unroll
            for (int npp = 0; npp < 4; npp++) {
                const int np0 = 2 * npp, np1 = 2 * npp + 1;
                uint32_t vhA[4], vlA[4], vhB[4], vlB[4];
                ldsm4t(vhA, vbase + np0 * 32);
                ldsm4t(vlA, vbase + np0 * 32 + (AV_LO - AV_HI));
                ldsm4t(vhB, vbase + np1 * 32);
                ldsm4t(vlB, vbase + np1 * 32 + (AV_LO - AV_HI));
                uint32_t h0A[2] = {vhA[0], vhA[1]}, h1A[2] = {vhA[2], vhA[3]};
                uint32_t l0A[2] = {vlA[0], vlA[1]}, l1A[2] = {vlA[2], vlA[3]};
                uint32_t h0B[2] = {vhB[0], vhB[1]}, h1B[2] = {vhB[2], vhB[3]};
                uint32_t l0B[2] = {vlB[0], vlB[1]}, l1B[2] = {vlB[2], vlB[3]};
                mma16816(of[2 * np0], ph, h0A);
                mma16816(of[2 * np0 + 1], ph, h1A);
                mma16816(of[2 * np1], ph, h0B);
                mma16816(of[2 * np1 + 1], ph, h1B);
                mma16816(of[2 * np0], ph, l0A);
                mma16816(of[2 * np0 + 1], ph, l1A);
                mma16816(of[2 * np1], ph, l0B);
                mma16816(of[2 * np1 + 1], ph, l1B);
            }
        }

        __syncthreads();
        if (t < qb) {
            load_V(t + 1);
            CP_COMMIT();
        }
    }

    const float inv0 = 1.0f / l0;
    const float inv1 = 1.0f / l1;
    const int r0g = q0 + wrow + (lane >> 2);
    const int colb = 2 * (lane & 3);
#pragma unroll
    for (int nf = 0; nf < 16; nf++) {
        const int col = h * DHEAD + 8 * nf + colb;
        __half2 a = {__float2half_rn(of[nf][0] * inv0), __float2half_rn(of[nf][1] * inv0)};
        __half2 bvals = {__float2half_rn(of[nf][2] * inv1), __float2half_rn(of[nf][3] * inv1)};
        *(__half2*)(g_at + (size_t)(b * NS + r0g) * NHID + col) = a;
        *(__half2*)(g_at + (size_t)(b * NS + r0g + 8) * NHID + col) = bvals;
    }
}

// ------------------------- launch ------------------------------------------
extern "C" void kernel_launch(void* const* d_in, const int* in_sizes, int n_in,
                              void* d_out, int out_size) {
    const float* hidden = (const float*)d_in[0];
    const void* pos = d_in[1];
    const float* Wqkv = (const float*)d_in[2];
    const float* Wout = (const float*)d_in[3];
    float* out = (float*)d_out;

    void *p_qkv, *p_hid, *p_w1h, *p_w1l, *p_w2h, *p_w2l, *p_at;
    cudaGetSymbolAddress(&p_qkv, g_qkv);
    cudaGetSymbolAddress(&p_hid, g_hid);
    cudaGetSymbolAddress(&p_w1h, g_w1_hi);
    cudaGetSymbolAddress(&p_w1l, g_w1_lo);
    cudaGetSymbolAddress(&p_w2h, g_w2_hi);
    cudaGetSymbolAddress(&p_w2l, g_w2_lo);
    cudaGetSymbolAddress(&p_at, g_at);

    const int nHid = NB * NS * NHID;
    const int nW1 = NQKV * NHID;
    const int nW2 = NHID * NHID;

    conv_half<<<(nHid / 4 + 255) / 256, 256>>>(hidden, (__half*)p_hid, nHid / 4);
    split_half<<<(nW1 / 4 + 255) / 256, 256>>>(Wqkv, (__half*)p_w1h, (__half*)p_w1l, nW1 / 4);
    split_half<<<(nW2 / 4 + 255) / 256, 256>>>(Wout, (__half*)p_w2h, (__half*)p_w2l, nW2 / 4);

    // 1) QKV projection + clamp (2-pass fp16)
    {
        cudaFuncSetAttribute(gemm_2p<1>, cudaFuncAttributeMaxDynamicSharedMemorySize, GSMEM);
        dim3 grid(NQKV / 64, (NB * NS) / 128);
        gemm_2p<1><<<grid, 256, GSMEM>>>(
            (const __half*)p_hid, (const __half*)p_w1h, (const __half*)p_w1l,
            (float*)p_qkv, NB * NS, NQKV, NHID);
    }
    // 2) RoPE + scatter
    rope_scatter<<<NB * NS, 128>>>(pos);

    // 3) tensor-core causal flash attention (2-pass)
    {
        cudaFuncSetAttribute(flash_attn_tc, cudaFuncAttributeMaxDynamicSharedMemorySize, ATTN_SMEM);
        dim3 grid(NS / 64, NHEADS, NB);
        flash_attn_tc<<<grid, 128, ATTN_SMEM>>>();
    }
    // 4) output projection (2-pass fp16)
    {
        cudaFuncSetAttribute(gemm_2p<0>, cudaFuncAttributeMaxDynamicSharedMemorySize, GSMEM);
        dim3 grid(NHID / 64, (NB * NS) / 128);
        gemm_2p<0><<<grid, 256, GSMEM>>>(
            (const __half*)p_at, (const __half*)p_w2h, (const __half*)p_w2l,
            out, NB * NS, NHID, NHID);
    }
}

// round 13
// speedup vs baseline: 1.9350x; 1.3264x over previous
#include <cuda_runtime.h>
#include <cuda_fp16.h>
#include <cstdint>
#include <math.h>

#define NB 2
#define NS 2048
#define NHID 2048
#define NHEADS 16
#define NKVH 4
#define DHEAD 128
#define NQKV 3072

// ------------------------- scratch (static device globals; no allocs) ------
static __device__ float g_qkv[(size_t)NB * NS * NQKV];

static __device__ __half g_q[(size_t)NB * NHEADS * NS * DHEAD];   // single fp16
static __device__ __half g_kh[(size_t)NB * NKVH * NS * DHEAD];
static __device__ __half g_kl[(size_t)NB * NKVH * NS * DHEAD];
static __device__ __half g_vh[(size_t)NB * NKVH * NS * DHEAD];
static __device__ __half g_vl[(size_t)NB * NKVH * NS * DHEAD];

static __device__ __half g_hid[(size_t)NB * NS * NHID];
static __device__ __half g_w1[(size_t)NQKV * NHID];               // single fp16
static __device__ __half g_w2[(size_t)NHID * NHID];               // single fp16
static __device__ __half g_at[(size_t)NB * NS * NHID];

// ------------------------- PTX helpers (baseline ISA only) -----------------
__device__ __forceinline__ uint32_t smem_u32(const void* p) {
    uint32_t a;
    asm("{ .reg .u64 t; cvta.to.shared.u64 t, %1; cvt.u32.u64 %0, t; }"
        : "=r"(a) : "l"(p));
    return a;
}

__device__ __forceinline__ void cp16(uint32_t dst, const void* src) {
    asm volatile("cp.async.cg.shared.global [%0], [%1], 16;"
                 :: "r"(dst), "l"(src));
}
#define CP_COMMIT() asm volatile("cp.async.commit_group;" ::: "memory")
#define CP_WAIT0() asm volatile("cp.async.wait_group 0;" ::: "memory")
#define CP_WAIT1() asm volatile("cp.async.wait_group 1;" ::: "memory")
#define CP_WAIT2() asm volatile("cp.async.wait_group 2;" ::: "memory")

__device__ __forceinline__ void ldsm4(uint32_t* r, uint32_t addr) {
    asm volatile("ldmatrix.sync.aligned.m8n8.x4.shared.b16 {%0,%1,%2,%3}, [%4];"
                 : "=r"(r[0]), "=r"(r[1]), "=r"(r[2]), "=r"(r[3]) : "r"(addr));
}

__device__ __forceinline__ void ldsm4t(uint32_t* r, uint32_t addr) {
    asm volatile("ldmatrix.sync.aligned.m8n8.x4.trans.shared.b16 {%0,%1,%2,%3}, [%4];"
                 : "=r"(r[0]), "=r"(r[1]), "=r"(r[2]), "=r"(r[3]) : "r"(addr));
}

__device__ __forceinline__ void mma16816(float* c, const uint32_t* a, const uint32_t* b) {
    asm volatile(
        "mma.sync.aligned.m16n8k16.row.col.f32.f16.f16.f32 "
        "{%0,%1,%2,%3}, {%4,%5,%6,%7}, {%8,%9}, {%0,%1,%2,%3};"
        : "+f"(c[0]), "+f"(c[1]), "+f"(c[2]), "+f"(c[3])
        : "r"(a[0]), "r"(a[1]), "r"(a[2]), "r"(a[3]), "r"(b[0]), "r"(b[1]));
}

__device__ __forceinline__ void hsplit(float x, __half& h, __half& l) {
    h = __float2half_rn(x);
    l = __float2half_rn(x - __half2float(h));
}

__device__ __forceinline__ uint32_t pack2(float a, float b) {
    __half2 p = {__float2half_rn(a), __float2half_rn(b)};
    return *(uint32_t*)&p;
}

#define SWZ128(x) ((x) ^ (((x) >> 3) & 0x70))
#define SWZ64(x) ((x) ^ (((x) >> 3) & 0x30))

// ------------------------- fp32 -> fp16 convert / split --------------------
__global__ void __launch_bounds__(256) conv_half(const float* __restrict__ x,
                                                 __half* __restrict__ o, int n4) {
    int i = blockIdx.x * 256 + threadIdx.x;
    if (i >= n4) return;
    float4 v = ((const float4*)x)[i];
    __half2 a = {__float2half_rn(v.x), __float2half_rn(v.y)};
    __half2 b = {__float2half_rn(v.z), __float2half_rn(v.w)};
    ((__half2*)o)[2 * i] = a;
    ((__half2*)o)[2 * i + 1] = b;
}

// ------------------------- 1-pass HMMA GEMM: C = A * B^T -------------------
// A and B single fp16. CTA 128x64, 8 warps (32x32), BK=32.
// Tiles: 64B rows (SWZ64). Stage = A 8KB + B 4KB = 12KB; double buffered.
#define GST 12288
#define GSMEM (2 * GST)

template <int CLAMP>
__global__ void __launch_bounds__(256, 3) gemm_1p(const __half* __restrict__ A,
                                                  const __half* __restrict__ B,
                                                  float* __restrict__ C,
                                                  int M, int N, int K) {
    extern __shared__ char smem[];
    const uint32_t sb = smem_u32(smem);
    const int tid = threadIdx.x;
    const int lane = tid & 31;
    const int wid = tid >> 5;
    const int wm = (wid & 3) * 32;
    const int wn = (wid >> 2) * 32;
    const int bx = blockIdx.x;
    const int by = blockIdx.y;

    auto load_stage = [&](int st, int kt) {
        const uint32_t s = sb + st * GST;
        const int kc = kt * 32;
#pragma unroll
        for (int i = 0; i < 2; i++) {  // A: 128 rows x 4 chunks
            const int q = tid + i * 256;
            const int r = q >> 2, c = q & 3;
            cp16(s + SWZ64(r * 64 + c * 16), A + (size_t)(by * 128 + r) * K + kc + c * 8);
        }
        {                              // B: 64 rows x 4 chunks = 256 tasks
            const int r = tid >> 2, c = tid & 3;
            cp16(s + 8192 + SWZ64(r * 64 + c * 16), B + (size_t)(bx * 64 + r) * K + kc + c * 8);
        }
    };

    float acc[2][4][4];
#pragma unroll
    for (int i = 0; i < 2; i++)
#pragma unroll
        for (int j = 0; j < 4; j++)
#pragma unroll
            for (int e = 0; e < 4; e++) acc[i][j][e] = 0.0f;

    const int KT = K >> 5;
    load_stage(0, 0);
    CP_COMMIT();

    const int lr = (lane & 7) + ((lane >> 3) & 1) * 8;
    const int lc = lane >> 4;

    for (int kt = 0; kt < KT; kt++) {
        CP_WAIT0();
        __syncthreads();
        if (kt + 1 < KT) {
            load_stage((kt + 1) & 1, kt + 1);
            CP_COMMIT();
        }
        const uint32_t s = sb + (kt & 1) * GST;
#pragma unroll
        for (int ks = 0; ks < 2; ks++) {
            const int ch = 2 * ks + lc;  // 0..3
            uint32_t bf[4][2];
#pragma unroll
            for (int nf2 = 0; nf2 < 2; nf2++) {
                uint32_t tb[4];
                ldsm4(tb, s + 8192 + SWZ64((wn + nf2 * 16 + lr) * 64 + ch * 16));
                bf[nf2 * 2][0] = tb[0]; bf[nf2 * 2 + 1][0] = tb[1];
                bf[nf2 * 2][1] = tb[2]; bf[nf2 * 2 + 1][1] = tb[3];
            }
#pragma unroll
            for (int mf = 0; mf < 2; mf++) {
                uint32_t af[4];
                ldsm4(af, s + SWZ64((wm + mf * 16 + lr) * 64 + ch * 16));
#pragma unroll
                for (int nf = 0; nf < 4; nf++) mma16816(acc[mf][nf], af, bf[nf]);
            }
        }
    }

    const int erow = lane >> 2;
    const int ecol = (lane & 3) * 2;
#pragma unroll
    for (int mf = 0; mf < 2; mf++) {
#pragma unroll
        for (int nf = 0; nf < 4; nf++) {
            float* c = acc[mf][nf];
            if (CLAMP) {
#pragma unroll
                for (int e = 0; e < 4; e++)
                    c[e] = fminf(8.0f, fmaxf(-8.0f, c[e]));
            }
            const int row = by * 128 + wm + mf * 16 + erow;
            const int col = bx * 64 + wn + nf * 8 + ecol;
            float2 v0 = {c[0], c[1]};
            float2 v1 = {c[2], c[3]};
            *(float2*)(C + (size_t)row * N + col) = v0;
            *(float2*)(C + (size_t)(row + 8) * N + col) = v1;
        }
    }
}

// ------------------------- RoPE + scatter ----------------------------------
__global__ void __launch_bounds__(128) rope_scatter(const void* __restrict__ pos_ids) {
    const int bs = blockIdx.x;
    const int b = bs / NS;
    const int s = bs % NS;
    const int d = threadIdx.x;
    const int dm = d & 63;

    const int* p32 = (const int*)pos_ids;
    const bool is64 = (p32[1] == 0) && (p32[3] == 0) && (p32[2 * NS + 1] == 0);
    const long long pv = is64 ? ((const long long*)pos_ids)[bs] : (long long)p32[bs];

    const double p = (double)pv;
    const double C_LN = 0.20503692777194264;  // ln(500000)/64
    const double invf = exp(-(double)dm * C_LN);
    double sd, cd;
    sincos(p * invf, &sd, &cd);
    const float c = (float)cd;
    const float sn = (float)sd;
    const float sign = (d < 64) ? -1.0f : 1.0f;
    const float qscale = 0.08838834764831845f;

    const float* row = g_qkv + (size_t)bs * NQKV;

#pragma unroll
    for (int h = 0; h < NHEADS; h++) {
        float v = row[h * DHEAD + d];
        float pr = row[h * DHEAD + (d ^ 64)];
        float qv = (v * c + sign * pr * sn) * qscale;
        size_t idx = (((size_t)b * NHEADS + h) * NS + s) * DHEAD + d;
        g_q[idx] = __float2half_rn(qv);
    }
#pragma unroll
    for (int h = 0; h < NKVH; h++) {
        float v = row[NHID + h * DHEAD + d];
        float pr = row[NHID + h * DHEAD + (d ^ 64)];
        float kv = v * c + sign * pr * sn;
        __half hh, ll;
        hsplit(kv, hh, ll);
        size_t idx = (((size_t)b * NKVH + h) * NS + s) * DHEAD + d;
        g_kh[idx] = hh;
        g_kl[idx] = ll;
        float vv = row[NHID + NKVH * DHEAD + h * DHEAD + d];
        hsplit(vv, hh, ll);
        g_vh[idx] = hh;
        g_vl[idx] = ll;
    }
}

// ------------------------- tensor-core flash attention ---------------------
// BM=64, BN=64, 4 warps. 2-pass: Q single fp16 x K hi/lo; P single x V hi/lo.
#define AQ 0
#define AK_HI 17408
#define AK_LO 34816
#define AV_HI 52224
#define AV_LO 69632
#define ATTN_SMEM 87040

__global__ void __launch_bounds__(128) flash_attn_tc() {
    extern __shared__ char smem[];
    const uint32_t sb = smem_u32(smem);
    const int tid = threadIdx.x;
    const int lane = tid & 31;
    const int w = tid >> 5;
    const int qb = gridDim.x - 1 - blockIdx.x;
    const int h = blockIdx.y;
    const int b = blockIdx.z;
    const int hk = h >> 2;
    const int q0 = qb * 64;
    const int wrow = w * 16;

    const __half* Qg = g_q + ((size_t)(b * NHEADS + h) * NS + q0) * DHEAD;
    const __half* Kh = g_kh + ((size_t)(b * NKVH + hk) * NS) * DHEAD;
    const __half* Kl = g_kl + ((size_t)(b * NKVH + hk) * NS) * DHEAD;
    const __half* Vh = g_vh + ((size_t)(b * NKVH + hk) * NS) * DHEAD;
    const __half* Vl = g_vl + ((size_t)(b * NKVH + hk) * NS) * DHEAD;

    auto load_K = [&](int t) {
#pragma unroll
        for (int i = 0; i < 8; i++) {
            int q = tid + i * 128;
            int r = q >> 4, cc = q & 15;
            cp16(sb + AK_HI + r * 272 + cc * 16, Kh + (size_t)(t * 64 + r) * DHEAD + cc * 8);
            cp16(sb + AK_LO + r * 272 + cc * 16, Kl + (size_t)(t * 64 + r) * DHEAD + cc * 8);
        }
    };
    auto load_V = [&](int t) {
#pragma unroll
        for (int i = 0; i < 8; i++) {
            int q = tid + i * 128;
            int r = q >> 4, cc = q & 15;
            cp16(sb + AV_HI + r * 272 + cc * 16, Vh + (size_t)(t * 64 + r) * DHEAD + cc * 8);
            cp16(sb + AV_LO + r * 272 + cc * 16, Vl + (size_t)(t * 64 + r) * DHEAD + cc * 8);
        }
    };

#pragma unroll
    for (int i = 0; i < 8; i++) {
        int q = tid + i * 128;
        int r = q >> 4, cc = q & 15;
        cp16(sb + AQ + r * 272 + cc * 16, Qg + (size_t)r * DHEAD + cc * 8);
    }
    CP_COMMIT();
    load_K(0);
    CP_COMMIT();
    load_V(0);
    CP_COMMIT();

    const int lr = (lane & 7) + ((lane >> 3) & 1) * 8;
    const int lc16 = (lane >> 4) * 16;

    CP_WAIT2();
    __syncthreads();
    uint32_t qf[8][4];
#pragma unroll
    for (int kc = 0; kc < 8; kc++)
        ldsm4(qf[kc], sb + AQ + (wrow + lr) * 272 + kc * 32 + lc16);

    float of[16][4];
#pragma unroll
    for (int f = 0; f < 16; f++)
#pragma unroll
        for (int e = 0; e < 4; e++) of[f][e] = 0.0f;
    float m0 = -1e30f, m1 = -1e30f, l0 = 0.0f, l1 = 0.0f;

    for (int t = 0; t <= qb; t++) {
        CP_WAIT1();
        __syncthreads();

        float sc[8][4];
#pragma unroll
        for (int nf = 0; nf < 8; nf++)
#pragma unroll
            for (int e = 0; e < 4; e++) sc[nf][e] = 0.0f;

#pragma unroll
        for (int kc = 0; kc < 8; kc++) {
            uint32_t bh0[4][2], bh1[4][2], bl0[4][2], bl1[4][2];
#pragma unroll
            for (int np = 0; np < 4; np++) {
                uint32_t kh4[4], kl4[4];
                const uint32_t kaddr = sb + AK_HI + (np * 16 + lr) * 272 + kc * 32 + lc16;
                ldsm4(kh4, kaddr);
                ldsm4(kl4, kaddr + (AK_LO - AK_HI));
                bh0[np][0] = kh4[0]; bh0[np][1] = kh4[2];
                bh1[np][0] = kh4[1]; bh1[np][1] = kh4[3];
                bl0[np][0] = kl4[0]; bl0[np][1] = kl4[2];
                bl1[np][0] = kl4[1]; bl1[np][1] = kl4[3];
            }
#pragma unroll
            for (int np = 0; np < 4; np++) {
                mma16816(sc[2 * np], qf[kc], bh0[np]);
                mma16816(sc[2 * np + 1], qf[kc], bh1[np]);
            }
#pragma unroll
            for (int np = 0; np < 4; np++) {
                mma16816(sc[2 * np], qf[kc], bl0[np]);
                mma16816(sc[2 * np + 1], qf[kc], bl1[np]);
            }
        }

        __syncthreads();
        if (t < qb) {
            load_K(t + 1);
            CP_COMMIT();
        }

        if (t == qb) {
            const int row0 = q0 + wrow + (lane >> 2);
            const int colb = t * 64 + 2 * (lane & 3);
#pragma unroll
            for (int nf = 0; nf < 8; nf++) {
                const int cb = colb + 8 * nf;
                if (cb > row0) sc[nf][0] = -1e30f;
                if (cb + 1 > row0) sc[nf][1] = -1e30f;
                if (cb > row0 + 8) sc[nf][2] = -1e30f;
                if (cb + 1 > row0 + 8) sc[nf][3] = -1e30f;
            }
        }

        float rmax0 = -1e30f, rmax1 = -1e30f;
#pragma unroll
        for (int nf = 0; nf < 8; nf++) {
            rmax0 = fmaxf(rmax0, fmaxf(sc[nf][0], sc[nf][1]));
            rmax1 = fmaxf(rmax1, fmaxf(sc[nf][2], sc[nf][3]));
        }
        rmax0 = fmaxf(rmax0, __shfl_xor_sync(0xffffffffu, rmax0, 1));
        rmax0 = fmaxf(rmax0, __shfl_xor_sync(0xffffffffu, rmax0, 2));
        rmax1 = fmaxf(rmax1, __shfl_xor_sync(0xffffffffu, rmax1, 1));
        rmax1 = fmaxf(rmax1, __shfl_xor_sync(0xffffffffu, rmax1, 2));
        const float mn0 = fmaxf(m0, rmax0);
        const float mn1 = fmaxf(m1, rmax1);
        const float scl0 = __expf(m0 - mn0);
        const float scl1 = __expf(m1 - mn1);
        float rs0 = 0.0f, rs1 = 0.0f;
#pragma unroll
        for (int nf = 0; nf < 8; nf++) {
            sc[nf][0] = __expf(sc[nf][0] - mn0); rs0 += sc[nf][0];
            sc[nf][1] = __expf(sc[nf][1] - mn0); rs0 += sc[nf][1];
            sc[nf][2] = __expf(sc[nf][2] - mn1); rs1 += sc[nf][2];
            sc[nf][3] = __expf(sc[nf][3] - mn1); rs1 += sc[nf][3];
        }
        rs0 += __shfl_xor_sync(0xffffffffu, rs0, 1);
        rs0 += __shfl_xor_sync(0xffffffffu, rs0, 2);
        rs1 += __shfl_xor_sync(0xffffffffu, rs1, 1);
        rs1 += __shfl_xor_sync(0xffffffffu, rs1, 2);
        l0 = l0 * scl0 + rs0;
        l1 = l1 * scl1 + rs1;
        m0 = mn0;
        m1 = mn1;
#pragma unroll
        for (int f = 0; f < 16; f++) {
            of[f][0] *= scl0; of[f][1] *= scl0;
            of[f][2] *= scl1; of[f][3] *= scl1;
        }

        if (t < qb) CP_WAIT1(); else CP_WAIT0();
        __syncthreads();

#pragma unroll
        for (int kb = 0; kb < 4; kb++) {
            uint32_t ph[4];
            ph[0] = pack2(sc[2 * kb][0], sc[2 * kb][1]);
            ph[1] = pack2(sc[2 * kb][2], sc[2 * kb][3]);
            ph[2] = pack2(sc[2 * kb + 1][0], sc[2 * kb + 1][1]);
            ph[3] = pack2(sc[2 * kb + 1][2], sc[2 * kb + 1][3]);
            const uint32_t vbase = sb + AV_HI + (kb * 16 + lr) * 272 + lc16;
#pragma unroll
            for (int npp = 0; npp < 4; npp++) {
                const int np0 = 2 * npp, np1 = 2 * npp + 1;
                uint32_t vhA[4], vlA[4], vhB[4], vlB[4];
                ldsm4t(vhA, vbase + np0 * 32);
                ldsm4t(vlA, vbase + np0 * 32 + (AV_LO - AV_HI));
                ldsm4t(vhB, vbase + np1 * 32);
                ldsm4t(vlB, vbase + np1 * 32 + (AV_LO - AV_HI));
                uint32_t h0A[2] = {vhA[0], vhA[1]}, h1A[2] = {vhA[2], vhA[3]};
                uint32_t l0A[2] = {vlA[0], vlA[1]}, l1A[2] = {vlA[2], vlA[3]};
                uint32_t h0B[2] = {vhB[0], vhB[1]}, h1B[2] = {vhB[2], vhB[3]};
                uint32_t l0B[2] = {vlB[0], vlB[1]}, l1B[2] = {vlB[2], vlB[3]};
                mma16816(of[2 * np0], ph, h0A);
                mma16816(of[2 * np0 + 1], ph, h1A);
                mma16816(of[2 * np1], ph, h0B);
                mma16816(of[2 * np1 + 1], ph, h1B);
                mma16816(of[2 * np0], ph, l0A);
                mma16816(of[2 * np0 + 1], ph, l1A);
                mma16816(of[2 * np1], ph, l0B);
                mma16816(of[2 * np1 + 1], ph, l1B);
            }
        }

        __syncthreads();
        if (t < qb) {
            load_V(t + 1);
            CP_COMMIT();
        }
    }

    const float inv0 = 1.0f / l0;
    const float inv1 = 1.0f / l1;
    const int r0g = q0 + wrow + (lane >> 2);
    const int colb = 2 * (lane & 3);
#pragma unroll
    for (int nf = 0; nf < 16; nf++) {
        const int col = h * DHEAD + 8 * nf + colb;
        __half2 a = {__float2half_rn(of[nf][0] * inv0), __float2half_rn(of[nf][1] * inv0)};
        __half2 bvals = {__float2half_rn(of[nf][2] * inv1), __float2half_rn(of[nf][3] * inv1)};
        *(__half2*)(g_at + (size_t)(b * NS + r0g) * NHID + col) = a;
        *(__half2*)(g_at + (size_t)(b * NS + r0g + 8) * NHID + col) = bvals;
    }
}

// ------------------------- launch ------------------------------------------
extern "C" void kernel_launch(void* const* d_in, const int* in_sizes, int n_in,
                              void* d_out, int out_size) {
    const float* hidden = (const float*)d_in[0];
    const void* pos = d_in[1];
    const float* Wqkv = (const float*)d_in[2];
    const float* Wout = (const float*)d_in[3];
    float* out = (float*)d_out;

    void *p_qkv, *p_hid, *p_w1, *p_w2, *p_at;
    cudaGetSymbolAddress(&p_qkv, g_qkv);
    cudaGetSymbolAddress(&p_hid, g_hid);
    cudaGetSymbolAddress(&p_w1, g_w1);
    cudaGetSymbolAddress(&p_w2, g_w2);
    cudaGetSymbolAddress(&p_at, g_at);

    const int nHid = NB * NS * NHID;
    const int nW1 = NQKV * NHID;
    const int nW2 = NHID * NHID;

    conv_half<<<(nHid / 4 + 255) / 256, 256>>>(hidden, (__half*)p_hid, nHid / 4);
    conv_half<<<(nW1 / 4 + 255) / 256, 256>>>(Wqkv, (__half*)p_w1, nW1 / 4);
    conv_half<<<(nW2 / 4 + 255) / 256, 256>>>(Wout, (__half*)p_w2, nW2 / 4);

    // 1) QKV projection + clamp (1-pass fp16)
    {
        cudaFuncSetAttribute(gemm_1p<1>, cudaFuncAttributeMaxDynamicSharedMemorySize, GSMEM);
        dim3 grid(NQKV / 64, (NB * NS) / 128);
        gemm_1p<1><<<grid, 256, GSMEM>>>(
            (const __half*)p_hid, (const __half*)p_w1,
            (float*)p_qkv, NB * NS, NQKV, NHID);
    }
    // 2) RoPE + scatter
    rope_scatter<<<NB * NS, 128>>>(pos);

    // 3) tensor-core causal flash attention (2-pass)
    {
        cudaFuncSetAttribute(flash_attn_tc, cudaFuncAttributeMaxDynamicSharedMemorySize, ATTN_SMEM);
        dim3 grid(NS / 64, NHEADS, NB);
        flash_attn_tc<<<grid, 128, ATTN_SMEM>>>();
    }
    // 4) output projection (1-pass fp16)
    {
        cudaFuncSetAttribute(gemm_1p<0>, cudaFuncAttributeMaxDynamicSharedMemorySize, GSMEM);
        dim3 grid(NHID / 64, (NB * NS) / 128);
        gemm_1p<0><<<grid, 256, GSMEM>>>(
            (const __half*)p_at, (const __half*)p_w2,
            out, NB * NS, NHID, NHID);
    }
}

// round 14
// speedup vs baseline: 2.3985x; 1.2395x over previous
#include <cuda_runtime.h>
#include <cuda_fp16.h>
#include <cstdint>
#include <math.h>

#define NB 2
#define NS 2048
#define NHID 2048
#define NHEADS 16
#define NKVH 4
#define DHEAD 128
#define NQKV 3072

// ------------------------- scratch (static device globals; no allocs) ------
static __device__ float g_qkv[(size_t)NB * NS * NQKV];

static __device__ __half g_q[(size_t)NB * NHEADS * NS * DHEAD];
static __device__ __half g_k[(size_t)NB * NKVH * NS * DHEAD];
static __device__ __half g_v[(size_t)NB * NKVH * NS * DHEAD];

static __device__ __half g_hid[(size_t)NB * NS * NHID];
static __device__ __half g_w1[(size_t)NQKV * NHID];
static __device__ __half g_w2[(size_t)NHID * NHID];
static __device__ __half g_at[(size_t)NB * NS * NHID];

// ------------------------- PTX helpers (baseline ISA only) -----------------
__device__ __forceinline__ uint32_t smem_u32(const void* p) {
    uint32_t a;
    asm("{ .reg .u64 t; cvta.to.shared.u64 t, %1; cvt.u32.u64 %0, t; }"
        : "=r"(a) : "l"(p));
    return a;
}

__device__ __forceinline__ void cp16(uint32_t dst, const void* src) {
    asm volatile("cp.async.cg.shared.global [%0], [%1], 16;"
                 :: "r"(dst), "l"(src));
}
#define CP_COMMIT() asm volatile("cp.async.commit_group;" ::: "memory")
#define CP_WAIT0() asm volatile("cp.async.wait_group 0;" ::: "memory")
#define CP_WAIT1() asm volatile("cp.async.wait_group 1;" ::: "memory")
#define CP_WAIT2() asm volatile("cp.async.wait_group 2;" ::: "memory")

__device__ __forceinline__ void ldsm4(uint32_t* r, uint32_t addr) {
    asm volatile("ldmatrix.sync.aligned.m8n8.x4.shared.b16 {%0,%1,%2,%3}, [%4];"
                 : "=r"(r[0]), "=r"(r[1]), "=r"(r[2]), "=r"(r[3]) : "r"(addr));
}

__device__ __forceinline__ void ldsm4t(uint32_t* r, uint32_t addr) {
    asm volatile("ldmatrix.sync.aligned.m8n8.x4.trans.shared.b16 {%0,%1,%2,%3}, [%4];"
                 : "=r"(r[0]), "=r"(r[1]), "=r"(r[2]), "=r"(r[3]) : "r"(addr));
}

__device__ __forceinline__ void mma16816(float* c, const uint32_t* a, const uint32_t* b) {
    asm volatile(
        "mma.sync.aligned.m16n8k16.row.col.f32.f16.f16.f32 "
        "{%0,%1,%2,%3}, {%4,%5,%6,%7}, {%8,%9}, {%0,%1,%2,%3};"
        : "+f"(c[0]), "+f"(c[1]), "+f"(c[2]), "+f"(c[3])
        : "r"(a[0]), "r"(a[1]), "r"(a[2]), "r"(a[3]), "r"(b[0]), "r"(b[1]));
}

__device__ __forceinline__ uint32_t pack2(float a, float b) {
    __half2 p = {__float2half_rn(a), __float2half_rn(b)};
    return *(uint32_t*)&p;
}

#define SWZ64(x) ((x) ^ (((x) >> 3) & 0x30))

// ------------------------- fp32 -> fp16 convert ----------------------------
__global__ void __launch_bounds__(256) conv_half(const float* __restrict__ x,
                                                 __half* __restrict__ o, int n4) {
    int i = blockIdx.x * 256 + threadIdx.x;
    if (i >= n4) return;
    float4 v = ((const float4*)x)[i];
    __half2 a = {__float2half_rn(v.x), __float2half_rn(v.y)};
    __half2 b = {__float2half_rn(v.z), __float2half_rn(v.w)};
    ((__half2*)o)[2 * i] = a;
    ((__half2*)o)[2 * i + 1] = b;
}

// ------------------------- 1-pass HMMA GEMM: C = A * B^T -------------------
#define GST 12288
#define GSMEM (2 * GST)

template <int CLAMP>
__global__ void __launch_bounds__(256, 3) gemm_1p(const __half* __restrict__ A,
                                                  const __half* __restrict__ B,
                                                  float* __restrict__ C,
                                                  int M, int N, int K) {
    extern __shared__ char smem[];
    const uint32_t sb = smem_u32(smem);
    const int tid = threadIdx.x;
    const int lane = tid & 31;
    const int wid = tid >> 5;
    const int wm = (wid & 3) * 32;
    const int wn = (wid >> 2) * 32;
    const int bx = blockIdx.x;
    const int by = blockIdx.y;

    auto load_stage = [&](int st, int kt) {
        const uint32_t s = sb + st * GST;
        const int kc = kt * 32;
#pragma unroll
        for (int i = 0; i < 2; i++) {
            const int q = tid + i * 256;
            const int r = q >> 2, c = q & 3;
            cp16(s + SWZ64(r * 64 + c * 16), A + (size_t)(by * 128 + r) * K + kc + c * 8);
        }
        {
            const int r = tid >> 2, c = tid & 3;
            cp16(s + 8192 + SWZ64(r * 64 + c * 16), B + (size_t)(bx * 64 + r) * K + kc + c * 8);
        }
    };

    float acc[2][4][4];
#pragma unroll
    for (int i = 0; i < 2; i++)
#pragma unroll
        for (int j = 0; j < 4; j++)
#pragma unroll
            for (int e = 0; e < 4; e++) acc[i][j][e] = 0.0f;

    const int KT = K >> 5;
    load_stage(0, 0);
    CP_COMMIT();

    const int lr = (lane & 7) + ((lane >> 3) & 1) * 8;
    const int lc = lane >> 4;

    for (int kt = 0; kt < KT; kt++) {
        CP_WAIT0();
        __syncthreads();
        if (kt + 1 < KT) {
            load_stage((kt + 1) & 1, kt + 1);
            CP_COMMIT();
        }
        const uint32_t s = sb + (kt & 1) * GST;
#pragma unroll
        for (int ks = 0; ks < 2; ks++) {
            const int ch = 2 * ks + lc;
            uint32_t bf[4][2];
#pragma unroll
            for (int nf2 = 0; nf2 < 2; nf2++) {
                uint32_t tb[4];
                ldsm4(tb, s + 8192 + SWZ64((wn + nf2 * 16 + lr) * 64 + ch * 16));
                bf[nf2 * 2][0] = tb[0]; bf[nf2 * 2 + 1][0] = tb[1];
                bf[nf2 * 2][1] = tb[2]; bf[nf2 * 2 + 1][1] = tb[3];
            }
#pragma unroll
            for (int mf = 0; mf < 2; mf++) {
                uint32_t af[4];
                ldsm4(af, s + SWZ64((wm + mf * 16 + lr) * 64 + ch * 16));
#pragma unroll
                for (int nf = 0; nf < 4; nf++) mma16816(acc[mf][nf], af, bf[nf]);
            }
        }
    }

    const int erow = lane >> 2;
    const int ecol = (lane & 3) * 2;
#pragma unroll
    for (int mf = 0; mf < 2; mf++) {
#pragma unroll
        for (int nf = 0; nf < 4; nf++) {
            float* c = acc[mf][nf];
            if (CLAMP) {
#pragma unroll
                for (int e = 0; e < 4; e++)
                    c[e] = fminf(8.0f, fmaxf(-8.0f, c[e]));
            }
            const int row = by * 128 + wm + mf * 16 + erow;
            const int col = bx * 64 + wn + nf * 8 + ecol;
            float2 v0 = {c[0], c[1]};
            float2 v1 = {c[2], c[3]};
            *(float2*)(C + (size_t)row * N + col) = v0;
            *(float2*)(C + (size_t)(row + 8) * N + col) = v1;
        }
    }
}

// ------------------------- RoPE + scatter ----------------------------------
__global__ void __launch_bounds__(128) rope_scatter(const void* __restrict__ pos_ids) {
    const int bs = blockIdx.x;
    const int b = bs / NS;
    const int s = bs % NS;
    const int d = threadIdx.x;
    const int dm = d & 63;

    const int* p32 = (const int*)pos_ids;
    const bool is64 = (p32[1] == 0) && (p32[3] == 0) && (p32[2 * NS + 1] == 0);
    const long long pv = is64 ? ((const long long*)pos_ids)[bs] : (long long)p32[bs];

    const double p = (double)pv;
    const double C_LN = 0.20503692777194264;  // ln(500000)/64
    const double invf = exp(-(double)dm * C_LN);
    double sd, cd;
    sincos(p * invf, &sd, &cd);
    const float c = (float)cd;
    const float sn = (float)sd;
    const float sign = (d < 64) ? -1.0f : 1.0f;
    const float qscale = 0.08838834764831845f;

    const float* row = g_qkv + (size_t)bs * NQKV;

#pragma unroll
    for (int h = 0; h < NHEADS; h++) {
        float v = row[h * DHEAD + d];
        float pr = row[h * DHEAD + (d ^ 64)];
        float qv = (v * c + sign * pr * sn) * qscale;
        g_q[(((size_t)b * NHEADS + h) * NS + s) * DHEAD + d] = __float2half_rn(qv);
    }
#pragma unroll
    for (int h = 0; h < NKVH; h++) {
        float v = row[NHID + h * DHEAD + d];
        float pr = row[NHID + h * DHEAD + (d ^ 64)];
        float kv = v * c + sign * pr * sn;
        size_t idx = (((size_t)b * NKVH + h) * NS + s) * DHEAD + d;
        g_k[idx] = __float2half_rn(kv);
        g_v[idx] = __float2half_rn(row[NHID + NKVH * DHEAD + h * DHEAD + d]);
    }
}

// ------------------------- tensor-core flash attention ---------------------
// BM=64, BN=64, 4 warps. 1-pass fp16 everywhere. Pipelined K/V prefetch.
#define AQ 0
#define AK 17408
#define AV 34816
#define ATTN_SMEM 52224

__global__ void __launch_bounds__(128) flash_attn_tc() {
    extern __shared__ char smem[];
    const uint32_t sb = smem_u32(smem);
    const int tid = threadIdx.x;
    const int lane = tid & 31;
    const int w = tid >> 5;
    const int qb = gridDim.x - 1 - blockIdx.x;
    const int h = blockIdx.y;
    const int b = blockIdx.z;
    const int hk = h >> 2;
    const int q0 = qb * 64;
    const int wrow = w * 16;

    const __half* Qg = g_q + ((size_t)(b * NHEADS + h) * NS + q0) * DHEAD;
    const __half* Kg = g_k + ((size_t)(b * NKVH + hk) * NS) * DHEAD;
    const __half* Vg = g_v + ((size_t)(b * NKVH + hk) * NS) * DHEAD;

    auto load_K = [&](int t) {
#pragma unroll
        for (int i = 0; i < 8; i++) {
            int q = tid + i * 128;
            int r = q >> 4, cc = q & 15;
            cp16(sb + AK + r * 272 + cc * 16, Kg + (size_t)(t * 64 + r) * DHEAD + cc * 8);
        }
    };
    auto load_V = [&](int t) {
#pragma unroll
        for (int i = 0; i < 8; i++) {
            int q = tid + i * 128;
            int r = q >> 4, cc = q & 15;
            cp16(sb + AV + r * 272 + cc * 16, Vg + (size_t)(t * 64 + r) * DHEAD + cc * 8);
        }
    };

#pragma unroll
    for (int i = 0; i < 8; i++) {
        int q = tid + i * 128;
        int r = q >> 4, cc = q & 15;
        cp16(sb + AQ + r * 272 + cc * 16, Qg + (size_t)r * DHEAD + cc * 8);
    }
    CP_COMMIT();
    load_K(0);
    CP_COMMIT();
    load_V(0);
    CP_COMMIT();

    const int lr = (lane & 7) + ((lane >> 3) & 1) * 8;
    const int lc16 = (lane >> 4) * 16;

    CP_WAIT2();
    __syncthreads();
    uint32_t qf[8][4];
#pragma unroll
    for (int kc = 0; kc < 8; kc++)
        ldsm4(qf[kc], sb + AQ + (wrow + lr) * 272 + kc * 32 + lc16);

    float of[16][4];
#pragma unroll
    for (int f = 0; f < 16; f++)
#pragma unroll
        for (int e = 0; e < 4; e++) of[f][e] = 0.0f;
    float m0 = -1e30f, m1 = -1e30f, l0 = 0.0f, l1 = 0.0f;

    for (int t = 0; t <= qb; t++) {
        CP_WAIT1();   // K(t) landed (V(t) may be in flight)
        __syncthreads();

        float sc[8][4];
#pragma unroll
        for (int nf = 0; nf < 8; nf++)
#pragma unroll
            for (int e = 0; e < 4; e++) sc[nf][e] = 0.0f;

#pragma unroll
        for (int kc = 0; kc < 8; kc++) {
            uint32_t b0[4][2], b1[4][2];
#pragma unroll
            for (int np = 0; np < 4; np++) {
                uint32_t k4[4];
                ldsm4(k4, sb + AK + (np * 16 + lr) * 272 + kc * 32 + lc16);
                b0[np][0] = k4[0]; b0[np][1] = k4[2];
                b1[np][0] = k4[1]; b1[np][1] = k4[3];
            }
#pragma unroll
            for (int np = 0; np < 4; np++) {
                mma16816(sc[2 * np], qf[kc], b0[np]);
                mma16816(sc[2 * np + 1], qf[kc], b1[np]);
            }
        }

        __syncthreads();
        if (t < qb) {
            load_K(t + 1);
            CP_COMMIT();
        }

        if (t == qb) {
            const int row0 = q0 + wrow + (lane >> 2);
            const int colb = t * 64 + 2 * (lane & 3);
#pragma unroll
            for (int nf = 0; nf < 8; nf++) {
                const int cb = colb + 8 * nf;
                if (cb > row0) sc[nf][0] = -1e30f;
                if (cb + 1 > row0) sc[nf][1] = -1e30f;
                if (cb > row0 + 8) sc[nf][2] = -1e30f;
                if (cb + 1 > row0 + 8) sc[nf][3] = -1e30f;
            }
        }

        float rmax0 = -1e30f, rmax1 = -1e30f;
#pragma unroll
        for (int nf = 0; nf < 8; nf++) {
            rmax0 = fmaxf(rmax0, fmaxf(sc[nf][0], sc[nf][1]));
            rmax1 = fmaxf(rmax1, fmaxf(sc[nf][2], sc[nf][3]));
        }
        rmax0 = fmaxf(rmax0, __shfl_xor_sync(0xffffffffu, rmax0, 1));
        rmax0 = fmaxf(rmax0, __shfl_xor_sync(0xffffffffu, rmax0, 2));
        rmax1 = fmaxf(rmax1, __shfl_xor_sync(0xffffffffu, rmax1, 1));
        rmax1 = fmaxf(rmax1, __shfl_xor_sync(0xffffffffu, rmax1, 2));
        const float mn0 = fmaxf(m0, rmax0);
        const float mn1 = fmaxf(m1, rmax1);
        const float scl0 = __expf(m0 - mn0);
        const float scl1 = __expf(m1 - mn1);
        float rs0 = 0.0f, rs1 = 0.0f;
#pragma unroll
        for (int nf = 0; nf < 8; nf++) {
            sc[nf][0] = __expf(sc[nf][0] - mn0); rs0 += sc[nf][0];
            sc[nf][1] = __expf(sc[nf][1] - mn0); rs0 += sc[nf][1];
            sc[nf][2] = __expf(sc[nf][2] - mn1); rs1 += sc[nf][2];
            sc[nf][3] = __expf(sc[nf][3] - mn1); rs1 += sc[nf][3];
        }
        rs0 += __shfl_xor_sync(0xffffffffu, rs0, 1);
        rs0 += __shfl_xor_sync(0xffffffffu, rs0, 2);
        rs1 += __shfl_xor_sync(0xffffffffu, rs1, 1);
        rs1 += __shfl_xor_sync(0xffffffffu, rs1, 2);
        l0 = l0 * scl0 + rs0;
        l1 = l1 * scl1 + rs1;
        m0 = mn0;
        m1 = mn1;
#pragma unroll
        for (int f = 0; f < 16; f++) {
            of[f][0] *= scl0; of[f][1] *= scl0;
            of[f][2] *= scl1; of[f][3] *= scl1;
        }

        if (t < qb) CP_WAIT1(); else CP_WAIT0();
        __syncthreads();

        // O += P V (P packed fp16; V via ldsm.trans)
#pragma unroll
        for (int kb = 0; kb < 4; kb++) {
            uint32_t ph[4];
            ph[0] = pack2(sc[2 * kb][0], sc[2 * kb][1]);
            ph[1] = pack2(sc[2 * kb][2], sc[2 * kb][3]);
            ph[2] = pack2(sc[2 * kb + 1][0], sc[2 * kb + 1][1]);
            ph[3] = pack2(sc[2 * kb + 1][2], sc[2 * kb + 1][3]);
            const uint32_t vbase = sb + AV + (kb * 16 + lr) * 272 + lc16;
#pragma unroll
            for (int npp = 0; npp < 4; npp++) {
                const int np0 = 2 * npp, np1 = 2 * npp + 1;
                uint32_t vA[4], vB[4];
                ldsm4t(vA, vbase + np0 * 32);
                ldsm4t(vB, vbase + np1 * 32);
                uint32_t h0A[2] = {vA[0], vA[1]}, h1A[2] = {vA[2], vA[3]};
                uint32_t h0B[2] = {vB[0], vB[1]}, h1B[2] = {vB[2], vB[3]};
                mma16816(of[2 * np0], ph, h0A);
                mma16816(of[2 * np0 + 1], ph, h1A);
                mma16816(of[2 * np1], ph, h0B);
                mma16816(of[2 * np1 + 1], ph, h1B);
            }
        }

        __syncthreads();
        if (t < qb) {
            load_V(t + 1);
            CP_COMMIT();
        }
    }

    const float inv0 = 1.0f / l0;
    const float inv1 = 1.0f / l1;
    const int r0g = q0 + wrow + (lane >> 2);
    const int colb = 2 * (lane & 3);
#pragma unroll
    for (int nf = 0; nf < 16; nf++) {
        const int col = h * DHEAD + 8 * nf + colb;
        __half2 a = {__float2half_rn(of[nf][0] * inv0), __float2half_rn(of[nf][1] * inv0)};
        __half2 bvals = {__float2half_rn(of[nf][2] * inv1), __float2half_rn(of[nf][3] * inv1)};
        *(__half2*)(g_at + (size_t)(b * NS + r0g) * NHID + col) = a;
        *(__half2*)(g_at + (size_t)(b * NS + r0g + 8) * NHID + col) = bvals;
    }
}

// ------------------------- launch ------------------------------------------
extern "C" void kernel_launch(void* const* d_in, const int* in_sizes, int n_in,
                              void* d_out, int out_size) {
    const float* hidden = (const float*)d_in[0];
    const void* pos = d_in[1];
    const float* Wqkv = (const float*)d_in[2];
    const float* Wout = (const float*)d_in[3];
    float* out = (float*)d_out;

    void *p_qkv, *p_hid, *p_w1, *p_w2, *p_at;
    cudaGetSymbolAddress(&p_qkv, g_qkv);
    cudaGetSymbolAddress(&p_hid, g_hid);
    cudaGetSymbolAddress(&p_w1, g_w1);
    cudaGetSymbolAddress(&p_w2, g_w2);
    cudaGetSymbolAddress(&p_at, g_at);

    const int nHid = NB * NS * NHID;
    const int nW1 = NQKV * NHID;
    const int nW2 = NHID * NHID;

    conv_half<<<(nHid / 4 + 255) / 256, 256>>>(hidden, (__half*)p_hid, nHid / 4);
    conv_half<<<(nW1 / 4 + 255) / 256, 256>>>(Wqkv, (__half*)p_w1, nW1 / 4);
    conv_half<<<(nW2 / 4 + 255) / 256, 256>>>(Wout, (__half*)p_w2, nW2 / 4);

    // 1) QKV projection + clamp (1-pass fp16)
    {
        cudaFuncSetAttribute(gemm_1p<1>, cudaFuncAttributeMaxDynamicSharedMemorySize, GSMEM);
        dim3 grid(NQKV / 64, (NB * NS) / 128);
        gemm_1p<1><<<grid, 256, GSMEM>>>(
            (const __half*)p_hid, (const __half*)p_w1,
            (float*)p_qkv, NB * NS, NQKV, NHID);
    }
    // 2) RoPE + scatter
    rope_scatter<<<NB * NS, 128>>>(pos);

    // 3) tensor-core causal flash attention (1-pass)
    {
        cudaFuncSetAttribute(flash_attn_tc, cudaFuncAttributeMaxDynamicSharedMemorySize, ATTN_SMEM);
        dim3 grid(NS / 64, NHEADS, NB);
        flash_attn_tc<<<grid, 128, ATTN_SMEM>>>();
    }
    // 4) output projection (1-pass fp16)
    {
        cudaFuncSetAttribute(gemm_1p<0>, cudaFuncAttributeMaxDynamicSharedMemorySize, GSMEM);
        dim3 grid(NHID / 64, (NB * NS) / 128);
        gemm_1p<0><<<grid, 256, GSMEM>>>(
            (const __half*)p_at, (const __half*)p_w2,
            out, NB * NS, NHID, NHID);
    }
}

// round 15
// speedup vs baseline: 2.4218x; 1.0097x over previous
#include <cuda_runtime.h>
#include <cuda_fp16.h>
#include <cstdint>
#include <math.h>

#define NB 2
#define NS 2048
#define NHID 2048
#define NHEADS 16
#define NKVH 4
#define DHEAD 128
#define NQKV 3072

// ------------------------- scratch (static device globals; no allocs) ------
static __device__ float g_qkv[(size_t)NB * NS * NQKV];

static __device__ __half g_q[(size_t)NB * NHEADS * NS * DHEAD];
static __device__ __half g_k[(size_t)NB * NKVH * NS * DHEAD];
static __device__ __half g_v[(size_t)NB * NKVH * NS * DHEAD];

static __device__ __half g_hid[(size_t)NB * NS * NHID];
static __device__ __half g_w1[(size_t)NQKV * NHID];
static __device__ __half g_w2[(size_t)NHID * NHID];
static __device__ __half g_at[(size_t)NB * NS * NHID];

// ------------------------- PTX helpers (baseline ISA only) -----------------
__device__ __forceinline__ uint32_t smem_u32(const void* p) {
    uint32_t a;
    asm("{ .reg .u64 t; cvta.to.shared.u64 t, %1; cvt.u32.u64 %0, t; }"
        : "=r"(a) : "l"(p));
    return a;
}

__device__ __forceinline__ void cp16(uint32_t dst, const void* src) {
    asm volatile("cp.async.cg.shared.global [%0], [%1], 16;"
                 :: "r"(dst), "l"(src));
}
#define CP_COMMIT() asm volatile("cp.async.commit_group;" ::: "memory")
#define CP_WAIT0() asm volatile("cp.async.wait_group 0;" ::: "memory")
#define CP_WAIT1() asm volatile("cp.async.wait_group 1;" ::: "memory")
#define CP_WAIT2() asm volatile("cp.async.wait_group 2;" ::: "memory")

__device__ __forceinline__ void ldsm4(uint32_t* r, uint32_t addr) {
    asm volatile("ldmatrix.sync.aligned.m8n8.x4.shared.b16 {%0,%1,%2,%3}, [%4];"
                 : "=r"(r[0]), "=r"(r[1]), "=r"(r[2]), "=r"(r[3]) : "r"(addr));
}

__device__ __forceinline__ void ldsm4t(uint32_t* r, uint32_t addr) {
    asm volatile("ldmatrix.sync.aligned.m8n8.x4.trans.shared.b16 {%0,%1,%2,%3}, [%4];"
                 : "=r"(r[0]), "=r"(r[1]), "=r"(r[2]), "=r"(r[3]) : "r"(addr));
}

__device__ __forceinline__ void mma16816(float* c, const uint32_t* a, const uint32_t* b) {
    asm volatile(
        "mma.sync.aligned.m16n8k16.row.col.f32.f16.f16.f32 "
        "{%0,%1,%2,%3}, {%4,%5,%6,%7}, {%8,%9}, {%0,%1,%2,%3};"
        : "+f"(c[0]), "+f"(c[1]), "+f"(c[2]), "+f"(c[3])
        : "r"(a[0]), "r"(a[1]), "r"(a[2]), "r"(a[3]), "r"(b[0]), "r"(b[1]));
}

__device__ __forceinline__ uint32_t pack2(float a, float b) {
    __half2 p = {__float2half_rn(a), __float2half_rn(b)};
    return *(uint32_t*)&p;
}

#define SWZ64(x) ((x) ^ (((x) >> 3) & 0x30))

// ------------------------- fp32 -> fp16 convert ----------------------------
__global__ void __launch_bounds__(256) conv_half(const float* __restrict__ x,
                                                 __half* __restrict__ o, int n4) {
    int i = blockIdx.x * 256 + threadIdx.x;
    if (i >= n4) return;
    float4 v = ((const float4*)x)[i];
    __half2 a = {__float2half_rn(v.x), __float2half_rn(v.y)};
    __half2 b = {__float2half_rn(v.z), __float2half_rn(v.w)};
    ((__half2*)o)[2 * i] = a;
    ((__half2*)o)[2 * i + 1] = b;
}

// ------------------------- 1-pass HMMA GEMM: C = A * B^T -------------------
// CTA 128x64, 128 threads, 4 warps, warp tile 64x32, BK=32.
// Tiles: 64B rows (SWZ64). Stage = A 8KB + B 4KB = 12KB; double buffered.
#define GST 12288
#define GSMEM (2 * GST)

template <int CLAMP>
__global__ void __launch_bounds__(128, 4) gemm_1p(const __half* __restrict__ A,
                                                  const __half* __restrict__ B,
                                                  float* __restrict__ C,
                                                  int M, int N, int K) {
    extern __shared__ char smem[];
    const uint32_t sb = smem_u32(smem);
    const int tid = threadIdx.x;
    const int lane = tid & 31;
    const int wid = tid >> 5;
    const int wm = (wid & 1) * 64;   // M offset within 128
    const int wn = (wid >> 1) * 32;  // N offset within 64
    const int bx = blockIdx.x;
    const int by = blockIdx.y;

    auto load_stage = [&](int st, int kt) {
        const uint32_t s = sb + st * GST;
        const int kc = kt * 32;
#pragma unroll
        for (int i = 0; i < 4; i++) {  // A: 128 rows x 4 chunks = 512 tasks
            const int q = tid + i * 128;
            const int r = q >> 2, c = q & 3;
            cp16(s + SWZ64(r * 64 + c * 16), A + (size_t)(by * 128 + r) * K + kc + c * 8);
        }
#pragma unroll
        for (int i = 0; i < 2; i++) {  // B: 64 rows x 4 chunks = 256 tasks
            const int q = tid + i * 128;
            const int r = q >> 2, c = q & 3;
            cp16(s + 8192 + SWZ64(r * 64 + c * 16), B + (size_t)(bx * 64 + r) * K + kc + c * 8);
        }
    };

    float acc[4][4][4];
#pragma unroll
    for (int i = 0; i < 4; i++)
#pragma unroll
        for (int j = 0; j < 4; j++)
#pragma unroll
            for (int e = 0; e < 4; e++) acc[i][j][e] = 0.0f;

    const int KT = K >> 5;
    load_stage(0, 0);
    CP_COMMIT();

    const int lr = (lane & 7) + ((lane >> 3) & 1) * 8;
    const int lc = lane >> 4;

    for (int kt = 0; kt < KT; kt++) {
        CP_WAIT0();
        __syncthreads();
        if (kt + 1 < KT) {
            load_stage((kt + 1) & 1, kt + 1);
            CP_COMMIT();
        }
        const uint32_t s = sb + (kt & 1) * GST;
#pragma unroll
        for (int ks = 0; ks < 2; ks++) {
            const int ch = 2 * ks + lc;  // 0..3
            uint32_t bf[4][2];
#pragma unroll
            for (int nf2 = 0; nf2 < 2; nf2++) {
                uint32_t tb[4];
                ldsm4(tb, s + 8192 + SWZ64((wn + nf2 * 16 + lr) * 64 + ch * 16));
                bf[nf2 * 2][0] = tb[0]; bf[nf2 * 2 + 1][0] = tb[1];
                bf[nf2 * 2][1] = tb[2]; bf[nf2 * 2 + 1][1] = tb[3];
            }
            uint32_t af[4][4];
#pragma unroll
            for (int mf = 0; mf < 4; mf++)
                ldsm4(af[mf], s + SWZ64((wm + mf * 16 + lr) * 64 + ch * 16));
            // 16 independent MMAs
#pragma unroll
            for (int mf = 0; mf < 4; mf++)
#pragma unroll
                for (int nf = 0; nf < 4; nf++)
                    mma16816(acc[mf][nf], af[mf], bf[nf]);
        }
    }

    const int erow = lane >> 2;
    const int ecol = (lane & 3) * 2;
#pragma unroll
    for (int mf = 0; mf < 4; mf++) {
#pragma unroll
        for (int nf = 0; nf < 4; nf++) {
            float* c = acc[mf][nf];
            if (CLAMP) {
#pragma unroll
                for (int e = 0; e < 4; e++)
                    c[e] = fminf(8.0f, fmaxf(-8.0f, c[e]));
            }
            const int row = by * 128 + wm + mf * 16 + erow;
            const int col = bx * 64 + wn + nf * 8 + ecol;
            float2 v0 = {c[0], c[1]};
            float2 v1 = {c[2], c[3]};
            *(float2*)(C + (size_t)row * N + col) = v0;
            *(float2*)(C + (size_t)(row + 8) * N + col) = v1;
        }
    }
}

// ------------------------- RoPE + scatter ----------------------------------
__global__ void __launch_bounds__(128) rope_scatter(const void* __restrict__ pos_ids) {
    const int bs = blockIdx.x;
    const int b = bs / NS;
    const int s = bs % NS;
    const int d = threadIdx.x;
    const int dm = d & 63;

    const int* p32 = (const int*)pos_ids;
    const bool is64 = (p32[1] == 0) && (p32[3] == 0) && (p32[2 * NS + 1] == 0);
    const long long pv = is64 ? ((const long long*)pos_ids)[bs] : (long long)p32[bs];

    const double p = (double)pv;
    const double C_LN = 0.20503692777194264;  // ln(500000)/64
    const double invf = exp(-(double)dm * C_LN);
    double sd, cd;
    sincos(p * invf, &sd, &cd);
    const float c = (float)cd;
    const float sn = (float)sd;
    const float sign = (d < 64) ? -1.0f : 1.0f;
    const float qscale = 0.08838834764831845f;

    const float* row = g_qkv + (size_t)bs * NQKV;

#pragma unroll
    for (int h = 0; h < NHEADS; h++) {
        float v = row[h * DHEAD + d];
        float pr = row[h * DHEAD + (d ^ 64)];
        float qv = (v * c + sign * pr * sn) * qscale;
        g_q[(((size_t)b * NHEADS + h) * NS + s) * DHEAD + d] = __float2half_rn(qv);
    }
#pragma unroll
    for (int h = 0; h < NKVH; h++) {
        float v = row[NHID + h * DHEAD + d];
        float pr = row[NHID + h * DHEAD + (d ^ 64)];
        float kv = v * c + sign * pr * sn;
        size_t idx = (((size_t)b * NKVH + h) * NS + s) * DHEAD + d;
        g_k[idx] = __float2half_rn(kv);
        g_v[idx] = __float2half_rn(row[NHID + NKVH * DHEAD + h * DHEAD + d]);
    }
}

// ------------------------- tensor-core flash attention ---------------------
// BM=64, BN=64, 4 warps. 1-pass fp16 everywhere. Pipelined K/V prefetch.
#define AQ 0
#define AK 17408
#define AV 34816
#define ATTN_SMEM 52224

__global__ void __launch_bounds__(128) flash_attn_tc() {
    extern __shared__ char smem[];
    const uint32_t sb = smem_u32(smem);
    const int tid = threadIdx.x;
    const int lane = tid & 31;
    const int w = tid >> 5;
    const int qb = gridDim.x - 1 - blockIdx.x;
    const int h = blockIdx.y;
    const int b = blockIdx.z;
    const int hk = h >> 2;
    const int q0 = qb * 64;
    const int wrow = w * 16;

    const __half* Qg = g_q + ((size_t)(b * NHEADS + h) * NS + q0) * DHEAD;
    const __half* Kg = g_k + ((size_t)(b * NKVH + hk) * NS) * DHEAD;
    const __half* Vg = g_v + ((size_t)(b * NKVH + hk) * NS) * DHEAD;

    auto load_K = [&](int t) {
#pragma unroll
        for (int i = 0; i < 8; i++) {
            int q = tid + i * 128;
            int r = q >> 4, cc = q & 15;
            cp16(sb + AK + r * 272 + cc * 16, Kg + (size_t)(t * 64 + r) * DHEAD + cc * 8);
        }
    };
    auto load_V = [&](int t) {
#pragma unroll
        for (int i = 0; i < 8; i++) {
            int q = tid + i * 128;
            int r = q >> 4, cc = q & 15;
            cp16(sb + AV + r * 272 + cc * 16, Vg + (size_t)(t * 64 + r) * DHEAD + cc * 8);
        }
    };

#pragma unroll
    for (int i = 0; i < 8; i++) {
        int q = tid + i * 128;
        int r = q >> 4, cc = q & 15;
        cp16(sb + AQ + r * 272 + cc * 16, Qg + (size_t)r * DHEAD + cc * 8);
    }
    CP_COMMIT();
    load_K(0);
    CP_COMMIT();
    load_V(0);
    CP_COMMIT();

    const int lr = (lane & 7) + ((lane >> 3) & 1) * 8;
    const int lc16 = (lane >> 4) * 16;

    CP_WAIT2();
    __syncthreads();
    uint32_t qf[8][4];
#pragma unroll
    for (int kc = 0; kc < 8; kc++)
        ldsm4(qf[kc], sb + AQ + (wrow + lr) * 272 + kc * 32 + lc16);

    float of[16][4];
#pragma unroll
    for (int f = 0; f < 16; f++)
#pragma unroll
        for (int e = 0; e < 4; e++) of[f][e] = 0.0f;
    float m0 = -1e30f, m1 = -1e30f, l0 = 0.0f, l1 = 0.0f;

    for (int t = 0; t <= qb; t++) {
        CP_WAIT1();
        __syncthreads();

        float sc[8][4];
#pragma unroll
        for (int nf = 0; nf < 8; nf++)
#pragma unroll
            for (int e = 0; e < 4; e++) sc[nf][e] = 0.0f;

#pragma unroll
        for (int kc = 0; kc < 8; kc++) {
            uint32_t b0[4][2], b1[4][2];
#pragma unroll
            for (int np = 0; np < 4; np++) {
                uint32_t k4[4];
                ldsm4(k4, sb + AK + (np * 16 + lr) * 272 + kc * 32 + lc16);
                b0[np][0] = k4[0]; b0[np][1] = k4[2];
                b1[np][0] = k4[1]; b1[np][1] = k4[3];
            }
#pragma unroll
            for (int np = 0; np < 4; np++) {
                mma16816(sc[2 * np], qf[kc], b0[np]);
                mma16816(sc[2 * np + 1], qf[kc], b1[np]);
            }
        }

        __syncthreads();
        if (t < qb) {
            load_K(t + 1);
            CP_COMMIT();
        }

        if (t == qb) {
            const int row0 = q0 + wrow + (lane >> 2);
            const int colb = t * 64 + 2 * (lane & 3);
#pragma unroll
            for (int nf = 0; nf < 8; nf++) {
                const int cb = colb + 8 * nf;
                if (cb > row0) sc[nf][0] = -1e30f;
                if (cb + 1 > row0) sc[nf][1] = -1e30f;
                if (cb > row0 + 8) sc[nf][2] = -1e30f;
                if (cb + 1 > row0 + 8) sc[nf][3] = -1e30f;
            }
        }

        float rmax0 = -1e30f, rmax1 = -1e30f;
#pragma unroll
        for (int nf = 0; nf < 8; nf++) {
            rmax0 = fmaxf(rmax0, fmaxf(sc[nf][0], sc[nf][1]));
            rmax1 = fmaxf(rmax1, fmaxf(sc[nf][2], sc[nf][3]));
        }
        rmax0 = fmaxf(rmax0, __shfl_xor_sync(0xffffffffu, rmax0, 1));
        rmax0 = fmaxf(rmax0, __shfl_xor_sync(0xffffffffu, rmax0, 2));
        rmax1 = fmaxf(rmax1, __shfl_xor_sync(0xffffffffu, rmax1, 1));
        rmax1 = fmaxf(rmax1, __shfl_xor_sync(0xffffffffu, rmax1, 2));
        const float mn0 = fmaxf(m0, rmax0);
        const float mn1 = fmaxf(m1, rmax1);
        const float scl0 = __expf(m0 - mn0);
        const float scl1 = __expf(m1 - mn1);
        float rs0 = 0.0f, rs1 = 0.0f;
#pragma unroll
        for (int nf = 0; nf < 8; nf++) {
            sc[nf][0] = __expf(sc[nf][0] - mn0); rs0 += sc[nf][0];
            sc[nf][1] = __expf(sc[nf][1] - mn0); rs0 += sc[nf][1];
            sc[nf][2] = __expf(sc[nf][2] - mn1); rs1 += sc[nf][2];
            sc[nf][3] = __expf(sc[nf][3] - mn1); rs1 += sc[nf][3];
        }
        rs0 += __shfl_xor_sync(0xffffffffu, rs0, 1);
        rs0 += __shfl_xor_sync(0xffffffffu, rs0, 2);
        rs1 += __shfl_xor_sync(0xffffffffu, rs1, 1);
        rs1 += __shfl_xor_sync(0xffffffffu, rs1, 2);
        l0 = l0 * scl0 + rs0;
        l1 = l1 * scl1 + rs1;
        m0 = mn0;
        m1 = mn1;
#pragma unroll
        for (int f = 0; f < 16; f++) {
            of[f][0] *= scl0; of[f][1] *= scl0;
            of[f][2] *= scl1; of[f][3] *= scl1;
        }

        if (t < qb) CP_WAIT1(); else CP_WAIT0();
        __syncthreads();

#pragma unroll
        for (int kb = 0; kb < 4; kb++) {
            uint32_t ph[4];
            ph[0] = pack2(sc[2 * kb][0], sc[2 * kb][1]);
            ph[1] = pack2(sc[2 * kb][2], sc[2 * kb][3]);
            ph[2] = pack2(sc[2 * kb + 1][0], sc[2 * kb + 1][1]);
            ph[3] = pack2(sc[2 * kb + 1][2], sc[2 * kb + 1][3]);
            const uint32_t vbase = sb + AV + (kb * 16 + lr) * 272 + lc16;
#pragma unroll
            for (int npp = 0; npp < 4; npp++) {
                const int np0 = 2 * npp, np1 = 2 * npp + 1;
                uint32_t vA[4], vB[4];
                ldsm4t(vA, vbase + np0 * 32);
                ldsm4t(vB, vbase + np1 * 32);
                uint32_t h0A[2] = {vA[0], vA[1]}, h1A[2] = {vA[2], vA[3]};
                uint32_t h0B[2] = {vB[0], vB[1]}, h1B[2] = {vB[2], vB[3]};
                mma16816(of[2 * np0], ph, h0A);
                mma16816(of[2 * np0 + 1], ph, h1A);
                mma16816(of[2 * np1], ph, h0B);
                mma16816(of[2 * np1 + 1], ph, h1B);
            }
        }

        __syncthreads();
        if (t < qb) {
            load_V(t + 1);
            CP_COMMIT();
        }
    }

    const float inv0 = 1.0f / l0;
    const float inv1 = 1.0f / l1;
    const int r0g = q0 + wrow + (lane >> 2);
    const int colb = 2 * (lane & 3);
#pragma unroll
    for (int nf = 0; nf < 16; nf++) {
        const int col = h * DHEAD + 8 * nf + colb;
        __half2 a = {__float2half_rn(of[nf][0] * inv0), __float2half_rn(of[nf][1] * inv0)};
        __half2 bvals = {__float2half_rn(of[nf][2] * inv1), __float2half_rn(of[nf][3] * inv1)};
        *(__half2*)(g_at + (size_t)(b * NS + r0g) * NHID + col) = a;
        *(__half2*)(g_at + (size_t)(b * NS + r0g + 8) * NHID + col) = bvals;
    }
}

// ------------------------- launch ------------------------------------------
extern "C" void kernel_launch(void* const* d_in, const int* in_sizes, int n_in,
                              void* d_out, int out_size) {
    const float* hidden = (const float*)d_in[0];
    const void* pos = d_in[1];
    const float* Wqkv = (const float*)d_in[2];
    const float* Wout = (const float*)d_in[3];
    float* out = (float*)d_out;

    void *p_qkv, *p_hid, *p_w1, *p_w2, *p_at;
    cudaGetSymbolAddress(&p_qkv, g_qkv);
    cudaGetSymbolAddress(&p_hid, g_hid);
    cudaGetSymbolAddress(&p_w1, g_w1);
    cudaGetSymbolAddress(&p_w2, g_w2);
    cudaGetSymbolAddress(&p_at, g_at);

    const int nHid = NB * NS * NHID;
    const int nW1 = NQKV * NHID;
    const int nW2 = NHID * NHID;

    conv_half<<<(nHid / 4 + 255) / 256, 256>>>(hidden, (__half*)p_hid, nHid / 4);
    conv_half<<<(nW1 / 4 + 255) / 256, 256>>>(Wqkv, (__half*)p_w1, nW1 / 4);
    conv_half<<<(nW2 / 4 + 255) / 256, 256>>>(Wout, (__half*)p_w2, nW2 / 4);

    // 1) QKV projection + clamp (1-pass fp16, 64x32 warp tiles)
    {
        cudaFuncSetAttribute(gemm_1p<1>, cudaFuncAttributeMaxDynamicSharedMemorySize, GSMEM);
        dim3 grid(NQKV / 64, (NB * NS) / 128);
        gemm_1p<1><<<grid, 128, GSMEM>>>(
            (const __half*)p_hid, (const __half*)p_w1,
            (float*)p_qkv, NB * NS, NQKV, NHID);
    }
    // 2) RoPE + scatter
    rope_scatter<<<NB * NS, 128>>>(pos);

    // 3) tensor-core causal flash attention (1-pass)
    {
        cudaFuncSetAttribute(flash_attn_tc, cudaFuncAttributeMaxDynamicSharedMemorySize, ATTN_SMEM);
        dim3 grid(NS / 64, NHEADS, NB);
        flash_attn_tc<<<grid, 128, ATTN_SMEM>>>();
    }
    // 4) output projection (1-pass fp16, 64x32 warp tiles)
    {
        cudaFuncSetAttribute(gemm_1p<0>, cudaFuncAttributeMaxDynamicSharedMemorySize, GSMEM);
        dim3 grid(NHID / 64, (NB * NS) / 128);
        gemm_1p<0><<<grid, 128, GSMEM>>>(
            (const __half*)p_at, (const __half*)p_w2,
            out, NB * NS, NHID, NHID);
    }
}

// round 16
// speedup vs baseline: 2.5731x; 1.0625x over previous
#include <cuda_runtime.h>
#include <cuda_fp16.h>
#include <cstdint>
#include <math.h>

#define NB 2
#define NS 2048
#define NHID 2048
#define NHEADS 16
#define NKVH 4
#define DHEAD 128
#define NQKV 3072

// ------------------------- scratch (static device globals; no allocs) ------
static __device__ float g_cos[(size_t)NB * NS * 64];
static __device__ float g_sin[(size_t)NB * NS * 64];

static __device__ __half g_q[(size_t)NB * NHEADS * NS * DHEAD];  // pair-interleaved d
static __device__ __half g_k[(size_t)NB * NKVH * NS * DHEAD];    // pair-interleaved d
static __device__ __half g_v[(size_t)NB * NKVH * NS * DHEAD];    // original d order

static __device__ __half g_hid[(size_t)NB * NS * NHID];
static __device__ __half g_w1[(size_t)NQKV * NHID];              // rows permuted (Q,K)
static __device__ __half g_w2[(size_t)NHID * NHID];
static __device__ __half g_at[(size_t)NB * NS * NHID];

// ------------------------- PTX helpers (baseline ISA only) -----------------
__device__ __forceinline__ uint32_t smem_u32(const void* p) {
    uint32_t a;
    asm("{ .reg .u64 t; cvta.to.shared.u64 t, %1; cvt.u32.u64 %0, t; }"
        : "=r"(a) : "l"(p));
    return a;
}

__device__ __forceinline__ void cp16(uint32_t dst, const void* src) {
    asm volatile("cp.async.cg.shared.global [%0], [%1], 16;"
                 :: "r"(dst), "l"(src));
}
#define CP_COMMIT() asm volatile("cp.async.commit_group;" ::: "memory")
#define CP_WAIT0() asm volatile("cp.async.wait_group 0;" ::: "memory")
#define CP_WAIT1() asm volatile("cp.async.wait_group 1;" ::: "memory")
#define CP_WAIT2() asm volatile("cp.async.wait_group 2;" ::: "memory")

__device__ __forceinline__ void ldsm4(uint32_t* r, uint32_t addr) {
    asm volatile("ldmatrix.sync.aligned.m8n8.x4.shared.b16 {%0,%1,%2,%3}, [%4];"
                 : "=r"(r[0]), "=r"(r[1]), "=r"(r[2]), "=r"(r[3]) : "r"(addr));
}

__device__ __forceinline__ void ldsm4t(uint32_t* r, uint32_t addr) {
    asm volatile("ldmatrix.sync.aligned.m8n8.x4.trans.shared.b16 {%0,%1,%2,%3}, [%4];"
                 : "=r"(r[0]), "=r"(r[1]), "=r"(r[2]), "=r"(r[3]) : "r"(addr));
}

__device__ __forceinline__ void mma16816(float* c, const uint32_t* a, const uint32_t* b) {
    asm volatile(
        "mma.sync.aligned.m16n8k16.row.col.f32.f16.f16.f32 "
        "{%0,%1,%2,%3}, {%4,%5,%6,%7}, {%8,%9}, {%0,%1,%2,%3};"
        : "+f"(c[0]), "+f"(c[1]), "+f"(c[2]), "+f"(c[3])
        : "r"(a[0]), "r"(a[1]), "r"(a[2]), "r"(a[3]), "r"(b[0]), "r"(b[1]));
}

__device__ __forceinline__ uint32_t pack2(float a, float b) {
    __half2 p = {__float2half_rn(a), __float2half_rn(b)};
    return *(uint32_t*)&p;
}

#define SWZ64(x) ((x) ^ (((x) >> 3) & 0x30))

// ------------------------- fp32 -> fp16 convert ----------------------------
__global__ void __launch_bounds__(256) conv_half(const float* __restrict__ x,
                                                 __half* __restrict__ o, int n4) {
    int i = blockIdx.x * 256 + threadIdx.x;
    if (i >= n4) return;
    float4 v = ((const float4*)x)[i];
    __half2 a = {__float2half_rn(v.x), __float2half_rn(v.y)};
    __half2 b = {__float2half_rn(v.z), __float2half_rn(v.w)};
    ((__half2*)o)[2 * i] = a;
    ((__half2*)o)[2 * i + 1] = b;
}

// W1 convert with row permutation: new row h*128 + 2d+e <- orig h*128 + d + 64e
// (Q section rows 0..2047, K section 2048..2559; V unchanged)
__global__ void __launch_bounds__(256) conv_w1_perm(const float* __restrict__ W,
                                                    __half* __restrict__ o) {
    int idx = blockIdx.x * 256 + threadIdx.x;  // 3072 rows x 256 chunks
    int row = idx >> 8;
    int c8 = idx & 255;
    int orow;
    if (row < 2048) {
        int h = row >> 7, cih = row & 127;
        orow = h * 128 + (cih >> 1) + 64 * (cih & 1);
    } else if (row < 2560) {
        int rr = row - 2048;
        int h = rr >> 7, cih = rr & 127;
        orow = 2048 + h * 128 + (cih >> 1) + 64 * (cih & 1);
    } else {
        orow = row;
    }
    const float4* src = (const float4*)(W + (size_t)orow * NHID + c8 * 8);
    float4 a = src[0], b = src[1];
    __half2 h0 = {__float2half_rn(a.x), __float2half_rn(a.y)};
    __half2 h1 = {__float2half_rn(a.z), __float2half_rn(a.w)};
    __half2 h2 = {__float2half_rn(b.x), __float2half_rn(b.y)};
    __half2 h3 = {__float2half_rn(b.z), __float2half_rn(b.w)};
    __half2* dst = (__half2*)(o + (size_t)row * NHID + c8 * 8);
    dst[0] = h0; dst[1] = h1; dst[2] = h2; dst[3] = h3;
}

// ------------------------- RoPE cos/sin table (fp64 trig) ------------------
__global__ void __launch_bounds__(256) rope_table(const void* __restrict__ pos_ids) {
    int i = blockIdx.x * 256 + threadIdx.x;  // NB*NS*64
    int bs = i >> 6, d = i & 63;
    const int* p32 = (const int*)pos_ids;
    const bool is64 = (p32[1] == 0) && (p32[3] == 0) && (p32[2 * NS + 1] == 0);
    const long long pv = is64 ? ((const long long*)pos_ids)[bs] : (long long)p32[bs];
    const double C_LN = 0.20503692777194264;  // ln(500000)/64
    const double invf = exp(-(double)d * C_LN);
    double sd, cd;
    sincos((double)pv * invf, &sd, &cd);
    g_cos[i] = (float)cd;
    g_sin[i] = (float)sd;
}

// ------------------------- QKV GEMM + fused clamp/RoPE/fp16 ----------------
// CTA 128x64, 128 threads, 4 warps, warp tile 64x32, BK=32. N fixed 3072.
// bx<32: Q (head bx/2, half bx&1), bx<40: K, else V. W1 rows pre-permuted so
// acc pair (c[0],c[1]) = RoPE pair (orig d, d+64) at cols (2d, 2d+1).
#define GST 12288
#define GSMEM (2 * GST)

__global__ void __launch_bounds__(128, 4) gemm_qkv_rope(const __half* __restrict__ A,
                                                        const __half* __restrict__ B) {
    extern __shared__ char smem[];
    const uint32_t sb = smem_u32(smem);
    const int tid = threadIdx.x;
    const int lane = tid & 31;
    const int wid = tid >> 5;
    const int wm = (wid & 1) * 64;
    const int wn = (wid >> 1) * 32;
    const int bx = blockIdx.x;
    const int by = blockIdx.y;
    const int K = NHID;

    auto load_stage = [&](int st, int kt) {
        const uint32_t s = sb + st * GST;
        const int kc = kt * 32;
#pragma unroll
        for (int i = 0; i < 4; i++) {
            const int q = tid + i * 128;
            const int r = q >> 2, c = q & 3;
            cp16(s + SWZ64(r * 64 + c * 16), A + (size_t)(by * 128 + r) * K + kc + c * 8);
        }
#pragma unroll
        for (int i = 0; i < 2; i++) {
            const int q = tid + i * 128;
            const int r = q >> 2, c = q & 3;
            cp16(s + 8192 + SWZ64(r * 64 + c * 16), B + (size_t)(bx * 64 + r) * K + kc + c * 8);
        }
    };

    float acc[4][4][4];
#pragma unroll
    for (int i = 0; i < 4; i++)
#pragma unroll
        for (int j = 0; j < 4; j++)
#pragma unroll
            for (int e = 0; e < 4; e++) acc[i][j][e] = 0.0f;

    const int KT = K >> 5;
    load_stage(0, 0);
    CP_COMMIT();

    const int lr = (lane & 7) + ((lane >> 3) & 1) * 8;
    const int lc = lane >> 4;

    for (int kt = 0; kt < KT; kt++) {
        CP_WAIT0();
        __syncthreads();
        if (kt + 1 < KT) {
            load_stage((kt + 1) & 1, kt + 1);
            CP_COMMIT();
        }
        const uint32_t s = sb + (kt & 1) * GST;
#pragma unroll
        for (int ks = 0; ks < 2; ks++) {
            const int ch = 2 * ks + lc;
            uint32_t bf[4][2];
#pragma unroll
            for (int nf2 = 0; nf2 < 2; nf2++) {
                uint32_t tb[4];
                ldsm4(tb, s + 8192 + SWZ64((wn + nf2 * 16 + lr) * 64 + ch * 16));
                bf[nf2 * 2][0] = tb[0]; bf[nf2 * 2 + 1][0] = tb[1];
                bf[nf2 * 2][1] = tb[2]; bf[nf2 * 2 + 1][1] = tb[3];
            }
            uint32_t af[4][4];
#pragma unroll
            for (int mf = 0; mf < 4; mf++)
                ldsm4(af[mf], s + SWZ64((wm + mf * 16 + lr) * 64 + ch * 16));
#pragma unroll
            for (int mf = 0; mf < 4; mf++)
#pragma unroll
                for (int nf = 0; nf < 4; nf++)
                    mma16816(acc[mf][nf], af[mf], bf[nf]);
        }
    }

    // ---- fused epilogue: clamp -> (RoPE) -> fp16 store ----
    const int erow = lane >> 2;
    const int ecol = (lane & 3) * 2;
    const float qscale = 0.08838834764831845f;

    __half* dst;
    int head, cbase, nh;
    bool dorope;
    float oscale = 1.0f;
    if (bx < 32) {
        head = bx >> 1; cbase = (bx & 1) * 64; nh = NHEADS;
        dst = g_q; dorope = true; oscale = qscale;
    } else if (bx < 40) {
        head = (bx - 32) >> 1; cbase = ((bx - 32) & 1) * 64; nh = NKVH;
        dst = g_k; dorope = true;
    } else {
        head = (bx - 40) >> 1; cbase = ((bx - 40) & 1) * 64; nh = NKVH;
        dst = g_v; dorope = false;
    }

#pragma unroll
    for (int mf = 0; mf < 4; mf++) {
#pragma unroll
        for (int nf = 0; nf < 4; nf++) {
            float* c = acc[mf][nf];
#pragma unroll
            for (int e = 0; e < 4; e++) c[e] = fminf(8.0f, fmaxf(-8.0f, c[e]));
            const int cih = cbase + wn + nf * 8 + ecol;
            const int r0 = by * 128 + wm + mf * 16 + erow;
            const int r1 = r0 + 8;
            float x0 = c[0], y0 = c[1], x1 = c[2], y1 = c[3];
            if (dorope) {
                const int d = cih >> 1;
                const float c0 = g_cos[(size_t)r0 * 64 + d];
                const float s0 = g_sin[(size_t)r0 * 64 + d];
                const float c1 = g_cos[(size_t)r1 * 64 + d];
                const float s1 = g_sin[(size_t)r1 * 64 + d];
                float ox0 = (x0 * c0 - y0 * s0) * oscale;
                float oy0 = (y0 * c0 + x0 * s0) * oscale;
                float ox1 = (x1 * c1 - y1 * s1) * oscale;
                float oy1 = (y1 * c1 + x1 * s1) * oscale;
                x0 = ox0; y0 = oy0; x1 = ox1; y1 = oy1;
            }
            const int b0 = r0 >> 11, s0i = r0 & (NS - 1);
            const int b1 = r1 >> 11, s1i = r1 & (NS - 1);
            __half2 p0 = {__float2half_rn(x0), __float2half_rn(y0)};
            __half2 p1 = {__float2half_rn(x1), __float2half_rn(y1)};
            *(__half2*)(dst + ((size_t)(b0 * nh + head) * NS + s0i) * DHEAD + cih) = p0;
            *(__half2*)(dst + ((size_t)(b1 * nh + head) * NS + s1i) * DHEAD + cih) = p1;
        }
    }
}

// ------------------------- 1-pass HMMA GEMM (out-proj) ---------------------
template <int CLAMP>
__global__ void __launch_bounds__(128, 4) gemm_1p(const __half* __restrict__ A,
                                                  const __half* __restrict__ B,
                                                  float* __restrict__ C,
                                                  int M, int N, int K) {
    extern __shared__ char smem[];
    const uint32_t sb = smem_u32(smem);
    const int tid = threadIdx.x;
    const int lane = tid & 31;
    const int wid = tid >> 5;
    const int wm = (wid & 1) * 64;
    const int wn = (wid >> 1) * 32;
    const int bx = blockIdx.x;
    const int by = blockIdx.y;

    auto load_stage = [&](int st, int kt) {
        const uint32_t s = sb + st * GST;
        const int kc = kt * 32;
#pragma unroll
        for (int i = 0; i < 4; i++) {
            const int q = tid + i * 128;
            const int r = q >> 2, c = q & 3;
            cp16(s + SWZ64(r * 64 + c * 16), A + (size_t)(by * 128 + r) * K + kc + c * 8);
        }
#pragma unroll
        for (int i = 0; i < 2; i++) {
            const int q = tid + i * 128;
            const int r = q >> 2, c = q & 3;
            cp16(s + 8192 + SWZ64(r * 64 + c * 16), B + (size_t)(bx * 64 + r) * K + kc + c * 8);
        }
    };

    float acc[4][4][4];
#pragma unroll
    for (int i = 0; i < 4; i++)
#pragma unroll
        for (int j = 0; j < 4; j++)
#pragma unroll
            for (int e = 0; e < 4; e++) acc[i][j][e] = 0.0f;

    const int KT = K >> 5;
    load_stage(0, 0);
    CP_COMMIT();

    const int lr = (lane & 7) + ((lane >> 3) & 1) * 8;
    const int lc = lane >> 4;

    for (int kt = 0; kt < KT; kt++) {
        CP_WAIT0();
        __syncthreads();
        if (kt + 1 < KT) {
            load_stage((kt + 1) & 1, kt + 1);
            CP_COMMIT();
        }
        const uint32_t s = sb + (kt & 1) * GST;
#pragma unroll
        for (int ks = 0; ks < 2; ks++) {
            const int ch = 2 * ks + lc;
            uint32_t bf[4][2];
#pragma unroll
            for (int nf2 = 0; nf2 < 2; nf2++) {
                uint32_t tb[4];
                ldsm4(tb, s + 8192 + SWZ64((wn + nf2 * 16 + lr) * 64 + ch * 16));
                bf[nf2 * 2][0] = tb[0]; bf[nf2 * 2 + 1][0] = tb[1];
                bf[nf2 * 2][1] = tb[2]; bf[nf2 * 2 + 1][1] = tb[3];
            }
            uint32_t af[4][4];
#pragma unroll
            for (int mf = 0; mf < 4; mf++)
                ldsm4(af[mf], s + SWZ64((wm + mf * 16 + lr) * 64 + ch * 16));
#pragma unroll
            for (int mf = 0; mf < 4; mf++)
#pragma unroll
                for (int nf = 0; nf < 4; nf++)
                    mma16816(acc[mf][nf], af[mf], bf[nf]);
        }
    }

    const int erow = lane >> 2;
    const int ecol = (lane & 3) * 2;
#pragma unroll
    for (int mf = 0; mf < 4; mf++) {
#pragma unroll
        for (int nf = 0; nf < 4; nf++) {
            float* c = acc[mf][nf];
            if (CLAMP) {
#pragma unroll
                for (int e = 0; e < 4; e++)
                    c[e] = fminf(8.0f, fmaxf(-8.0f, c[e]));
            }
            const int row = by * 128 + wm + mf * 16 + erow;
            const int col = bx * 64 + wn + nf * 8 + ecol;
            float2 v0 = {c[0], c[1]};
            float2 v1 = {c[2], c[3]};
            *(float2*)(C + (size_t)row * N + col) = v0;
            *(float2*)(C + (size_t)(row + 8) * N + col) = v1;
        }
    }
}

// ------------------------- tensor-core flash attention ---------------------
// BM=64, BN=64, 4 warps. 1-pass fp16. (d-order permuted for Q/K — invariant.)
#define AQ 0
#define AK 17408
#define AV 34816
#define ATTN_SMEM 52224

__global__ void __launch_bounds__(128) flash_attn_tc() {
    extern __shared__ char smem[];
    const uint32_t sb = smem_u32(smem);
    const int tid = threadIdx.x;
    const int lane = tid & 31;
    const int w = tid >> 5;
    const int qb = gridDim.x - 1 - blockIdx.x;
    const int h = blockIdx.y;
    const int b = blockIdx.z;
    const int hk = h >> 2;
    const int q0 = qb * 64;
    const int wrow = w * 16;

    const __half* Qg = g_q + ((size_t)(b * NHEADS + h) * NS + q0) * DHEAD;
    const __half* Kg = g_k + ((size_t)(b * NKVH + hk) * NS) * DHEAD;
    const __half* Vg = g_v + ((size_t)(b * NKVH + hk) * NS) * DHEAD;

    auto load_K = [&](int t) {
#pragma unroll
        for (int i = 0; i < 8; i++) {
            int q = tid + i * 128;
            int r = q >> 4, cc = q & 15;
            cp16(sb + AK + r * 272 + cc * 16, Kg + (size_t)(t * 64 + r) * DHEAD + cc * 8);
        }
    };
    auto load_V = [&](int t) {
#pragma unroll
        for (int i = 0; i < 8; i++) {
            int q = tid + i * 128;
            int r = q >> 4, cc = q & 15;
            cp16(sb + AV + r * 272 + cc * 16, Vg + (size_t)(t * 64 + r) * DHEAD + cc * 8);
        }
    };

#pragma unroll
    for (int i = 0; i < 8; i++) {
        int q = tid + i * 128;
        int r = q >> 4, cc = q & 15;
        cp16(sb + AQ + r * 272 + cc * 16, Qg + (size_t)r * DHEAD + cc * 8);
    }
    CP_COMMIT();
    load_K(0);
    CP_COMMIT();
    load_V(0);
    CP_COMMIT();

    const int lr = (lane & 7) + ((lane >> 3) & 1) * 8;
    const int lc16 = (lane >> 4) * 16;

    CP_WAIT2();
    __syncthreads();
    uint32_t qf[8][4];
#pragma unroll
    for (int kc = 0; kc < 8; kc++)
        ldsm4(qf[kc], sb + AQ + (wrow + lr) * 272 + kc * 32 + lc16);

    float of[16][4];
#pragma unroll
    for (int f = 0; f < 16; f++)
#pragma unroll
        for (int e = 0; e < 4; e++) of[f][e] = 0.0f;
    float m0 = -1e30f, m1 = -1e30f, l0 = 0.0f, l1 = 0.0f;

    for (int t = 0; t <= qb; t++) {
        CP_WAIT1();
        __syncthreads();

        float sc[8][4];
#pragma unroll
        for (int nf = 0; nf < 8; nf++)
#pragma unroll
            for (int e = 0; e < 4; e++) sc[nf][e] = 0.0f;

#pragma unroll
        for (int kc = 0; kc < 8; kc++) {
            uint32_t b0[4][2], b1[4][2];
#pragma unroll
            for (int np = 0; np < 4; np++) {
                uint32_t k4[4];
                ldsm4(k4, sb + AK + (np * 16 + lr) * 272 + kc * 32 + lc16);
                b0[np][0] = k4[0]; b0[np][1] = k4[2];
                b1[np][0] = k4[1]; b1[np][1] = k4[3];
            }
#pragma unroll
            for (int np = 0; np < 4; np++) {
                mma16816(sc[2 * np], qf[kc], b0[np]);
                mma16816(sc[2 * np + 1], qf[kc], b1[np]);
            }
        }

        __syncthreads();
        if (t < qb) {
            load_K(t + 1);
            CP_COMMIT();
        }

        if (t == qb) {
            const int row0 = q0 + wrow + (lane >> 2);
            const int colb = t * 64 + 2 * (lane & 3);
#pragma unroll
            for (int nf = 0; nf < 8; nf++) {
                const int cb = colb + 8 * nf;
                if (cb > row0) sc[nf][0] = -1e30f;
                if (cb + 1 > row0) sc[nf][1] = -1e30f;
                if (cb > row0 + 8) sc[nf][2] = -1e30f;
                if (cb + 1 > row0 + 8) sc[nf][3] = -1e30f;
            }
        }

        float rmax0 = -1e30f, rmax1 = -1e30f;
#pragma unroll
        for (int nf = 0; nf < 8; nf++) {
            rmax0 = fmaxf(rmax0, fmaxf(sc[nf][0], sc[nf][1]));
            rmax1 = fmaxf(rmax1, fmaxf(sc[nf][2], sc[nf][3]));
        }
        rmax0 = fmaxf(rmax0, __shfl_xor_sync(0xffffffffu, rmax0, 1));
        rmax0 = fmaxf(rmax0, __shfl_xor_sync(0xffffffffu, rmax0, 2));
        rmax1 = fmaxf(rmax1, __shfl_xor_sync(0xffffffffu, rmax1, 1));
        rmax1 = fmaxf(rmax1, __shfl_xor_sync(0xffffffffu, rmax1, 2));
        const float mn0 = fmaxf(m0, rmax0);
        const float mn1 = fmaxf(m1, rmax1);
        const float scl0 = __expf(m0 - mn0);
        const float scl1 = __expf(m1 - mn1);
        float rs0 = 0.0f, rs1 = 0.0f;
#pragma unroll
        for (int nf = 0; nf < 8; nf++) {
            sc[nf][0] = __expf(sc[nf][0] - mn0); rs0 += sc[nf][0];
            sc[nf][1] = __expf(sc[nf][1] - mn0); rs0 += sc[nf][1];
            sc[nf][2] = __expf(sc[nf][2] - mn1); rs1 += sc[nf][2];
            sc[nf][3] = __expf(sc[nf][3] - mn1); rs1 += sc[nf][3];
        }
        rs0 += __shfl_xor_sync(0xffffffffu, rs0, 1);
        rs0 += __shfl_xor_sync(0xffffffffu, rs0, 2);
        rs1 += __shfl_xor_sync(0xffffffffu, rs1, 1);
        rs1 += __shfl_xor_sync(0xffffffffu, rs1, 2);
        l0 = l0 * scl0 + rs0;
        l1 = l1 * scl1 + rs1;
        m0 = mn0;
        m1 = mn1;
#pragma unroll
        for (int f = 0; f < 16; f++) {
            of[f][0] *= scl0; of[f][1] *= scl0;
            of[f][2] *= scl1; of[f][3] *= scl1;
        }

        if (t < qb) CP_WAIT1(); else CP_WAIT0();
        __syncthreads();

#pragma unroll
        for (int kb = 0; kb < 4; kb++) {
            uint32_t ph[4];
            ph[0] = pack2(sc[2 * kb][0], sc[2 * kb][1]);
            ph[1] = pack2(sc[2 * kb][2], sc[2 * kb][3]);
            ph[2] = pack2(sc[2 * kb + 1][0], sc[2 * kb + 1][1]);
            ph[3] = pack2(sc[2 * kb + 1][2], sc[2 * kb + 1][3]);
            const uint32_t vbase = sb + AV + (kb * 16 + lr) * 272 + lc16;
#pragma unroll
            for (int npp = 0; npp < 4; npp++) {
                const int np0 = 2 * npp, np1 = 2 * npp + 1;
                uint32_t vA[4], vB[4];
                ldsm4t(vA, vbase + np0 * 32);
                ldsm4t(vB, vbase + np1 * 32);
                uint32_t h0A[2] = {vA[0], vA[1]}, h1A[2] = {vA[2], vA[3]};
                uint32_t h0B[2] = {vB[0], vB[1]}, h1B[2] = {vB[2], vB[3]};
                mma16816(of[2 * np0], ph, h0A);
                mma16816(of[2 * np0 + 1], ph, h1A);
                mma16816(of[2 * np1], ph, h0B);
                mma16816(of[2 * np1 + 1], ph, h1B);
            }
        }

        __syncthreads();
        if (t < qb) {
            load_V(t + 1);
            CP_COMMIT();
        }
    }

    const float inv0 = 1.0f / l0;
    const float inv1 = 1.0f / l1;
    const int r0g = q0 + wrow + (lane >> 2);
    const int colb = 2 * (lane & 3);
#pragma unroll
    for (int nf = 0; nf < 16; nf++) {
        const int col = h * DHEAD + 8 * nf + colb;
        __half2 a = {__float2half_rn(of[nf][0] * inv0), __float2half_rn(of[nf][1] * inv0)};
        __half2 bvals = {__float2half_rn(of[nf][2] * inv1), __float2half_rn(of[nf][3] * inv1)};
        *(__half2*)(g_at + (size_t)(b * NS + r0g) * NHID + col) = a;
        *(__half2*)(g_at + (size_t)(b * NS + r0g + 8) * NHID + col) = bvals;
    }
}

// ------------------------- launch ------------------------------------------
extern "C" void kernel_launch(void* const* d_in, const int* in_sizes, int n_in,
                              void* d_out, int out_size) {
    const float* hidden = (const float*)d_in[0];
    const void* pos = d_in[1];
    const float* Wqkv = (const float*)d_in[2];
    const float* Wout = (const float*)d_in[3];
    float* out = (float*)d_out;

    void *p_hid, *p_w1, *p_w2, *p_at;
    cudaGetSymbolAddress(&p_hid, g_hid);
    cudaGetSymbolAddress(&p_w1, g_w1);
    cudaGetSymbolAddress(&p_w2, g_w2);
    cudaGetSymbolAddress(&p_at, g_at);

    const int nHid = NB * NS * NHID;
    const int nW2 = NHID * NHID;

    conv_half<<<(nHid / 4 + 255) / 256, 256>>>(hidden, (__half*)p_hid, nHid / 4);
    conv_w1_perm<<<NQKV, 256>>>(Wqkv, (__half*)p_w1);
    conv_half<<<(nW2 / 4 + 255) / 256, 256>>>(Wout, (__half*)p_w2, nW2 / 4);
    rope_table<<<(NB * NS * 64) / 256, 256>>>(pos);

    // 1) QKV projection + clamp + RoPE + fp16 store (fused)
    {
        cudaFuncSetAttribute(gemm_qkv_rope, cudaFuncAttributeMaxDynamicSharedMemorySize, GSMEM);
        dim3 grid(NQKV / 64, (NB * NS) / 128);
        gemm_qkv_rope<<<grid, 128, GSMEM>>>((const __half*)p_hid, (const __half*)p_w1);
    }
    // 2) tensor-core causal flash attention
    {
        cudaFuncSetAttribute(flash_attn_tc, cudaFuncAttributeMaxDynamicSharedMemorySize, ATTN_SMEM);
        dim3 grid(NS / 64, NHEADS, NB);
        flash_attn_tc<<<grid, 128, ATTN_SMEM>>>();
    }
    // 3) output projection
    {
        cudaFuncSetAttribute(gemm_1p<0>, cudaFuncAttributeMaxDynamicSharedMemorySize, GSMEM);
        dim3 grid(NHID / 64, (NB * NS) / 128);
        gemm_1p<0><<<grid, 128, GSMEM>>>(
            (const __half*)p_at, (const __half*)p_w2,
            out, NB * NS, NHID, NHID);
    }
}

// round 17
// speedup vs baseline: 2.6412x; 1.0265x over previous
#include <cuda_runtime.h>
#include <cuda_fp16.h>
#include <cstdint>
#include <math.h>

#define NB 2
#define NS 2048
#define NHID 2048
#define NHEADS 16
#define NKVH 4
#define DHEAD 128
#define NQKV 3072

// ------------------------- scratch (static device globals; no allocs) ------
static __device__ float2 g_cs[(size_t)NB * NS * 64];  // {cos, sin}

static __device__ __half g_q[(size_t)NB * NHEADS * NS * DHEAD];  // pair-interleaved d
static __device__ __half g_k[(size_t)NB * NKVH * NS * DHEAD];    // pair-interleaved d
static __device__ __half g_v[(size_t)NB * NKVH * NS * DHEAD];    // original d order

static __device__ __half g_hid[(size_t)NB * NS * NHID];
static __device__ __half g_w1[(size_t)NQKV * NHID];              // rows permuted (Q,K)
static __device__ __half g_w2[(size_t)NHID * NHID];
static __device__ __half g_at[(size_t)NB * NS * NHID];

// ------------------------- PTX helpers (baseline ISA only) -----------------
__device__ __forceinline__ uint32_t smem_u32(const void* p) {
    uint32_t a;
    asm("{ .reg .u64 t; cvta.to.shared.u64 t, %1; cvt.u32.u64 %0, t; }"
        : "=r"(a) : "l"(p));
    return a;
}

__device__ __forceinline__ void cp16(uint32_t dst, const void* src) {
    asm volatile("cp.async.cg.shared.global [%0], [%1], 16;"
                 :: "r"(dst), "l"(src));
}
#define CP_COMMIT() asm volatile("cp.async.commit_group;" ::: "memory")
#define CP_WAIT0() asm volatile("cp.async.wait_group 0;" ::: "memory")
#define CP_WAIT1() asm volatile("cp.async.wait_group 1;" ::: "memory")
#define CP_WAIT2() asm volatile("cp.async.wait_group 2;" ::: "memory")

__device__ __forceinline__ void ldsm4(uint32_t* r, uint32_t addr) {
    asm volatile("ldmatrix.sync.aligned.m8n8.x4.shared.b16 {%0,%1,%2,%3}, [%4];"
                 : "=r"(r[0]), "=r"(r[1]), "=r"(r[2]), "=r"(r[3]) : "r"(addr));
}

__device__ __forceinline__ void ldsm4t(uint32_t* r, uint32_t addr) {
    asm volatile("ldmatrix.sync.aligned.m8n8.x4.trans.shared.b16 {%0,%1,%2,%3}, [%4];"
                 : "=r"(r[0]), "=r"(r[1]), "=r"(r[2]), "=r"(r[3]) : "r"(addr));
}

__device__ __forceinline__ void mma16816(float* c, const uint32_t* a, const uint32_t* b) {
    asm volatile(
        "mma.sync.aligned.m16n8k16.row.col.f32.f16.f16.f32 "
        "{%0,%1,%2,%3}, {%4,%5,%6,%7}, {%8,%9}, {%0,%1,%2,%3};"
        : "+f"(c[0]), "+f"(c[1]), "+f"(c[2]), "+f"(c[3])
        : "r"(a[0]), "r"(a[1]), "r"(a[2]), "r"(a[3]), "r"(b[0]), "r"(b[1]));
}

__device__ __forceinline__ uint32_t pack2(float a, float b) {
    __half2 p = {__float2half_rn(a), __float2half_rn(b)};
    return *(uint32_t*)&p;
}

#define SWZ64(x) ((x) ^ (((x) >> 3) & 0x30))

// ------------------------- fp32 -> fp16 convert ----------------------------
__global__ void __launch_bounds__(256) conv_half(const float* __restrict__ x,
                                                 __half* __restrict__ o, int n4) {
    int i = blockIdx.x * 256 + threadIdx.x;
    if (i >= n4) return;
    float4 v = ((const float4*)x)[i];
    __half2 a = {__float2half_rn(v.x), __float2half_rn(v.y)};
    __half2 b = {__float2half_rn(v.z), __float2half_rn(v.w)};
    ((__half2*)o)[2 * i] = a;
    ((__half2*)o)[2 * i + 1] = b;
}

// W1 convert with row permutation: new row h*128 + 2d+e <- orig h*128 + d + 64e
__global__ void __launch_bounds__(256) conv_w1_perm(const float* __restrict__ W,
                                                    __half* __restrict__ o) {
    int idx = blockIdx.x * 256 + threadIdx.x;
    int row = idx >> 8;
    int c8 = idx & 255;
    int orow;
    if (row < 2048) {
        int h = row >> 7, cih = row & 127;
        orow = h * 128 + (cih >> 1) + 64 * (cih & 1);
    } else if (row < 2560) {
        int rr = row - 2048;
        int h = rr >> 7, cih = rr & 127;
        orow = 2048 + h * 128 + (cih >> 1) + 64 * (cih & 1);
    } else {
        orow = row;
    }
    const float4* src = (const float4*)(W + (size_t)orow * NHID + c8 * 8);
    float4 a = src[0], b = src[1];
    __half2 h0 = {__float2half_rn(a.x), __float2half_rn(a.y)};
    __half2 h1 = {__float2half_rn(a.z), __float2half_rn(a.w)};
    __half2 h2 = {__float2half_rn(b.x), __float2half_rn(b.y)};
    __half2 h3 = {__float2half_rn(b.z), __float2half_rn(b.w)};
    __half2* dst = (__half2*)(o + (size_t)row * NHID + c8 * 8);
    dst[0] = h0; dst[1] = h1; dst[2] = h2; dst[3] = h3;
}

// ------------------------- RoPE cos/sin table (fp32, reference-faithful) ---
// Reference computes freqs in fp32 then cos/sin of that fp32 value; mirror it:
// invf exact via fp64 exp -> rounded to fp32, fp32 multiply, sincosf.
__global__ void __launch_bounds__(256) rope_table(const void* __restrict__ pos_ids) {
    int i = blockIdx.x * 256 + threadIdx.x;  // NB*NS*64
    int bs = i >> 6, d = i & 63;
    const int* p32 = (const int*)pos_ids;
    const bool is64 = (p32[1] == 0) && (p32[3] == 0) && (p32[2 * NS + 1] == 0);
    const long long pv = is64 ? ((const long long*)pos_ids)[bs] : (long long)p32[bs];
    const double C_LN = 0.20503692777194264;  // ln(500000)/64
    const float invf = (float)exp(-(double)d * C_LN);
    const float arg = __fmul_rn((float)pv, invf);
    float s, c;
    __sincosf(arg, &s, &c);   // fast path; refine with sincosf for accuracy
    sincosf(arg, &s, &c);
    g_cs[i] = {c, s};
}

// ------------------------- QKV GEMM + fused clamp/RoPE/fp16 ----------------
#define GST 12288
#define GSMEM (2 * GST)

__global__ void __launch_bounds__(128, 4) gemm_qkv_rope(const __half* __restrict__ A,
                                                        const __half* __restrict__ B) {
    extern __shared__ char smem[];
    const uint32_t sb = smem_u32(smem);
    const int tid = threadIdx.x;
    const int lane = tid & 31;
    const int wid = tid >> 5;
    const int wm = (wid & 1) * 64;
    const int wn = (wid >> 1) * 32;
    const int bx = blockIdx.x;
    const int by = blockIdx.y;
    const int K = NHID;

    auto load_stage = [&](int st, int kt) {
        const uint32_t s = sb + st * GST;
        const int kc = kt * 32;
#pragma unroll
        for (int i = 0; i < 4; i++) {
            const int q = tid + i * 128;
            const int r = q >> 2, c = q & 3;
            cp16(s + SWZ64(r * 64 + c * 16), A + (size_t)(by * 128 + r) * K + kc + c * 8);
        }
#pragma unroll
        for (int i = 0; i < 2; i++) {
            const int q = tid + i * 128;
            const int r = q >> 2, c = q & 3;
            cp16(s + 8192 + SWZ64(r * 64 + c * 16), B + (size_t)(bx * 64 + r) * K + kc + c * 8);
        }
    };

    float acc[4][4][4];
#pragma unroll
    for (int i = 0; i < 4; i++)
#pragma unroll
        for (int j = 0; j < 4; j++)
#pragma unroll
            for (int e = 0; e < 4; e++) acc[i][j][e] = 0.0f;

    const int KT = K >> 5;
    load_stage(0, 0);
    CP_COMMIT();

    const int lr = (lane & 7) + ((lane >> 3) & 1) * 8;
    const int lc = lane >> 4;

    for (int kt = 0; kt < KT; kt++) {
        CP_WAIT0();
        __syncthreads();
        if (kt + 1 < KT) {
            load_stage((kt + 1) & 1, kt + 1);
            CP_COMMIT();
        }
        const uint32_t s = sb + (kt & 1) * GST;
#pragma unroll
        for (int ks = 0; ks < 2; ks++) {
            const int ch = 2 * ks + lc;
            uint32_t bf[4][2];
#pragma unroll
            for (int nf2 = 0; nf2 < 2; nf2++) {
                uint32_t tb[4];
                ldsm4(tb, s + 8192 + SWZ64((wn + nf2 * 16 + lr) * 64 + ch * 16));
                bf[nf2 * 2][0] = tb[0]; bf[nf2 * 2 + 1][0] = tb[1];
                bf[nf2 * 2][1] = tb[2]; bf[nf2 * 2 + 1][1] = tb[3];
            }
            uint32_t af[4][4];
#pragma unroll
            for (int mf = 0; mf < 4; mf++)
                ldsm4(af[mf], s + SWZ64((wm + mf * 16 + lr) * 64 + ch * 16));
#pragma unroll
            for (int mf = 0; mf < 4; mf++)
#pragma unroll
                for (int nf = 0; nf < 4; nf++)
                    mma16816(acc[mf][nf], af[mf], bf[nf]);
        }
    }

    // ---- fused epilogue: clamp -> (RoPE) -> fp16 store ----
    const int erow = lane >> 2;
    const int ecol = (lane & 3) * 2;
    const float qscale = 0.08838834764831845f;

    __half* dst;
    int head, cbase, nh;
    bool dorope;
    float oscale = 1.0f;
    if (bx < 32) {
        head = bx >> 1; cbase = (bx & 1) * 64; nh = NHEADS;
        dst = g_q; dorope = true; oscale = qscale;
    } else if (bx < 40) {
        head = (bx - 32) >> 1; cbase = ((bx - 32) & 1) * 64; nh = NKVH;
        dst = g_k; dorope = true;
    } else {
        head = (bx - 40) >> 1; cbase = ((bx - 40) & 1) * 64; nh = NKVH;
        dst = g_v; dorope = false;
    }

#pragma unroll
    for (int mf = 0; mf < 4; mf++) {
#pragma unroll
        for (int nf = 0; nf < 4; nf++) {
            float* c = acc[mf][nf];
#pragma unroll
            for (int e = 0; e < 4; e++) c[e] = fminf(8.0f, fmaxf(-8.0f, c[e]));
            const int cih = cbase + wn + nf * 8 + ecol;
            const int r0 = by * 128 + wm + mf * 16 + erow;
            const int r1 = r0 + 8;
            float x0 = c[0], y0 = c[1], x1 = c[2], y1 = c[3];
            if (dorope) {
                const int d = cih >> 1;
                const float2 cs0 = g_cs[(size_t)r0 * 64 + d];
                const float2 cs1 = g_cs[(size_t)r1 * 64 + d];
                float ox0 = (x0 * cs0.x - y0 * cs0.y) * oscale;
                float oy0 = (y0 * cs0.x + x0 * cs0.y) * oscale;
                float ox1 = (x1 * cs1.x - y1 * cs1.y) * oscale;
                float oy1 = (y1 * cs1.x + x1 * cs1.y) * oscale;
                x0 = ox0; y0 = oy0; x1 = ox1; y1 = oy1;
            }
            const int b0 = r0 >> 11, s0i = r0 & (NS - 1);
            const int b1 = r1 >> 11, s1i = r1 & (NS - 1);
            __half2 p0 = {__float2half_rn(x0), __float2half_rn(y0)};
            __half2 p1 = {__float2half_rn(x1), __float2half_rn(y1)};
            *(__half2*)(dst + ((size_t)(b0 * nh + head) * NS + s0i) * DHEAD + cih) = p0;
            *(__half2*)(dst + ((size_t)(b1 * nh + head) * NS + s1i) * DHEAD + cih) = p1;
        }
    }
}

// ------------------------- 1-pass HMMA GEMM (out-proj) ---------------------
template <int CLAMP>
__global__ void __launch_bounds__(128, 4) gemm_1p(const __half* __restrict__ A,
                                                  const __half* __restrict__ B,
                                                  float* __restrict__ C,
                                                  int M, int N, int K) {
    extern __shared__ char smem[];
    const uint32_t sb = smem_u32(smem);
    const int tid = threadIdx.x;
    const int lane = tid & 31;
    const int wid = tid >> 5;
    const int wm = (wid & 1) * 64;
    const int wn = (wid >> 1) * 32;
    const int bx = blockIdx.x;
    const int by = blockIdx.y;

    auto load_stage = [&](int st, int kt) {
        const uint32_t s = sb + st * GST;
        const int kc = kt * 32;
#pragma unroll
        for (int i = 0; i < 4; i++) {
            const int q = tid + i * 128;
            const int r = q >> 2, c = q & 3;
            cp16(s + SWZ64(r * 64 + c * 16), A + (size_t)(by * 128 + r) * K + kc + c * 8);
        }
#pragma unroll
        for (int i = 0; i < 2; i++) {
            const int q = tid + i * 128;
            const int r = q >> 2, c = q & 3;
            cp16(s + 8192 + SWZ64(r * 64 + c * 16), B + (size_t)(bx * 64 + r) * K + kc + c * 8);
        }
    };

    float acc[4][4][4];
#pragma unroll
    for (int i = 0; i < 4; i++)
#pragma unroll
        for (int j = 0; j < 4; j++)
#pragma unroll
            for (int e = 0; e < 4; e++) acc[i][j][e] = 0.0f;

    const int KT = K >> 5;
    load_stage(0, 0);
    CP_COMMIT();

    const int lr = (lane & 7) + ((lane >> 3) & 1) * 8;
    const int lc = lane >> 4;

    for (int kt = 0; kt < KT; kt++) {
        CP_WAIT0();
        __syncthreads();
        if (kt + 1 < KT) {
            load_stage((kt + 1) & 1, kt + 1);
            CP_COMMIT();
        }
        const uint32_t s = sb + (kt & 1) * GST;
#pragma unroll
        for (int ks = 0; ks < 2; ks++) {
            const int ch = 2 * ks + lc;
            uint32_t bf[4][2];
#pragma unroll
            for (int nf2 = 0; nf2 < 2; nf2++) {
                uint32_t tb[4];
                ldsm4(tb, s + 8192 + SWZ64((wn + nf2 * 16 + lr) * 64 + ch * 16));
                bf[nf2 * 2][0] = tb[0]; bf[nf2 * 2 + 1][0] = tb[1];
                bf[nf2 * 2][1] = tb[2]; bf[nf2 * 2 + 1][1] = tb[3];
            }
            uint32_t af[4][4];
#pragma unroll
            for (int mf = 0; mf < 4; mf++)
                ldsm4(af[mf], s + SWZ64((wm + mf * 16 + lr) * 64 + ch * 16));
#pragma unroll
            for (int mf = 0; mf < 4; mf++)
#pragma unroll
                for (int nf = 0; nf < 4; nf++)
                    mma16816(acc[mf][nf], af[mf], bf[nf]);
        }
    }

    const int erow = lane >> 2;
    const int ecol = (lane & 3) * 2;
#pragma unroll
    for (int mf = 0; mf < 4; mf++) {
#pragma unroll
        for (int nf = 0; nf < 4; nf++) {
            float* c = acc[mf][nf];
            if (CLAMP) {
#pragma unroll
                for (int e = 0; e < 4; e++)
                    c[e] = fminf(8.0f, fmaxf(-8.0f, c[e]));
            }
            const int row = by * 128 + wm + mf * 16 + erow;
            const int col = bx * 64 + wn + nf * 8 + ecol;
            float2 v0 = {c[0], c[1]};
            float2 v1 = {c[2], c[3]};
            *(float2*)(C + (size_t)row * N + col) = v0;
            *(float2*)(C + (size_t)(row + 8) * N + col) = v1;
        }
    }
}

// ------------------------- tensor-core flash attention ---------------------
#define AQ 0
#define AK 17408
#define AV 34816
#define ATTN_SMEM 52224

__global__ void __launch_bounds__(128) flash_attn_tc() {
    extern __shared__ char smem[];
    const uint32_t sb = smem_u32(smem);
    const int tid = threadIdx.x;
    const int lane = tid & 31;
    const int w = tid >> 5;
    const int qb = gridDim.x - 1 - blockIdx.x;
    const int h = blockIdx.y;
    const int b = blockIdx.z;
    const int hk = h >> 2;
    const int q0 = qb * 64;
    const int wrow = w * 16;

    const __half* Qg = g_q + ((size_t)(b * NHEADS + h) * NS + q0) * DHEAD;
    const __half* Kg = g_k + ((size_t)(b * NKVH + hk) * NS) * DHEAD;
    const __half* Vg = g_v + ((size_t)(b * NKVH + hk) * NS) * DHEAD;

    auto load_K = [&](int t) {
#pragma unroll
        for (int i = 0; i < 8; i++) {
            int q = tid + i * 128;
            int r = q >> 4, cc = q & 15;
            cp16(sb + AK + r * 272 + cc * 16, Kg + (size_t)(t * 64 + r) * DHEAD + cc * 8);
        }
    };
    auto load_V = [&](int t) {
#pragma unroll
        for (int i = 0; i < 8; i++) {
            int q = tid + i * 128;
            int r = q >> 4, cc = q & 15;
            cp16(sb + AV + r * 272 + cc * 16, Vg + (size_t)(t * 64 + r) * DHEAD + cc * 8);
        }
    };

#pragma unroll
    for (int i = 0; i < 8; i++) {
        int q = tid + i * 128;
        int r = q >> 4, cc = q & 15;
        cp16(sb + AQ + r * 272 + cc * 16, Qg + (size_t)r * DHEAD + cc * 8);
    }
    CP_COMMIT();
    load_K(0);
    CP_COMMIT();
    load_V(0);
    CP_COMMIT();

    const int lr = (lane & 7) + ((lane >> 3) & 1) * 8;
    const int lc16 = (lane >> 4) * 16;

    CP_WAIT2();
    __syncthreads();
    uint32_t qf[8][4];
#pragma unroll
    for (int kc = 0; kc < 8; kc++)
        ldsm4(qf[kc], sb + AQ + (wrow + lr) * 272 + kc * 32 + lc16);

    float of[16][4];
#pragma unroll
    for (int f = 0; f < 16; f++)
#pragma unroll
        for (int e = 0; e < 4; e++) of[f][e] = 0.0f;
    float m0 = -1e30f, m1 = -1e30f, l0 = 0.0f, l1 = 0.0f;

    for (int t = 0; t <= qb; t++) {
        CP_WAIT1();
        __syncthreads();

        float sc[8][4];
#pragma unroll
        for (int nf = 0; nf < 8; nf++)
#pragma unroll
            for (int e = 0; e < 4; e++) sc[nf][e] = 0.0f;

#pragma unroll
        for (int kc = 0; kc < 8; kc++) {
            uint32_t b0[4][2], b1[4][2];
#pragma unroll
            for (int np = 0; np < 4; np++) {
                uint32_t k4[4];
                ldsm4(k4, sb + AK + (np * 16 + lr) * 272 + kc * 32 + lc16);
                b0[np][0] = k4[0]; b0[np][1] = k4[2];
                b1[np][0] = k4[1]; b1[np][1] = k4[3];
            }
#pragma unroll
            for (int np = 0; np < 4; np++) {
                mma16816(sc[2 * np], qf[kc], b0[np]);
                mma16816(sc[2 * np + 1], qf[kc], b1[np]);
            }
        }

        __syncthreads();
        if (t < qb) {
            load_K(t + 1);
            CP_COMMIT();
        }

        if (t == qb) {
            const int row0 = q0 + wrow + (lane >> 2);
            const int colb = t * 64 + 2 * (lane & 3);
#pragma unroll
            for (int nf = 0; nf < 8; nf++) {
                const int cb = colb + 8 * nf;
                if (cb > row0) sc[nf][0] = -1e30f;
                if (cb + 1 > row0) sc[nf][1] = -1e30f;
                if (cb > row0 + 8) sc[nf][2] = -1e30f;
                if (cb + 1 > row0 + 8) sc[nf][3] = -1e30f;
            }
        }

        float rmax0 = -1e30f, rmax1 = -1e30f;
#pragma unroll
        for (int nf = 0; nf < 8; nf++) {
            rmax0 = fmaxf(rmax0, fmaxf(sc[nf][0], sc[nf][1]));
            rmax1 = fmaxf(rmax1, fmaxf(sc[nf][2], sc[nf][3]));
        }
        rmax0 = fmaxf(rmax0, __shfl_xor_sync(0xffffffffu, rmax0, 1));
        rmax0 = fmaxf(rmax0, __shfl_xor_sync(0xffffffffu, rmax0, 2));
        rmax1 = fmaxf(rmax1, __shfl_xor_sync(0xffffffffu, rmax1, 1));
        rmax1 = fmaxf(rmax1, __shfl_xor_sync(0xffffffffu, rmax1, 2));
        const float mn0 = fmaxf(m0, rmax0);
        const float mn1 = fmaxf(m1, rmax1);
        const float scl0 = __expf(m0 - mn0);
        const float scl1 = __expf(m1 - mn1);
        float rs0 = 0.0f, rs1 = 0.0f;
#pragma unroll
        for (int nf = 0; nf < 8; nf++) {
            sc[nf][0] = __expf(sc[nf][0] - mn0); rs0 += sc[nf][0];
            sc[nf][1] = __expf(sc[nf][1] - mn0); rs0 += sc[nf][1];
            sc[nf][2] = __expf(sc[nf][2] - mn1); rs1 += sc[nf][2];
            sc[nf][3] = __expf(sc[nf][3] - mn1); rs1 += sc[nf][3];
        }
        rs0 += __shfl_xor_sync(0xffffffffu, rs0, 1);
        rs0 += __shfl_xor_sync(0xffffffffu, rs0, 2);
        rs1 += __shfl_xor_sync(0xffffffffu, rs1, 1);
        rs1 += __shfl_xor_sync(0xffffffffu, rs1, 2);
        l0 = l0 * scl0 + rs0;
        l1 = l1 * scl1 + rs1;
        m0 = mn0;
        m1 = mn1;
#pragma unroll
        for (int f = 0; f < 16; f++) {
            of[f][0] *= scl0; of[f][1] *= scl0;
            of[f][2] *= scl1; of[f][3] *= scl1;
        }

        if (t < qb) CP_WAIT1(); else CP_WAIT0();
        __syncthreads();

#pragma unroll
        for (int kb = 0; kb < 4; kb++) {
            uint32_t ph[4];
            ph[0] = pack2(sc[2 * kb][0], sc[2 * kb][1]);
            ph[1] = pack2(sc[2 * kb][2], sc[2 * kb][3]);
            ph[2] = pack2(sc[2 * kb + 1][0], sc[2 * kb + 1][1]);
            ph[3] = pack2(sc[2 * kb + 1][2], sc[2 * kb + 1][3]);
            const uint32_t vbase = sb + AV + (kb * 16 + lr) * 272 + lc16;
#pragma unroll
            for (int npp = 0; npp < 4; npp++) {
                const int np0 = 2 * npp, np1 = 2 * npp + 1;
                uint32_t vA[4], vB[4];
                ldsm4t(vA, vbase + np0 * 32);
                ldsm4t(vB, vbase + np1 * 32);
                uint32_t h0A[2] = {vA[0], vA[1]}, h1A[2] = {vA[2], vA[3]};
                uint32_t h0B[2] = {vB[0], vB[1]}, h1B[2] = {vB[2], vB[3]};
                mma16816(of[2 * np0], ph, h0A);
                mma16816(of[2 * np0 + 1], ph, h1A);
                mma16816(of[2 * np1], ph, h0B);
                mma16816(of[2 * np1 + 1], ph, h1B);
            }
        }

        __syncthreads();
        if (t < qb) {
            load_V(t + 1);
            CP_COMMIT();
        }
    }

    const float inv0 = 1.0f / l0;
    const float inv1 = 1.0f / l1;
    const int r0g = q0 + wrow + (lane >> 2);
    const int colb = 2 * (lane & 3);
#pragma unroll
    for (int nf = 0; nf < 16; nf++) {
        const int col = h * DHEAD + 8 * nf + colb;
        __half2 a = {__float2half_rn(of[nf][0] * inv0), __float2half_rn(of[nf][1] * inv0)};
        __half2 bvals = {__float2half_rn(of[nf][2] * inv1), __float2half_rn(of[nf][3] * inv1)};
        *(__half2*)(g_at + (size_t)(b * NS + r0g) * NHID + col) = a;
        *(__half2*)(g_at + (size_t)(b * NS + r0g + 8) * NHID + col) = bvals;
    }
}

// ------------------------- launch ------------------------------------------
extern "C" void kernel_launch(void* const* d_in, const int* in_sizes, int n_in,
                              void* d_out, int out_size) {
    const float* hidden = (const float*)d_in[0];
    const void* pos = d_in[1];
    const float* Wqkv = (const float*)d_in[2];
    const float* Wout = (const float*)d_in[3];
    float* out = (float*)d_out;

    void *p_hid, *p_w1, *p_w2, *p_at;
    cudaGetSymbolAddress(&p_hid, g_hid);
    cudaGetSymbolAddress(&p_w1, g_w1);
    cudaGetSymbolAddress(&p_w2, g_w2);
    cudaGetSymbolAddress(&p_at, g_at);

    const int nHid = NB * NS * NHID;
    const int nW2 = NHID * NHID;

    conv_half<<<(nHid / 4 + 255) / 256, 256>>>(hidden, (__half*)p_hid, nHid / 4);
    conv_w1_perm<<<NQKV, 256>>>(Wqkv, (__half*)p_w1);
    conv_half<<<(nW2 / 4 + 255) / 256, 256>>>(Wout, (__half*)p_w2, nW2 / 4);
    rope_table<<<(NB * NS * 64) / 256, 256>>>(pos);

    // 1) QKV projection + clamp + RoPE + fp16 store (fused)
    {
        cudaFuncSetAttribute(gemm_qkv_rope, cudaFuncAttributeMaxDynamicSharedMemorySize, GSMEM);
        dim3 grid(NQKV / 64, (NB * NS) / 128);
        gemm_qkv_rope<<<grid, 128, GSMEM>>>((const __half*)p_hid, (const __half*)p_w1);
    }
    // 2) tensor-core causal flash attention
    {
        cudaFuncSetAttribute(flash_attn_tc, cudaFuncAttributeMaxDynamicSharedMemorySize, ATTN_SMEM);
        dim3 grid(NS / 64, NHEADS, NB);
        flash_attn_tc<<<grid, 128, ATTN_SMEM>>>();
    }
    // 3) output projection
    {
        cudaFuncSetAttribute(gemm_1p<0>, cudaFuncAttributeMaxDynamicSharedMemorySize, GSMEM);
        dim3 grid(NHID / 64, (NB * NS) / 128);
        gemm_1p<0><<<grid, 128, GSMEM>>>(
            (const __half*)p_at, (const __half*)p_w2,
            out, NB * NS, NHID, NHID);
    }
}